// round 5
// baseline (speedup 1.0000x reference)
#include <cuda_runtime.h>
#include <math.h>
#include <stdint.h>

// ---------------------------------------------------------------------------
// PartitionedTransformerEncoderLayer — Round 5: HMMA tf32 everywhere,
// 128x128 block tiles (32x64 warp tiles) for the 5 big GEMMs.
// (tcgen05 is blocked: harness PTX targets sm_103, not sm_103a)
// ---------------------------------------------------------------------------

#define HH   8
#define TT   1024
#define BB   4
#define DMOD 1024
#define DM2  512
#define DQ   128
#define DQ2  64
#define DF2  2048
#define BT   4096

// scratch
__device__ float g_q[BB*HH*TT*DQ];
__device__ float g_k[BB*HH*TT*DQ];
__device__ float g_v[BB*HH*TT*DQ];
__device__ float g_s[(size_t)BB*HH*TT*TT];
__device__ float g_o[(size_t)BT*DMOD];
__device__ float g_t1[(size_t)BT*DMOD];
__device__ float g_x1[(size_t)BT*DMOD];
__device__ float g_x1r[(size_t)BT*DMOD];
__device__ float g_h[(size_t)BT*2*DF2];
__device__ float g_maskf[BB*TT];
__device__ float g_xr[(size_t)BT*DMOD];
__device__ float g_wqc[HH*DM2*192];
__device__ float g_wqp[HH*DM2*192];
__device__ float g_woc[HH*DQ2*DM2];
__device__ float g_wop[HH*DQ2*DM2];
__device__ float g_w1c[DF2*DM2];
__device__ float g_w1p[DF2*DM2];
__device__ float g_w2c[DM2*DF2];
__device__ float g_w2p[DM2*DF2];

// ---------------------------------------------------------------------------
__device__ __forceinline__ unsigned f2tf32u(float f) {
    unsigned u;
    asm("cvt.rna.tf32.f32 %0, %1;" : "=r"(u) : "f"(f));
    return u;
}
__device__ __forceinline__ float rtf(float f) { return __uint_as_float(f2tf32u(f)); }

__device__ __forceinline__ void cp16(void* smem, const void* g) {
    unsigned s = (unsigned)__cvta_generic_to_shared(smem);
    asm volatile("cp.async.cg.shared.global [%0], [%1], 16;" :: "r"(s), "l"(g));
}
__device__ __forceinline__ void cp_commit() { asm volatile("cp.async.commit_group;"); }
__device__ __forceinline__ void cp_wait0()  { asm volatile("cp.async.wait_group 0;"); }

__device__ __forceinline__ void ldm_x4(unsigned &r0, unsigned &r1,
                                       unsigned &r2, unsigned &r3,
                                       const unsigned* p) {
    unsigned addr = (unsigned)__cvta_generic_to_shared(p);
    asm volatile("ldmatrix.sync.aligned.m8n8.x4.shared.b16 {%0,%1,%2,%3}, [%4];"
                 : "=r"(r0), "=r"(r1), "=r"(r2), "=r"(r3) : "r"(addr));
}
__device__ __forceinline__ void mma_tf32(float* c, const unsigned* a, const unsigned* b) {
    asm volatile("mma.sync.aligned.m16n8k8.row.col.f32.tf32.tf32.f32 "
                 "{%0,%1,%2,%3}, {%4,%5,%6,%7}, {%8,%9}, {%0,%1,%2,%3};"
                 : "+f"(c[0]), "+f"(c[1]), "+f"(c[2]), "+f"(c[3])
                 : "r"(a[0]), "r"(a[1]), "r"(a[2]), "r"(a[3]),
                   "r"(b[0]), "r"(b[1]));
}

// ---------------------------------------------------------------------------
// Mask canonicalization
// ---------------------------------------------------------------------------
__global__ void mask_probe_k(const void* __restrict__ maskraw) {
    const unsigned int* w = (const unsigned int*)maskraw;
    int tid = threadIdx.x;
    unsigned int v = w[tid];
    int oki = (v == 0u || v == 1u);
    int okf = (v == 0u || v == 0x3F800000u);
    int all_i = __syncthreads_and(oki);
    int all_f = __syncthreads_and(okf);
    if (all_i) {
        const int* wi = (const int*)maskraw;
        for (int i = tid; i < BB*TT; i += 1024) g_maskf[i] = wi[i] ? 1.f : 0.f;
    } else if (all_f) {
        const float* wf = (const float*)maskraw;
        for (int i = tid; i < BB*TT; i += 1024) g_maskf[i] = (wf[i] != 0.f) ? 1.f : 0.f;
    } else {
        const unsigned char* wb = (const unsigned char*)maskraw;
        for (int i = tid; i < BB*TT; i += 1024) g_maskf[i] = wb[i] ? 1.f : 0.f;
    }
}

__global__ void __launch_bounds__(256) cvt_k(const float4* __restrict__ src,
                                             float4* __restrict__ dst, int n4) {
    int i = blockIdx.x * 256 + threadIdx.x;
    if (i < n4) {
        float4 v = src[i];
        v.x = rtf(v.x); v.y = rtf(v.y); v.z = rtf(v.z); v.w = rtf(v.w);
        dst[i] = v;
    }
}

// ---------------------------------------------------------------------------
// BIG GEMM: 128x128x32 tiles, 256 threads = 8 warps (4M x 2N), warp tile
// 32x64. cp.async double-buffered, dynamic smem (2 x (128x36 A + 128x36 B)).
//  1 DOTS : A=g_q,   B=g_k  (k-contig)           -> g_s      (z=b*8+h, K=128)
//  2 PV   : A=g_s,   B=g_v  (n-contig)           -> g_o rtf  (z=b*8+h, K=1024)
//  3 OPROJ: A=g_o,   B=g_wo (n-contig)           -> g_t1     (z=half,  K=512)
//  4 FFN1 : A=g_x1r, B=g_w1 (k-contig) +b relu   -> g_h rtf  (z=half,  K=512)
//  5 FFN2 : A=g_h,   B=g_w2 (k-contig) +b        -> g_t1     (z=half,  K=2048)
// ---------------------------------------------------------------------------
#define TILE_WORDS (128 * 36)

template<int MODE>
__global__ void __launch_bounds__(256, 2)
gemm_big(const float* __restrict__ bias0,
         const float* __restrict__ bias1)
{
    constexpr int K = (MODE == 1) ? 128 :
                      (MODE == 2) ? 1024 :
                      (MODE == 3) ? 512 :
                      (MODE == 4) ? 512 : 2048;
    constexpr bool B_KCONTIG = (MODE == 1 || MODE == 4 || MODE == 5);

    extern __shared__ unsigned smem[];
    // layout: A0 | A1 | B0 | B1, each 128x36 words
    unsigned* Abuf[2] = { smem, smem + TILE_WORDS };
    unsigned* Bbuf[2] = { smem + 2*TILE_WORDS, smem + 3*TILE_WORDS };

    const int tid  = threadIdx.x;
    const int lane = tid & 31;
    const int warp = tid >> 5;
    const int wm = (warp & 3) * 32;
    const int wn = (warp >> 2) * 64;
    const int m0 = blockIdx.y * 128;
    const int n0 = blockIdx.x * 128;
    const int z  = blockIdx.z;

    const float* Abase;
    if constexpr (MODE == 1)      Abase = g_q + (size_t)z * (TT*DQ);
    else if constexpr (MODE == 2) Abase = g_s + (size_t)z * ((size_t)TT*TT);
    else if constexpr (MODE == 3) Abase = g_o;
    else if constexpr (MODE == 4) Abase = g_x1r;
    else                          Abase = g_h;

    const float* Wb;
    int bstride;
    if constexpr (MODE == 1)      { Wb = g_k + (size_t)z * (TT*DQ); bstride = DQ;  }
    else if constexpr (MODE == 2) { Wb = g_v + (size_t)z * (TT*DQ); bstride = DQ;  }
    else if constexpr (MODE == 3) { Wb = z ? g_wop : g_woc;         bstride = DM2; }
    else if constexpr (MODE == 4) { Wb = z ? g_w1p : g_w1c;         bstride = DM2; }
    else                          { Wb = z ? g_w2p : g_w2c;         bstride = DF2; }

    float c[2][8][4];
#pragma unroll
    for (int mt = 0; mt < 2; mt++)
#pragma unroll
        for (int nt = 0; nt < 8; nt++)
#pragma unroll
            for (int r = 0; r < 4; r++) c[mt][nt][r] = 0.f;

    const int ld_r  = tid >> 3;          // 0..31 (row within group of 32)
    const int ld_kq = (tid & 7) << 2;    // k quad
    const int bt_kl = tid >> 5;          // transpose path: k row 0..7
    const int bt_nq = (tid & 31) << 2;   // n quad 0..124

    auto a_idx = [&](int m, int k) -> size_t {
        if constexpr (MODE == 1)
            return (size_t)m * DQ + k;
        else if constexpr (MODE == 2)
            return (size_t)m * TT + k;
        else if constexpr (MODE == 3)
            return (size_t)m * DMOD + (size_t)((k >> 6) << 7) + (size_t)z * DQ2 + (k & 63);
        else if constexpr (MODE == 4)
            return (size_t)m * DMOD + (size_t)z * DM2 + k;
        else
            return (size_t)m * (2*DF2) + (size_t)z * DF2 + k;
    };

    auto loadA = [&](int k0, int buf) {
#pragma unroll
        for (int it = 0; it < 4; it++) {
            int m = m0 + ld_r + it * 32;
            cp16(&Abuf[buf][(ld_r + it * 32) * 36 + ld_kq], Abase + a_idx(m, k0 + ld_kq));
        }
    };
    auto loadB_async = [&](int k0, int buf) {
#pragma unroll
        for (int it = 0; it < 4; it++) {
            int n = n0 + ld_r + it * 32;
            cp16(&Bbuf[buf][(ld_r + it * 32) * 36 + ld_kq], Wb + (size_t)n * bstride + k0 + ld_kq);
        }
    };
    float4 breg[4];
    auto ldgB = [&](int k0) {
#pragma unroll
        for (int it = 0; it < 4; it++) {
            int k = k0 + bt_kl + it * 8;
            breg[it] = *(const float4*)(Wb + (size_t)k * bstride + n0 + bt_nq);
        }
    };
    auto stsB = [&](int buf) {
#pragma unroll
        for (int it = 0; it < 4; it++) {
            int kk = bt_kl + it * 8;
            Bbuf[buf][(bt_nq + 0) * 36 + kk] = __float_as_uint(breg[it].x);
            Bbuf[buf][(bt_nq + 1) * 36 + kk] = __float_as_uint(breg[it].y);
            Bbuf[buf][(bt_nq + 2) * 36 + kk] = __float_as_uint(breg[it].z);
            Bbuf[buf][(bt_nq + 3) * 36 + kk] = __float_as_uint(breg[it].w);
        }
    };

    loadA(0, 0);
    if constexpr (B_KCONTIG) loadB_async(0, 0);
    else { ldgB(0); stsB(0); }
    cp_commit();
    cp_wait0();
    __syncthreads();

    const int grp = lane >> 3;
    const int rr  = lane & 7;

    int cur = 0;
    for (int k0 = 0; k0 < K; k0 += 32) {
        const int nxt = cur ^ 1;
        const bool has_next = (k0 + 32 < K);
        if (has_next) {
            loadA(k0 + 32, nxt);
            if constexpr (B_KCONTIG) loadB_async(k0 + 32, nxt);
            else ldgB(k0 + 32);
            cp_commit();
        }

#pragma unroll
        for (int ks = 0; ks < 4; ks++) {
            const int kw = ks * 8;
            unsigned a[2][4];
#pragma unroll
            for (int mt = 0; mt < 2; mt++) {
                const unsigned* p = &Abuf[cur][(wm + mt*16 + (grp & 1)*8 + rr) * 36
                                               + kw + (grp >> 1)*4];
                ldm_x4(a[mt][0], a[mt][1], a[mt][2], a[mt][3], p);
            }
#pragma unroll
            for (int bt = 0; bt < 4; bt++) {
                const unsigned* p = &Bbuf[cur][(wn + bt*16 + (grp >> 1)*8 + rr) * 36
                                               + kw + (grp & 1)*4];
                unsigned b0, b1, b2, b3;
                ldm_x4(b0, b1, b2, b3, p);
                unsigned bf0[2] = {b0, b1};
                unsigned bf1[2] = {b2, b3};
#pragma unroll
                for (int mt = 0; mt < 2; mt++) {
                    mma_tf32(c[mt][bt*2 + 0], a[mt], bf0);
                    mma_tf32(c[mt][bt*2 + 1], a[mt], bf1);
                }
            }
        }

        if (has_next) {
            if constexpr (!B_KCONTIG) stsB(nxt);
            cp_wait0();
        }
        __syncthreads();
        cur = nxt;
    }

    // ---- epilogue ----
    const int g   = lane >> 2;
    const int tig = lane & 3;

#pragma unroll
    for (int mt = 0; mt < 2; mt++) {
#pragma unroll
        for (int nt = 0; nt < 8; nt++) {
            const int mr = m0 + wm + mt*16 + g;
            const int nl = wn + nt*8 + 2*tig;
            float2 lo = make_float2(c[mt][nt][0], c[mt][nt][1]);
            float2 hi = make_float2(c[mt][nt][2], c[mt][nt][3]);

            if constexpr (MODE == 1) {
                size_t base = (size_t)z * ((size_t)TT*TT);
                *(float2*)(g_s + base + (size_t)mr * TT + n0 + nl) = lo;
                *(float2*)(g_s + base + (size_t)(mr+8) * TT + n0 + nl) = hi;
            } else if constexpr (MODE == 2) {
                const int b_ = z >> 3, h = z & 7;
                size_t r0 = ((size_t)(b_*TT + mr)) * DMOD + h*DQ + n0 + nl;
                size_t r1 = ((size_t)(b_*TT + mr + 8)) * DMOD + h*DQ + n0 + nl;
                lo.x = rtf(lo.x); lo.y = rtf(lo.y);
                hi.x = rtf(hi.x); hi.y = rtf(hi.y);
                *(float2*)(g_o + r0) = lo;
                *(float2*)(g_o + r1) = hi;
            } else if constexpr (MODE == 3) {
                size_t r0 = (size_t)mr * DMOD + (size_t)z * DM2 + n0 + nl;
                *(float2*)(g_t1 + r0) = lo;
                *(float2*)(g_t1 + r0 + 8*DMOD) = hi;
            } else if constexpr (MODE == 4) {
                const float* bs = z ? bias1 : bias0;
                float b0 = bs[n0 + nl], b1 = bs[n0 + nl + 1];
                size_t r0 = (size_t)mr * (2*DF2) + (size_t)z * DF2 + n0 + nl;
                float2 o0 = make_float2(rtf(fmaxf(lo.x + b0, 0.f)), rtf(fmaxf(lo.y + b1, 0.f)));
                float2 o1 = make_float2(rtf(fmaxf(hi.x + b0, 0.f)), rtf(fmaxf(hi.y + b1, 0.f)));
                *(float2*)(g_h + r0) = o0;
                *(float2*)(g_h + r0 + (size_t)8 * (2*DF2)) = o1;
            } else {
                const float* bs = z ? bias1 : bias0;
                float b0 = bs[n0 + nl], b1 = bs[n0 + nl + 1];
                size_t r0 = (size_t)mr * DMOD + (size_t)z * DM2 + n0 + nl;
                float2 o0 = make_float2(lo.x + b0, lo.y + b1);
                float2 o1 = make_float2(hi.x + b0, hi.y + b1);
                *(float2*)(g_t1 + r0) = o0;
                *(float2*)(g_t1 + r0 + 8*DMOD) = o1;
            }
        }
    }
}

// ---------------------------------------------------------------------------
// QKV GEMM (128x64x32, N=192 per head): round-3 proven kernel
// ---------------------------------------------------------------------------
__global__ void __launch_bounds__(256)
gemm_qkv()
{
    constexpr int K = 512;

    __shared__ unsigned As[2][128][36];
    __shared__ unsigned Bs[2][64][36];

    const int tid  = threadIdx.x;
    const int lane = tid & 31;
    const int warp = tid >> 5;
    const int wm = (warp & 3) * 32;
    const int wn = (warp >> 2) * 32;
    const int m0 = blockIdx.y * 128;
    const int n0 = blockIdx.x * 64;
    const int z  = blockIdx.z;

    const float* Abase = g_xr;
    const float* Wb = ((z >> 3) ? g_wqp : g_wqc) + (size_t)(z & 7) * (DM2 * 192);
    const int bstride = 192;

    float c[2][4][4];
#pragma unroll
    for (int mt = 0; mt < 2; mt++)
#pragma unroll
        for (int nt = 0; nt < 4; nt++)
#pragma unroll
            for (int r = 0; r < 4; r++) c[mt][nt][r] = 0.f;

    const int a_ml = tid >> 3;
    const int a_kq = (tid & 7) << 2;
    const int bt_kl = tid >> 4;
    const int bt_nq = (tid & 15) << 2;

    auto loadA = [&](int k0, int buf) {
#pragma unroll
        for (int it = 0; it < 4; it++) {
            int m = m0 + a_ml + it * 32;
            cp16(&As[buf][a_ml + it * 32][a_kq],
                 Abase + (size_t)m * DMOD + (size_t)(z >> 3) * DM2 + k0 + a_kq);
        }
    };
    float4 breg[2];
    auto ldgB = [&](int k0) {
#pragma unroll
        for (int it = 0; it < 2; it++) {
            int k = k0 + bt_kl + it * 16;
            breg[it] = *(const float4*)(Wb + (size_t)k * bstride + n0 + bt_nq);
        }
    };
    auto stsB = [&](int buf) {
#pragma unroll
        for (int it = 0; it < 2; it++) {
            int kk = bt_kl + it * 16;
            Bs[buf][bt_nq + 0][kk] = __float_as_uint(breg[it].x);
            Bs[buf][bt_nq + 1][kk] = __float_as_uint(breg[it].y);
            Bs[buf][bt_nq + 2][kk] = __float_as_uint(breg[it].z);
            Bs[buf][bt_nq + 3][kk] = __float_as_uint(breg[it].w);
        }
    };

    loadA(0, 0);
    ldgB(0); stsB(0);
    cp_commit();
    cp_wait0();
    __syncthreads();

    const int grp = lane >> 3;
    const int rr  = lane & 7;

    int cur = 0;
    for (int k0 = 0; k0 < K; k0 += 32) {
        const int nxt = cur ^ 1;
        const bool has_next = (k0 + 32 < K);
        if (has_next) {
            loadA(k0 + 32, nxt);
            ldgB(k0 + 32);
            cp_commit();
        }
#pragma unroll
        for (int ks = 0; ks < 4; ks++) {
            const int kw = ks * 8;
            unsigned a[2][4];
#pragma unroll
            for (int mt = 0; mt < 2; mt++) {
                const unsigned* p = &As[cur][wm + mt*16 + (grp & 1)*8 + rr][kw + (grp >> 1)*4];
                ldm_x4(a[mt][0], a[mt][1], a[mt][2], a[mt][3], p);
            }
            unsigned b[4][2];
#pragma unroll
            for (int bt = 0; bt < 2; bt++) {
                const unsigned* p = &Bs[cur][wn + bt*16 + (grp >> 1)*8 + rr][kw + (grp & 1)*4];
                unsigned r0, r1, r2, r3;
                ldm_x4(r0, r1, r2, r3, p);
                b[bt*2 + 0][0] = r0; b[bt*2 + 0][1] = r1;
                b[bt*2 + 1][0] = r2; b[bt*2 + 1][1] = r3;
            }
#pragma unroll
            for (int mt = 0; mt < 2; mt++)
#pragma unroll
                for (int nt = 0; nt < 4; nt++)
                    mma_tf32(c[mt][nt], a[mt], b[nt]);
        }
        if (has_next) {
            stsB(nxt);
            cp_wait0();
        }
        __syncthreads();
        cur = nxt;
    }

    const int g   = lane >> 2;
    const int tig = lane & 3;
    const int cc = blockIdx.x;            // 0=q 1=k 2=v
    const int h = z & 7, sel = z >> 3;
    const float scale = (cc == 0) ? 0.08838834764831845f : 1.0f;
    float* dst = (cc == 0) ? g_q : ((cc == 1) ? g_k : g_v);

#pragma unroll
    for (int mt = 0; mt < 2; mt++) {
#pragma unroll
        for (int nt = 0; nt < 4; nt++) {
            const int mr = m0 + wm + mt*16 + g;
            const int nl = wn + nt*8 + 2*tig;
            float2 lo = make_float2(rtf(c[mt][nt][0] * scale), rtf(c[mt][nt][1] * scale));
            float2 hi = make_float2(rtf(c[mt][nt][2] * scale), rtf(c[mt][nt][3] * scale));
            {
                int b_ = mr >> 10, t_ = mr & 1023;
                size_t base = ((((size_t)b_*HH + h)*TT + t_) << 7) + ((size_t)sel << 6);
                *(float2*)(dst + base + nl) = lo;
            }
            {
                int m2 = mr + 8;
                int b_ = m2 >> 10, t_ = m2 & 1023;
                size_t base = ((((size_t)b_*HH + h)*TT + t_) << 7) + ((size_t)sel << 6);
                *(float2*)(dst + base + nl) = hi;
            }
        }
    }
}

// ---------------------------------------------------------------------------
// Shuffle-based masked softmax; writes tf32-rounded probs
// ---------------------------------------------------------------------------
__global__ void __launch_bounds__(256) softmax_k()
{
    const int row = blockIdx.x;
    const int b = row >> 13;
    float4* S4 = (float4*)(g_s + (size_t)row * TT);
    const float4* M4 = (const float4*)(g_maskf + b * TT);
    const int tid = threadIdx.x;
    const int lane = tid & 31, wid = tid >> 5;

    __shared__ float red_max[8];
    __shared__ float red_sum[8];

    float4 v = S4[tid];
    float4 m = M4[tid];
    float vals[4];
    vals[0] = (m.x != 0.f) ? v.x : -INFINITY;
    vals[1] = (m.y != 0.f) ? v.y : -INFINITY;
    vals[2] = (m.z != 0.f) ? v.z : -INFINITY;
    vals[3] = (m.w != 0.f) ? v.w : -INFINITY;

    float mx = fmaxf(fmaxf(vals[0], vals[1]), fmaxf(vals[2], vals[3]));
#pragma unroll
    for (int o = 16; o > 0; o >>= 1)
        mx = fmaxf(mx, __shfl_xor_sync(0xFFFFFFFFu, mx, o));
    if (lane == 0) red_max[wid] = mx;
    __syncthreads();
    mx = red_max[0];
#pragma unroll
    for (int i = 1; i < 8; i++) mx = fmaxf(mx, red_max[i]);

    float e[4], sum = 0.f;
#pragma unroll
    for (int i = 0; i < 4; i++) {
        e[i] = (vals[i] == -INFINITY) ? 0.f : __expf(vals[i] - mx);
        sum += e[i];
    }
#pragma unroll
    for (int o = 16; o > 0; o >>= 1)
        sum += __shfl_xor_sync(0xFFFFFFFFu, sum, o);
    if (lane == 0) red_sum[wid] = sum;
    __syncthreads();
    float tot = red_sum[0];
#pragma unroll
    for (int i = 1; i < 8; i++) tot += red_sum[i];
    const float inv = 1.0f / tot;

    float4 o4;
    o4.x = rtf(e[0] * inv); o4.y = rtf(e[1] * inv);
    o4.z = rtf(e[2] * inv); o4.w = rtf(e[3] * inv);
    S4[tid] = o4;
}

// ---------------------------------------------------------------------------
// Fused residual + LayerNorm
// ---------------------------------------------------------------------------
template<int PHASE>
__global__ void __launch_bounds__(256)
ln_k(const float* __restrict__ a,
     const float* __restrict__ gamma,
     const float* __restrict__ beta,
     float* __restrict__ outp)
{
    const int row = blockIdx.x;
    const int tid = threadIdx.x;
    const int lane = tid & 31, wid = tid >> 5;
    const float* r1 = (PHASE == 0) ? a : g_x1;

    __shared__ float red1[8];
    __shared__ float red2[8];

    float4 av = ((const float4*)(r1 + (size_t)row * DMOD))[tid];
    float4 tv = ((const float4*)(g_t1 + (size_t)row * DMOD))[tid];
    float v[4] = {av.x + tv.x, av.y + tv.y, av.z + tv.z, av.w + tv.w};

    float s = v[0] + v[1] + v[2] + v[3];
#pragma unroll
    for (int o = 16; o > 0; o >>= 1) s += __shfl_xor_sync(0xFFFFFFFFu, s, o);
    if (lane == 0) red1[wid] = s;
    __syncthreads();
    float tot = red1[0];
#pragma unroll
    for (int i = 1; i < 8; i++) tot += red1[i];
    const float mu = tot * (1.0f / DMOD);

    float vs = 0.f;
#pragma unroll
    for (int i = 0; i < 4; i++) { float d = v[i] - mu; vs += d * d; }
#pragma unroll
    for (int o = 16; o > 0; o >>= 1) vs += __shfl_xor_sync(0xFFFFFFFFu, vs, o);
    if (lane == 0) red2[wid] = vs;
    __syncthreads();
    float vtot = red2[0];
#pragma unroll
    for (int i = 1; i < 8; i++) vtot += red2[i];
    const float rs = rsqrtf(vtot * (1.0f / DMOD) + 1e-5f);

    float4 g4 = ((const float4*)gamma)[tid];
    float4 b4 = ((const float4*)beta)[tid];
    float4 o4;
    o4.x = (v[0] - mu) * rs * g4.x + b4.x;
    o4.y = (v[1] - mu) * rs * g4.y + b4.y;
    o4.z = (v[2] - mu) * rs * g4.z + b4.z;
    o4.w = (v[3] - mu) * rs * g4.w + b4.w;

    if constexpr (PHASE == 0) {
        ((float4*)(g_x1 + (size_t)row * DMOD))[tid] = o4;
        float4 r4;
        r4.x = rtf(o4.x); r4.y = rtf(o4.y); r4.z = rtf(o4.z); r4.w = rtf(o4.w);
        ((float4*)(g_x1r + (size_t)row * DMOD))[tid] = r4;
    } else {
        ((float4*)(outp + (size_t)row * DMOD))[tid] = o4;
    }
}

// ---------------------------------------------------------------------------
extern "C" void kernel_launch(void* const* d_in, const int* in_sizes, int n_in,
                              void* d_out, int out_size)
{
    (void)in_sizes; (void)n_in; (void)out_size;
    const float* x      = (const float*)d_in[0];
    const void*  mask   = d_in[1];
    const float* wqkv_c = (const float*)d_in[2];
    const float* wqkv_p = (const float*)d_in[3];
    const float* wo_c   = (const float*)d_in[4];
    const float* wo_p   = (const float*)d_in[5];
    const float* w1_c   = (const float*)d_in[6];
    const float* b1_c   = (const float*)d_in[7];
    const float* w1_p   = (const float*)d_in[8];
    const float* b1_p   = (const float*)d_in[9];
    const float* w2_c   = (const float*)d_in[10];
    const float* b2_c   = (const float*)d_in[11];
    const float* w2_p   = (const float*)d_in[12];
    const float* b2_p   = (const float*)d_in[13];
    const float* ln1_g  = (const float*)d_in[14];
    const float* ln1_b  = (const float*)d_in[15];
    const float* ln2_g  = (const float*)d_in[16];
    const float* ln2_b  = (const float*)d_in[17];
    float* out = (float*)d_out;

    const int big_smem = 4 * TILE_WORDS * sizeof(unsigned);   // 73728 B
    cudaFuncSetAttribute(gemm_big<1>, cudaFuncAttributeMaxDynamicSharedMemorySize, big_smem);
    cudaFuncSetAttribute(gemm_big<2>, cudaFuncAttributeMaxDynamicSharedMemorySize, big_smem);
    cudaFuncSetAttribute(gemm_big<3>, cudaFuncAttributeMaxDynamicSharedMemorySize, big_smem);
    cudaFuncSetAttribute(gemm_big<4>, cudaFuncAttributeMaxDynamicSharedMemorySize, big_smem);
    cudaFuncSetAttribute(gemm_big<5>, cudaFuncAttributeMaxDynamicSharedMemorySize, big_smem);

    mask_probe_k<<<1, 1024>>>(mask);

    float* xr; cudaGetSymbolAddress((void**)&xr, g_xr);
    float* wqc; cudaGetSymbolAddress((void**)&wqc, g_wqc);
    float* wqp; cudaGetSymbolAddress((void**)&wqp, g_wqp);
    float* woc; cudaGetSymbolAddress((void**)&woc, g_woc);
    float* wop; cudaGetSymbolAddress((void**)&wop, g_wop);
    float* w1cd; cudaGetSymbolAddress((void**)&w1cd, g_w1c);
    float* w1pd; cudaGetSymbolAddress((void**)&w1pd, g_w1p);
    float* w2cd; cudaGetSymbolAddress((void**)&w2cd, g_w2c);
    float* w2pd; cudaGetSymbolAddress((void**)&w2pd, g_w2p);

    auto cvt = [&](const float* s, float* d, int n) {
        int n4 = n >> 2;
        cvt_k<<<(n4 + 255) / 256, 256>>>((const float4*)s, (float4*)d, n4);
    };
    cvt(x, xr, BT*DMOD);
    cvt(wqkv_c, wqc, HH*DM2*192);
    cvt(wqkv_p, wqp, HH*DM2*192);
    cvt(wo_c, woc, HH*DQ2*DM2);
    cvt(wo_p, wop, HH*DQ2*DM2);
    cvt(w1_c, w1cd, DF2*DM2);
    cvt(w1_p, w1pd, DF2*DM2);
    cvt(w2_c, w2cd, DM2*DF2);
    cvt(w2_p, w2pd, DM2*DF2);

    // 1. QKV (128x64 kernel; N=192 per head)
    gemm_qkv<<<dim3(3, 32, 16), 256>>>();
    // 2. DOTS: M=1024, N=1024 per (b,h)
    gemm_big<1><<<dim3(8, 8, 32), 256, big_smem>>>(nullptr, nullptr);
    // 3. masked softmax
    softmax_k<<<BB*HH*TT, 256>>>();
    // 4. PV: M=1024, N=128 per (b,h)
    gemm_big<2><<<dim3(1, 8, 32), 256, big_smem>>>(nullptr, nullptr);
    // 5. OPROJ: M=4096, N=512 per half
    gemm_big<3><<<dim3(4, 32, 2), 256, big_smem>>>(nullptr, nullptr);
    // 6. LN1
    ln_k<0><<<BT, 256>>>(x, ln1_g, ln1_b, nullptr);
    // 7. FFN1: M=4096, N=2048 per half
    gemm_big<4><<<dim3(16, 32, 2), 256, big_smem>>>(b1_c, b1_p);
    // 8. FFN2: M=4096, N=512 per half
    gemm_big<5><<<dim3(4, 32, 2), 256, big_smem>>>(b2_c, b2_p);
    // 9. LN2 -> out
    ln_k<1><<<BT, 256>>>(nullptr, ln2_g, ln2_b, out);
}

// round 6
// speedup vs baseline: 1.0297x; 1.0297x over previous
#include <cuda_runtime.h>
#include <math.h>
#include <stdint.h>

// ---------------------------------------------------------------------------
// PartitionedTransformerEncoderLayer — Round 6:
// flash-attention fusion (DOTS+softmax+PV in one kernel), HMMA tf32 GEMMs
// ---------------------------------------------------------------------------

#define HH   8
#define TT   1024
#define BB   4
#define DMOD 1024
#define DM2  512
#define DQ   128
#define DQ2  64
#define DF2  2048
#define BT   4096

// scratch
__device__ float g_q[BB*HH*TT*DQ];
__device__ float g_k[BB*HH*TT*DQ];
__device__ float g_v[BB*HH*TT*DQ];
__device__ float g_o[(size_t)BT*DMOD];
__device__ float g_t1[(size_t)BT*DMOD];
__device__ float g_x1[(size_t)BT*DMOD];
__device__ float g_x1r[(size_t)BT*DMOD];
__device__ float g_h[(size_t)BT*2*DF2];
__device__ float g_maskf[BB*TT];
__device__ float g_xr[(size_t)BT*DMOD];
__device__ float g_wqc[HH*DM2*192];
__device__ float g_wqp[HH*DM2*192];
__device__ float g_woc[HH*DQ2*DM2];
__device__ float g_wop[HH*DQ2*DM2];
__device__ float g_w1c[DF2*DM2];
__device__ float g_w1p[DF2*DM2];
__device__ float g_w2c[DM2*DF2];
__device__ float g_w2p[DM2*DF2];

// ---------------------------------------------------------------------------
__device__ __forceinline__ unsigned f2tf32u(float f) {
    unsigned u;
    asm("cvt.rna.tf32.f32 %0, %1;" : "=r"(u) : "f"(f));
    return u;
}
__device__ __forceinline__ float rtf(float f) { return __uint_as_float(f2tf32u(f)); }

__device__ __forceinline__ void cp16(void* smem, const void* g) {
    unsigned s = (unsigned)__cvta_generic_to_shared(smem);
    asm volatile("cp.async.cg.shared.global [%0], [%1], 16;" :: "r"(s), "l"(g));
}
__device__ __forceinline__ void cp_commit() { asm volatile("cp.async.commit_group;"); }
__device__ __forceinline__ void cp_wait0()  { asm volatile("cp.async.wait_group 0;"); }

__device__ __forceinline__ void ldm_x4(unsigned &r0, unsigned &r1,
                                       unsigned &r2, unsigned &r3,
                                       const unsigned* p) {
    unsigned addr = (unsigned)__cvta_generic_to_shared(p);
    asm volatile("ldmatrix.sync.aligned.m8n8.x4.shared.b16 {%0,%1,%2,%3}, [%4];"
                 : "=r"(r0), "=r"(r1), "=r"(r2), "=r"(r3) : "r"(addr));
}
__device__ __forceinline__ void mma_tf32(float* c, const unsigned* a, const unsigned* b) {
    asm volatile("mma.sync.aligned.m16n8k8.row.col.f32.tf32.tf32.f32 "
                 "{%0,%1,%2,%3}, {%4,%5,%6,%7}, {%8,%9}, {%0,%1,%2,%3};"
                 : "+f"(c[0]), "+f"(c[1]), "+f"(c[2]), "+f"(c[3])
                 : "r"(a[0]), "r"(a[1]), "r"(a[2]), "r"(a[3]),
                   "r"(b[0]), "r"(b[1]));
}

// ---------------------------------------------------------------------------
// Mask canonicalization
// ---------------------------------------------------------------------------
__global__ void mask_probe_k(const void* __restrict__ maskraw) {
    const unsigned int* w = (const unsigned int*)maskraw;
    int tid = threadIdx.x;
    unsigned int v = w[tid];
    int oki = (v == 0u || v == 1u);
    int okf = (v == 0u || v == 0x3F800000u);
    int all_i = __syncthreads_and(oki);
    int all_f = __syncthreads_and(okf);
    if (all_i) {
        const int* wi = (const int*)maskraw;
        for (int i = tid; i < BB*TT; i += 1024) g_maskf[i] = wi[i] ? 1.f : 0.f;
    } else if (all_f) {
        const float* wf = (const float*)maskraw;
        for (int i = tid; i < BB*TT; i += 1024) g_maskf[i] = (wf[i] != 0.f) ? 1.f : 0.f;
    } else {
        const unsigned char* wb = (const unsigned char*)maskraw;
        for (int i = tid; i < BB*TT; i += 1024) g_maskf[i] = wb[i] ? 1.f : 0.f;
    }
}

__global__ void __launch_bounds__(256) cvt_k(const float4* __restrict__ src,
                                             float4* __restrict__ dst, int n4) {
    int i = blockIdx.x * 256 + threadIdx.x;
    if (i < n4) {
        float4 v = src[i];
        v.x = rtf(v.x); v.y = rtf(v.y); v.z = rtf(v.z); v.w = rtf(v.w);
        dst[i] = v;
    }
}

// ---------------------------------------------------------------------------
// Flash attention: per CTA one (b,h) 128-row Q tile; loop over 16 KV tiles
// of 64 rows. S = Q K^T (HMMA tf32), online softmax, O += P V.
// 256 threads = 8 warps: 4M x 2N (warp tile m32; n32 for S, n/d 64 for PV).
// Smem (words): Qs[128][132] | Ks[64][132] | Vt[128][68] | Ps[128][68]
//               | redmax[128][2] | redsum[128][2]
// ---------------------------------------------------------------------------
#define QS_OFF  0
#define KS_OFF  16896
#define VT_OFF  25344
#define PS_OFF  34048
#define RMX_OFF 42752
#define RSM_OFF 43008
#define FLASH_SMEM_WORDS 43264

__global__ void __launch_bounds__(256, 1)
flash_k()
{
    extern __shared__ float smf[];
    unsigned* smu = (unsigned*)smf;

    const int tid  = threadIdx.x;
    const int lane = tid & 31;
    const int warp = tid >> 5;
    const int grp  = lane >> 3;
    const int rr   = lane & 7;
    const int g    = lane >> 2;
    const int tig  = lane & 3;

    const int wm  = (warp & 3) * 32;      // m offset (S and PV)
    const int wn  = (warp >> 2) * 32;     // n offset for S (t within 64)
    const int wnd = (warp >> 2) * 64;     // n offset for PV (d within 128)

    const int m0 = blockIdx.x * 128;
    const int z  = blockIdx.y;            // b*8 + h
    const int b  = z >> 3;
    const int h  = z & 7;

    const float* Qg = g_q + (size_t)z * (TT*DQ);
    const float* Kg = g_k + (size_t)z * (TT*DQ);
    const float* Vg = g_v + (size_t)z * (TT*DQ);

    // ---- prologue: async-load Q (128x128) and K tile 0 (64x128) ----
#pragma unroll
    for (int i = 0; i < 16; i++) {
        int linear = tid + i * 256;           // < 4096 float4
        int r = linear >> 5, c4 = (linear & 31) << 2;
        cp16(&smf[QS_OFF + r * 132 + c4], Qg + (size_t)(m0 + r) * DQ + c4);
    }
#pragma unroll
    for (int i = 0; i < 8; i++) {
        int linear = tid + i * 256;           // < 2048 float4
        int r = linear >> 5, c4 = (linear & 31) << 2;
        cp16(&smf[KS_OFF + r * 132 + c4], Kg + (size_t)r * DQ + c4);
    }
    cp_commit();

    // ---- state ----
    float co[2][8][4];
#pragma unroll
    for (int mt = 0; mt < 2; mt++)
#pragma unroll
        for (int nt = 0; nt < 8; nt++)
#pragma unroll
            for (int r = 0; r < 4; r++) co[mt][nt][r] = 0.f;
    float mrun[4] = {-1e30f, -1e30f, -1e30f, -1e30f};
    float lrun[4] = {0.f, 0.f, 0.f, 0.f};
    // row slot i = mt*2 + hi -> local row wm + mt*16 + g + hi*8

    for (int kt = 0; kt < 16; kt++) {
        cp_wait0();
        __syncthreads();                       // K tile (and Q on kt=0) visible; prev PV reads done

        // ---- S = Q K^T  (k = d = 128) ----
        float cs[2][4][4];
#pragma unroll
        for (int mt = 0; mt < 2; mt++)
#pragma unroll
            for (int nt = 0; nt < 4; nt++)
#pragma unroll
                for (int r = 0; r < 4; r++) cs[mt][nt][r] = 0.f;
#pragma unroll
        for (int ks = 0; ks < 16; ks++) {
            const int kw = ks * 8;
            unsigned a[2][4];
#pragma unroll
            for (int mt = 0; mt < 2; mt++)
                ldm_x4(a[mt][0], a[mt][1], a[mt][2], a[mt][3],
                       &smu[QS_OFF + (wm + mt*16 + (grp & 1)*8 + rr) * 132 + kw + (grp >> 1)*4]);
#pragma unroll
            for (int bt = 0; bt < 2; bt++) {
                unsigned b0, b1, b2, b3;
                ldm_x4(b0, b1, b2, b3,
                       &smu[KS_OFF + (wn + bt*16 + (grp >> 1)*8 + rr) * 132 + kw + (grp & 1)*4]);
                unsigned bf0[2] = {b0, b1};
                unsigned bf1[2] = {b2, b3};
#pragma unroll
                for (int mt = 0; mt < 2; mt++) {
                    mma_tf32(cs[mt][bt*2 + 0], a[mt], bf0);
                    mma_tf32(cs[mt][bt*2 + 1], a[mt], bf1);
                }
            }
        }

        // ---- V tile load + transpose (Vt[d][t]) ----
#pragma unroll
        for (int i = 0; i < 8; i++) {
            int linear = tid + i * 256;        // < 2048 float4
            int t = linear >> 5, d4 = (linear & 31) << 2;
            float4 v = *(const float4*)(Vg + (size_t)(kt*64 + t) * DQ + d4);
            smf[VT_OFF + (d4 + 0) * 68 + t] = v.x;
            smf[VT_OFF + (d4 + 1) * 68 + t] = v.y;
            smf[VT_OFF + (d4 + 2) * 68 + t] = v.z;
            smf[VT_OFF + (d4 + 3) * 68 + t] = v.w;
        }

        // ---- mask + row max partials ----
        float rmax[4] = {-1e30f, -1e30f, -1e30f, -1e30f};
#pragma unroll
        for (int mt = 0; mt < 2; mt++) {
#pragma unroll
            for (int nt = 0; nt < 4; nt++) {
                int col = kt*64 + wn + nt*8 + 2*tig;
                float2 mk = *(const float2*)&g_maskf[b*TT + col];
                if (mk.x == 0.f) { cs[mt][nt][0] = -1e30f; cs[mt][nt][2] = -1e30f; }
                if (mk.y == 0.f) { cs[mt][nt][1] = -1e30f; cs[mt][nt][3] = -1e30f; }
                rmax[mt*2+0] = fmaxf(rmax[mt*2+0], fmaxf(cs[mt][nt][0], cs[mt][nt][1]));
                rmax[mt*2+1] = fmaxf(rmax[mt*2+1], fmaxf(cs[mt][nt][2], cs[mt][nt][3]));
            }
        }
#pragma unroll
        for (int i = 0; i < 4; i++) {
            rmax[i] = fmaxf(rmax[i], __shfl_xor_sync(0xFFFFFFFFu, rmax[i], 1));
            rmax[i] = fmaxf(rmax[i], __shfl_xor_sync(0xFFFFFFFFu, rmax[i], 2));
        }
        if (tig == 0) {
#pragma unroll
            for (int i = 0; i < 4; i++) {
                int row = wm + (i >> 1)*16 + g + (i & 1)*8;
                smf[RMX_OFF + row*2 + (wn >> 5)] = rmax[i];
            }
        }
        __syncthreads();                        // redmax visible; S-ldm done -> K reload safe

        // prefetch next K tile (single buffer: all Ks reads completed above)
        if (kt + 1 < 16) {
#pragma unroll
            for (int i = 0; i < 8; i++) {
                int linear = tid + i * 256;
                int r = linear >> 5, c4 = (linear & 31) << 2;
                cp16(&smf[KS_OFF + r * 132 + c4], Kg + (size_t)((kt+1)*64 + r) * DQ + c4);
            }
        }
        cp_commit();                            // commit (possibly empty) group

        // ---- new max, p = exp(s - m), write P, row sums ----
        float newm[4], rsum[4] = {0.f, 0.f, 0.f, 0.f};
#pragma unroll
        for (int i = 0; i < 4; i++) {
            int row = wm + (i >> 1)*16 + g + (i & 1)*8;
            float cm = fmaxf(smf[RMX_OFF + row*2], smf[RMX_OFF + row*2 + 1]);
            newm[i] = fmaxf(mrun[i], cm);
        }
#pragma unroll
        for (int mt = 0; mt < 2; mt++) {
#pragma unroll
            for (int nt = 0; nt < 4; nt++) {
                int colL = wn + nt*8 + 2*tig;
                float p0 = (cs[mt][nt][0] <= -1e29f) ? 0.f : __expf(cs[mt][nt][0] - newm[mt*2+0]);
                float p1 = (cs[mt][nt][1] <= -1e29f) ? 0.f : __expf(cs[mt][nt][1] - newm[mt*2+0]);
                float p2 = (cs[mt][nt][2] <= -1e29f) ? 0.f : __expf(cs[mt][nt][2] - newm[mt*2+1]);
                float p3 = (cs[mt][nt][3] <= -1e29f) ? 0.f : __expf(cs[mt][nt][3] - newm[mt*2+1]);
                rsum[mt*2+0] += p0 + p1;
                rsum[mt*2+1] += p2 + p3;
                int rA = wm + mt*16 + g;
                smf[PS_OFF + rA*68 + colL + 0]     = rtf(p0);
                smf[PS_OFF + rA*68 + colL + 1]     = rtf(p1);
                smf[PS_OFF + (rA+8)*68 + colL + 0] = rtf(p2);
                smf[PS_OFF + (rA+8)*68 + colL + 1] = rtf(p3);
            }
        }
#pragma unroll
        for (int i = 0; i < 4; i++) {
            rsum[i] += __shfl_xor_sync(0xFFFFFFFFu, rsum[i], 1);
            rsum[i] += __shfl_xor_sync(0xFFFFFFFFu, rsum[i], 2);
        }
        if (tig == 0) {
#pragma unroll
            for (int i = 0; i < 4; i++) {
                int row = wm + (i >> 1)*16 + g + (i & 1)*8;
                smf[RSM_OFF + row*2 + (wn >> 5)] = rsum[i];
            }
        }
        __syncthreads();                        // Ps, Vt, redsum visible

        // ---- rescale O, update running stats ----
        float alpha[4];
#pragma unroll
        for (int i = 0; i < 4; i++) {
            int row = wm + (i >> 1)*16 + g + (i & 1)*8;
            float s = smf[RSM_OFF + row*2] + smf[RSM_OFF + row*2 + 1];
            alpha[i] = __expf(mrun[i] - newm[i]);
            lrun[i] = lrun[i] * alpha[i] + s;
            mrun[i] = newm[i];
        }
#pragma unroll
        for (int mt = 0; mt < 2; mt++)
#pragma unroll
            for (int nt = 0; nt < 8; nt++) {
                co[mt][nt][0] *= alpha[mt*2+0];
                co[mt][nt][1] *= alpha[mt*2+0];
                co[mt][nt][2] *= alpha[mt*2+1];
                co[mt][nt][3] *= alpha[mt*2+1];
            }

        // ---- O += P V  (k = t = 64, n = d = 128) ----
#pragma unroll
        for (int ks = 0; ks < 8; ks++) {
            const int kw = ks * 8;
            unsigned a[2][4];
#pragma unroll
            for (int mt = 0; mt < 2; mt++)
                ldm_x4(a[mt][0], a[mt][1], a[mt][2], a[mt][3],
                       &smu[PS_OFF + (wm + mt*16 + (grp & 1)*8 + rr) * 68 + kw + (grp >> 1)*4]);
#pragma unroll
            for (int bt = 0; bt < 4; bt++) {
                unsigned b0, b1, b2, b3;
                ldm_x4(b0, b1, b2, b3,
                       &smu[VT_OFF + (wnd + bt*16 + (grp >> 1)*8 + rr) * 68 + kw + (grp & 1)*4]);
                unsigned bf0[2] = {b0, b1};
                unsigned bf1[2] = {b2, b3};
#pragma unroll
                for (int mt = 0; mt < 2; mt++) {
                    mma_tf32(co[mt][bt*2 + 0], a[mt], bf0);
                    mma_tf32(co[mt][bt*2 + 1], a[mt], bf1);
                }
            }
        }
    }

    // ---- epilogue: O /= l, tf32-round, store to g_o [B,T,H*128] ----
    float invl[4];
#pragma unroll
    for (int i = 0; i < 4; i++) invl[i] = 1.0f / lrun[i];
#pragma unroll
    for (int mt = 0; mt < 2; mt++) {
#pragma unroll
        for (int nt = 0; nt < 8; nt++) {
            int rowA = m0 + wm + mt*16 + g;
            int col  = wnd + nt*8 + 2*tig;
            float2 lo = make_float2(rtf(co[mt][nt][0] * invl[mt*2+0]),
                                    rtf(co[mt][nt][1] * invl[mt*2+0]));
            float2 hi = make_float2(rtf(co[mt][nt][2] * invl[mt*2+1]),
                                    rtf(co[mt][nt][3] * invl[mt*2+1]));
            *(float2*)(g_o + ((size_t)(b*TT + rowA)) * DMOD + h*DQ + col) = lo;
            *(float2*)(g_o + ((size_t)(b*TT + rowA + 8)) * DMOD + h*DQ + col) = hi;
        }
    }
}

// ---------------------------------------------------------------------------
// HMMA tf32 GEMM (round-3 proven): 128x64x32, cp.async double-buffered.
//  0 QKV  : A=g_xr,  B=g_wq{c,p} per head -> g_q/g_k/g_v (rounded)
//  3 OPROJ: A=g_o,   B=g_wo{c,p}          -> g_t1
//  4 FFN1 : A=g_x1r, B=g_w1 (k-contig) +b relu -> g_h (rounded)
//  5 FFN2 : A=g_h,   B=g_w2 (k-contig) +b      -> g_t1
// ---------------------------------------------------------------------------
template<int MODE>
__global__ void __launch_bounds__(256)
gemm_tc(const float* __restrict__ bias0,
        const float* __restrict__ bias1)
{
    constexpr int K = (MODE == 0) ? 512 :
                      (MODE == 3) ? 512 :
                      (MODE == 4) ? 512 : 2048;
    constexpr bool B_KCONTIG = (MODE == 4 || MODE == 5);

    __shared__ unsigned As[2][128][36];
    __shared__ unsigned Bs[2][64][36];

    const int tid  = threadIdx.x;
    const int lane = tid & 31;
    const int warp = tid >> 5;
    const int wm = (warp & 3) * 32;
    const int wn = (warp >> 2) * 32;
    const int m0 = blockIdx.y * 128;
    const int n0 = blockIdx.x * 64;
    const int z  = blockIdx.z;

    const float* Abase;
    if constexpr (MODE == 0)      Abase = g_xr;
    else if constexpr (MODE == 3) Abase = g_o;
    else if constexpr (MODE == 4) Abase = g_x1r;
    else                          Abase = g_h;

    const float* Wb;
    int bstride;
    if constexpr (MODE == 0) { Wb = ((z >> 3) ? g_wqp : g_wqc) + (size_t)(z & 7) * (DM2 * 192); bstride = 192; }
    else if constexpr (MODE == 3) { Wb = z ? g_wop : g_woc; bstride = DM2; }
    else if constexpr (MODE == 4) { Wb = z ? g_w1p : g_w1c; bstride = DM2; }
    else                          { Wb = z ? g_w2p : g_w2c; bstride = DF2; }

    float c[2][4][4];
#pragma unroll
    for (int mt = 0; mt < 2; mt++)
#pragma unroll
        for (int nt = 0; nt < 4; nt++)
#pragma unroll
            for (int r = 0; r < 4; r++) c[mt][nt][r] = 0.f;

    const int a_ml = tid >> 3;
    const int a_kq = (tid & 7) << 2;
    const int bk_nl = tid >> 3;
    const int bk_kq = (tid & 7) << 2;
    const int bt_kl = tid >> 4;
    const int bt_nq = (tid & 15) << 2;

    auto a_idx = [&](int m, int k) -> size_t {
        if constexpr (MODE == 0)
            return (size_t)m * DMOD + (size_t)(z >> 3) * DM2 + k;
        else if constexpr (MODE == 3)
            return (size_t)m * DMOD + (size_t)((k >> 6) << 7) + (size_t)z * DQ2 + (k & 63);
        else if constexpr (MODE == 4)
            return (size_t)m * DMOD + (size_t)z * DM2 + k;
        else
            return (size_t)m * (2*DF2) + (size_t)z * DF2 + k;
    };

    auto loadA = [&](int k0, int buf) {
#pragma unroll
        for (int it = 0; it < 4; it++) {
            int m = m0 + a_ml + it * 32;
            cp16(&As[buf][a_ml + it * 32][a_kq], Abase + a_idx(m, k0 + a_kq));
        }
    };
    auto loadB_async = [&](int k0, int buf) {
#pragma unroll
        for (int it = 0; it < 2; it++) {
            int n = n0 + bk_nl + it * 32;
            cp16(&Bs[buf][bk_nl + it * 32][bk_kq], Wb + (size_t)n * bstride + k0 + bk_kq);
        }
    };
    float4 breg[2];
    auto ldgB = [&](int k0) {
#pragma unroll
        for (int it = 0; it < 2; it++) {
            int k = k0 + bt_kl + it * 16;
            breg[it] = *(const float4*)(Wb + (size_t)k * bstride + n0 + bt_nq);
        }
    };
    auto stsB = [&](int buf) {
#pragma unroll
        for (int it = 0; it < 2; it++) {
            int kk = bt_kl + it * 16;
            Bs[buf][bt_nq + 0][kk] = __float_as_uint(breg[it].x);
            Bs[buf][bt_nq + 1][kk] = __float_as_uint(breg[it].y);
            Bs[buf][bt_nq + 2][kk] = __float_as_uint(breg[it].z);
            Bs[buf][bt_nq + 3][kk] = __float_as_uint(breg[it].w);
        }
    };

    loadA(0, 0);
    if constexpr (B_KCONTIG) loadB_async(0, 0);
    else { ldgB(0); stsB(0); }
    cp_commit();
    cp_wait0();
    __syncthreads();

    const int grp = lane >> 3;
    const int rr  = lane & 7;

    int cur = 0;
    for (int k0 = 0; k0 < K; k0 += 32) {
        const int nxt = cur ^ 1;
        const bool has_next = (k0 + 32 < K);
        if (has_next) {
            loadA(k0 + 32, nxt);
            if constexpr (B_KCONTIG) loadB_async(k0 + 32, nxt);
            else ldgB(k0 + 32);
            cp_commit();
        }
#pragma unroll
        for (int ks = 0; ks < 4; ks++) {
            const int kw = ks * 8;
            unsigned a[2][4];
#pragma unroll
            for (int mt = 0; mt < 2; mt++) {
                const unsigned* p = &As[cur][wm + mt*16 + (grp & 1)*8 + rr][kw + (grp >> 1)*4];
                ldm_x4(a[mt][0], a[mt][1], a[mt][2], a[mt][3], p);
            }
            unsigned b[4][2];
#pragma unroll
            for (int bt = 0; bt < 2; bt++) {
                const unsigned* p = &Bs[cur][wn + bt*16 + (grp >> 1)*8 + rr][kw + (grp & 1)*4];
                unsigned r0, r1, r2, r3;
                ldm_x4(r0, r1, r2, r3, p);
                b[bt*2 + 0][0] = r0; b[bt*2 + 0][1] = r1;
                b[bt*2 + 1][0] = r2; b[bt*2 + 1][1] = r3;
            }
#pragma unroll
            for (int mt = 0; mt < 2; mt++)
#pragma unroll
                for (int nt = 0; nt < 4; nt++)
                    mma_tf32(c[mt][nt], a[mt], b[nt]);
        }
        if (has_next) {
            if constexpr (!B_KCONTIG) stsB(nxt);
            cp_wait0();
        }
        __syncthreads();
        cur = nxt;
    }

    const int g   = lane >> 2;
    const int tig = lane & 3;

#pragma unroll
    for (int mt = 0; mt < 2; mt++) {
#pragma unroll
        for (int nt = 0; nt < 4; nt++) {
            const int mr = m0 + wm + mt*16 + g;
            const int nl = wn + nt*8 + 2*tig;
            float2 lo = make_float2(c[mt][nt][0], c[mt][nt][1]);
            float2 hi = make_float2(c[mt][nt][2], c[mt][nt][3]);

            if constexpr (MODE == 0) {
                const int cc = blockIdx.x;            // 0=q 1=k 2=v (x covers 3 tiles of 64)
                const int hh = z & 7, sel = z >> 3;
                const float scale = (cc == 0) ? 0.08838834764831845f : 1.0f;
                float* dst = (cc == 0) ? g_q : ((cc == 1) ? g_k : g_v);
                lo.x = rtf(lo.x * scale); lo.y = rtf(lo.y * scale);
                hi.x = rtf(hi.x * scale); hi.y = rtf(hi.y * scale);
                {
                    int b_ = mr >> 10, t_ = mr & 1023;
                    size_t base = ((((size_t)b_*HH + hh)*TT + t_) << 7) + ((size_t)sel << 6);
                    *(float2*)(dst + base + nl) = lo;
                }
                {
                    int m2 = mr + 8;
                    int b_ = m2 >> 10, t_ = m2 & 1023;
                    size_t base = ((((size_t)b_*HH + hh)*TT + t_) << 7) + ((size_t)sel << 6);
                    *(float2*)(dst + base + nl) = hi;
                }
            } else if constexpr (MODE == 3) {
                size_t r0 = (size_t)mr * DMOD + (size_t)z * DM2 + n0 + nl;
                *(float2*)(g_t1 + r0) = lo;
                *(float2*)(g_t1 + r0 + 8*DMOD) = hi;
            } else if constexpr (MODE == 4) {
                const float* bs = z ? bias1 : bias0;
                float b0 = bs[n0 + nl], b1 = bs[n0 + nl + 1];
                size_t r0 = (size_t)mr * (2*DF2) + (size_t)z * DF2 + n0 + nl;
                float2 o0 = make_float2(rtf(fmaxf(lo.x + b0, 0.f)), rtf(fmaxf(lo.y + b1, 0.f)));
                float2 o1 = make_float2(rtf(fmaxf(hi.x + b0, 0.f)), rtf(fmaxf(hi.y + b1, 0.f)));
                *(float2*)(g_h + r0) = o0;
                *(float2*)(g_h + r0 + (size_t)8 * (2*DF2)) = o1;
            } else {
                const float* bs = z ? bias1 : bias0;
                float b0 = bs[n0 + nl], b1 = bs[n0 + nl + 1];
                size_t r0 = (size_t)mr * DMOD + (size_t)z * DM2 + n0 + nl;
                float2 o0 = make_float2(lo.x + b0, lo.y + b1);
                float2 o1 = make_float2(hi.x + b0, hi.y + b1);
                *(float2*)(g_t1 + r0) = o0;
                *(float2*)(g_t1 + r0 + 8*DMOD) = o1;
            }
        }
    }
}

// ---------------------------------------------------------------------------
// Fused residual + LayerNorm
// ---------------------------------------------------------------------------
template<int PHASE>
__global__ void __launch_bounds__(256)
ln_k(const float* __restrict__ a,
     const float* __restrict__ gamma,
     const float* __restrict__ beta,
     float* __restrict__ outp)
{
    const int row = blockIdx.x;
    const int tid = threadIdx.x;
    const int lane = tid & 31, wid = tid >> 5;
    const float* r1 = (PHASE == 0) ? a : g_x1;

    __shared__ float red1[8];
    __shared__ float red2[8];

    float4 av = ((const float4*)(r1 + (size_t)row * DMOD))[tid];
    float4 tv = ((const float4*)(g_t1 + (size_t)row * DMOD))[tid];
    float v[4] = {av.x + tv.x, av.y + tv.y, av.z + tv.z, av.w + tv.w};

    float s = v[0] + v[1] + v[2] + v[3];
#pragma unroll
    for (int o = 16; o > 0; o >>= 1) s += __shfl_xor_sync(0xFFFFFFFFu, s, o);
    if (lane == 0) red1[wid] = s;
    __syncthreads();
    float tot = red1[0];
#pragma unroll
    for (int i = 1; i < 8; i++) tot += red1[i];
    const float mu = tot * (1.0f / DMOD);

    float vs = 0.f;
#pragma unroll
    for (int i = 0; i < 4; i++) { float d = v[i] - mu; vs += d * d; }
#pragma unroll
    for (int o = 16; o > 0; o >>= 1) vs += __shfl_xor_sync(0xFFFFFFFFu, vs, o);
    if (lane == 0) red2[wid] = vs;
    __syncthreads();
    float vtot = red2[0];
#pragma unroll
    for (int i = 1; i < 8; i++) vtot += red2[i];
    const float rs = rsqrtf(vtot * (1.0f / DMOD) + 1e-5f);

    float4 g4 = ((const float4*)gamma)[tid];
    float4 b4 = ((const float4*)beta)[tid];
    float4 o4;
    o4.x = (v[0] - mu) * rs * g4.x + b4.x;
    o4.y = (v[1] - mu) * rs * g4.y + b4.y;
    o4.z = (v[2] - mu) * rs * g4.z + b4.z;
    o4.w = (v[3] - mu) * rs * g4.w + b4.w;

    if constexpr (PHASE == 0) {
        ((float4*)(g_x1 + (size_t)row * DMOD))[tid] = o4;
        float4 r4;
        r4.x = rtf(o4.x); r4.y = rtf(o4.y); r4.z = rtf(o4.z); r4.w = rtf(o4.w);
        ((float4*)(g_x1r + (size_t)row * DMOD))[tid] = r4;
    } else {
        ((float4*)(outp + (size_t)row * DMOD))[tid] = o4;
    }
}

// ---------------------------------------------------------------------------
extern "C" void kernel_launch(void* const* d_in, const int* in_sizes, int n_in,
                              void* d_out, int out_size)
{
    (void)in_sizes; (void)n_in; (void)out_size;
    const float* x      = (const float*)d_in[0];
    const void*  mask   = d_in[1];
    const float* wqkv_c = (const float*)d_in[2];
    const float* wqkv_p = (const float*)d_in[3];
    const float* wo_c   = (const float*)d_in[4];
    const float* wo_p   = (const float*)d_in[5];
    const float* w1_c   = (const float*)d_in[6];
    const float* b1_c   = (const float*)d_in[7];
    const float* w1_p   = (const float*)d_in[8];
    const float* b1_p   = (const float*)d_in[9];
    const float* w2_c   = (const float*)d_in[10];
    const float* b2_c   = (const float*)d_in[11];
    const float* w2_p   = (const float*)d_in[12];
    const float* b2_p   = (const float*)d_in[13];
    const float* ln1_g  = (const float*)d_in[14];
    const float* ln1_b  = (const float*)d_in[15];
    const float* ln2_g  = (const float*)d_in[16];
    const float* ln2_b  = (const float*)d_in[17];
    float* out = (float*)d_out;

    const int flash_smem = FLASH_SMEM_WORDS * 4;   // 173056 B
    cudaFuncSetAttribute(flash_k, cudaFuncAttributeMaxDynamicSharedMemorySize, flash_smem);

    mask_probe_k<<<1, 1024>>>(mask);

    float* xr; cudaGetSymbolAddress((void**)&xr, g_xr);
    float* wqc; cudaGetSymbolAddress((void**)&wqc, g_wqc);
    float* wqp; cudaGetSymbolAddress((void**)&wqp, g_wqp);
    float* woc; cudaGetSymbolAddress((void**)&woc, g_woc);
    float* wop; cudaGetSymbolAddress((void**)&wop, g_wop);
    float* w1cd; cudaGetSymbolAddress((void**)&w1cd, g_w1c);
    float* w1pd; cudaGetSymbolAddress((void**)&w1pd, g_w1p);
    float* w2cd; cudaGetSymbolAddress((void**)&w2cd, g_w2c);
    float* w2pd; cudaGetSymbolAddress((void**)&w2pd, g_w2p);

    auto cvt = [&](const float* s, float* d, int n) {
        int n4 = n >> 2;
        cvt_k<<<(n4 + 255) / 256, 256>>>((const float4*)s, (float4*)d, n4);
    };
    cvt(x, xr, BT*DMOD);
    cvt(wqkv_c, wqc, HH*DM2*192);
    cvt(wqkv_p, wqp, HH*DM2*192);
    cvt(wo_c, woc, HH*DQ2*DM2);
    cvt(wo_p, wop, HH*DQ2*DM2);
    cvt(w1_c, w1cd, DF2*DM2);
    cvt(w1_p, w1pd, DF2*DM2);
    cvt(w2_c, w2cd, DM2*DF2);
    cvt(w2_p, w2pd, DM2*DF2);

    // 1. QKV
    gemm_tc<0><<<dim3(3, 32, 16), 256>>>(nullptr, nullptr);
    // 2-4. flash attention (DOTS + softmax + PV fused)
    flash_k<<<dim3(8, 32), 256, flash_smem>>>();
    // 5. OPROJ
    gemm_tc<3><<<dim3(8, 32, 2), 256>>>(nullptr, nullptr);
    // 6. LN1
    ln_k<0><<<BT, 256>>>(x, ln1_g, ln1_b, nullptr);
    // 7. FFN1
    gemm_tc<4><<<dim3(32, 32, 2), 256>>>(b1_c, b1_p);
    // 8. FFN2
    gemm_tc<5><<<dim3(8, 32, 2), 256>>>(b2_c, b2_p);
    // 9. LN2 -> out
    ln_k<1><<<BT, 256>>>(nullptr, ln2_g, ln2_b, out);
}

// round 7
// speedup vs baseline: 1.1579x; 1.1245x over previous
#include <cuda_runtime.h>
#include <cuda_bf16.h>
#include <math.h>
#include <stdint.h>

// ---------------------------------------------------------------------------
// PartitionedTransformerEncoderLayer — Round 7:
// bf16 HMMA FFN (m16n8k16), tf32 HMMA attention path, flash attention fused
// ---------------------------------------------------------------------------

#define HH   8
#define TT   1024
#define BB   4
#define DMOD 1024
#define DM2  512
#define DQ   128
#define DQ2  64
#define DF2  2048
#define BT   4096

// scratch
__device__ float g_q[BB*HH*TT*DQ];
__device__ float g_k[BB*HH*TT*DQ];
__device__ float g_v[BB*HH*TT*DQ];
__device__ float g_o[(size_t)BT*DMOD];
__device__ float g_t1[(size_t)BT*DMOD];
__device__ float g_x1[(size_t)BT*DMOD];
__device__ float g_maskf[BB*TT];
__device__ float g_xr[(size_t)BT*DMOD];
__device__ float g_wqc[HH*DM2*192];
__device__ float g_wqp[HH*DM2*192];
__device__ float g_woc[HH*DQ2*DM2];
__device__ float g_wop[HH*DQ2*DM2];
// bf16 FFN operands
__device__ unsigned short g_x1b[(size_t)BT*DMOD];
__device__ unsigned short g_hb[(size_t)BT*2*DF2];
__device__ unsigned short g_w1cb[DF2*DM2];
__device__ unsigned short g_w1pb[DF2*DM2];
__device__ unsigned short g_w2cb[DM2*DF2];
__device__ unsigned short g_w2pb[DM2*DF2];

// ---------------------------------------------------------------------------
__device__ __forceinline__ unsigned f2tf32u(float f) {
    unsigned u;
    asm("cvt.rna.tf32.f32 %0, %1;" : "=r"(u) : "f"(f));
    return u;
}
__device__ __forceinline__ float rtf(float f) { return __uint_as_float(f2tf32u(f)); }

__device__ __forceinline__ unsigned bfpack(float lo, float hi) {
    unsigned r;
    asm("cvt.rn.bf16x2.f32 %0, %1, %2;" : "=r"(r) : "f"(hi), "f"(lo));
    return r;
}

__device__ __forceinline__ void cp16(void* smem, const void* g) {
    unsigned s = (unsigned)__cvta_generic_to_shared(smem);
    asm volatile("cp.async.cg.shared.global [%0], [%1], 16;" :: "r"(s), "l"(g));
}
__device__ __forceinline__ void cp_commit() { asm volatile("cp.async.commit_group;"); }
__device__ __forceinline__ void cp_wait0()  { asm volatile("cp.async.wait_group 0;"); }

__device__ __forceinline__ void ldm_x4(unsigned &r0, unsigned &r1,
                                       unsigned &r2, unsigned &r3,
                                       const void* p) {
    unsigned addr = (unsigned)__cvta_generic_to_shared(p);
    asm volatile("ldmatrix.sync.aligned.m8n8.x4.shared.b16 {%0,%1,%2,%3}, [%4];"
                 : "=r"(r0), "=r"(r1), "=r"(r2), "=r"(r3) : "r"(addr));
}
__device__ __forceinline__ void mma_tf32(float* c, const unsigned* a, const unsigned* b) {
    asm volatile("mma.sync.aligned.m16n8k8.row.col.f32.tf32.tf32.f32 "
                 "{%0,%1,%2,%3}, {%4,%5,%6,%7}, {%8,%9}, {%0,%1,%2,%3};"
                 : "+f"(c[0]), "+f"(c[1]), "+f"(c[2]), "+f"(c[3])
                 : "r"(a[0]), "r"(a[1]), "r"(a[2]), "r"(a[3]),
                   "r"(b[0]), "r"(b[1]));
}
__device__ __forceinline__ void mma_bf16(float* c, const unsigned* a, const unsigned* b) {
    asm volatile("mma.sync.aligned.m16n8k16.row.col.f32.bf16.bf16.f32 "
                 "{%0,%1,%2,%3}, {%4,%5,%6,%7}, {%8,%9}, {%0,%1,%2,%3};"
                 : "+f"(c[0]), "+f"(c[1]), "+f"(c[2]), "+f"(c[3])
                 : "r"(a[0]), "r"(a[1]), "r"(a[2]), "r"(a[3]),
                   "r"(b[0]), "r"(b[1]));
}

// ---------------------------------------------------------------------------
// Mask canonicalization
// ---------------------------------------------------------------------------
__global__ void mask_probe_k(const void* __restrict__ maskraw) {
    const unsigned int* w = (const unsigned int*)maskraw;
    int tid = threadIdx.x;
    unsigned int v = w[tid];
    int oki = (v == 0u || v == 1u);
    int okf = (v == 0u || v == 0x3F800000u);
    int all_i = __syncthreads_and(oki);
    int all_f = __syncthreads_and(okf);
    if (all_i) {
        const int* wi = (const int*)maskraw;
        for (int i = tid; i < BB*TT; i += 1024) g_maskf[i] = wi[i] ? 1.f : 0.f;
    } else if (all_f) {
        const float* wf = (const float*)maskraw;
        for (int i = tid; i < BB*TT; i += 1024) g_maskf[i] = (wf[i] != 0.f) ? 1.f : 0.f;
    } else {
        const unsigned char* wb = (const unsigned char*)maskraw;
        for (int i = tid; i < BB*TT; i += 1024) g_maskf[i] = wb[i] ? 1.f : 0.f;
    }
}

__global__ void __launch_bounds__(256) cvt_k(const float4* __restrict__ src,
                                             float4* __restrict__ dst, int n4) {
    int i = blockIdx.x * 256 + threadIdx.x;
    if (i < n4) {
        float4 v = src[i];
        v.x = rtf(v.x); v.y = rtf(v.y); v.z = rtf(v.z); v.w = rtf(v.w);
        dst[i] = v;
    }
}

// fp32 -> bf16 round-copy
__global__ void __launch_bounds__(256) cvtb_k(const float4* __restrict__ src,
                                              uint2* __restrict__ dst, int n4) {
    int i = blockIdx.x * 256 + threadIdx.x;
    if (i < n4) {
        float4 v = src[i];
        uint2 p;
        p.x = bfpack(v.x, v.y);
        p.y = bfpack(v.z, v.w);
        dst[i] = p;
    }
}

// ---------------------------------------------------------------------------
// Flash attention (unchanged from round 6, passing at rel_err 9.7e-5)
// ---------------------------------------------------------------------------
#define QS_OFF  0
#define KS_OFF  16896
#define VT_OFF  25344
#define PS_OFF  34048
#define RMX_OFF 42752
#define RSM_OFF 43008
#define FLASH_SMEM_WORDS 43264

__global__ void __launch_bounds__(256, 1)
flash_k()
{
    extern __shared__ float smf[];
    unsigned* smu = (unsigned*)smf;

    const int tid  = threadIdx.x;
    const int lane = tid & 31;
    const int warp = tid >> 5;
    const int grp  = lane >> 3;
    const int rr   = lane & 7;
    const int g    = lane >> 2;
    const int tig  = lane & 3;

    const int wm  = (warp & 3) * 32;
    const int wn  = (warp >> 2) * 32;
    const int wnd = (warp >> 2) * 64;

    const int m0 = blockIdx.x * 128;
    const int z  = blockIdx.y;
    const int b  = z >> 3;
    const int h  = z & 7;

    const float* Qg = g_q + (size_t)z * (TT*DQ);
    const float* Kg = g_k + (size_t)z * (TT*DQ);
    const float* Vg = g_v + (size_t)z * (TT*DQ);

#pragma unroll
    for (int i = 0; i < 16; i++) {
        int linear = tid + i * 256;
        int r = linear >> 5, c4 = (linear & 31) << 2;
        cp16(&smf[QS_OFF + r * 132 + c4], Qg + (size_t)(m0 + r) * DQ + c4);
    }
#pragma unroll
    for (int i = 0; i < 8; i++) {
        int linear = tid + i * 256;
        int r = linear >> 5, c4 = (linear & 31) << 2;
        cp16(&smf[KS_OFF + r * 132 + c4], Kg + (size_t)r * DQ + c4);
    }
    cp_commit();

    float co[2][8][4];
#pragma unroll
    for (int mt = 0; mt < 2; mt++)
#pragma unroll
        for (int nt = 0; nt < 8; nt++)
#pragma unroll
            for (int r = 0; r < 4; r++) co[mt][nt][r] = 0.f;
    float mrun[4] = {-1e30f, -1e30f, -1e30f, -1e30f};
    float lrun[4] = {0.f, 0.f, 0.f, 0.f};

    for (int kt = 0; kt < 16; kt++) {
        cp_wait0();
        __syncthreads();

        float cs[2][4][4];
#pragma unroll
        for (int mt = 0; mt < 2; mt++)
#pragma unroll
            for (int nt = 0; nt < 4; nt++)
#pragma unroll
                for (int r = 0; r < 4; r++) cs[mt][nt][r] = 0.f;
#pragma unroll
        for (int ks = 0; ks < 16; ks++) {
            const int kw = ks * 8;
            unsigned a[2][4];
#pragma unroll
            for (int mt = 0; mt < 2; mt++)
                ldm_x4(a[mt][0], a[mt][1], a[mt][2], a[mt][3],
                       &smu[QS_OFF + (wm + mt*16 + (grp & 1)*8 + rr) * 132 + kw + (grp >> 1)*4]);
#pragma unroll
            for (int bt = 0; bt < 2; bt++) {
                unsigned b0, b1, b2, b3;
                ldm_x4(b0, b1, b2, b3,
                       &smu[KS_OFF + (wn + bt*16 + (grp >> 1)*8 + rr) * 132 + kw + (grp & 1)*4]);
                unsigned bf0[2] = {b0, b1};
                unsigned bf1[2] = {b2, b3};
#pragma unroll
                for (int mt = 0; mt < 2; mt++) {
                    mma_tf32(cs[mt][bt*2 + 0], a[mt], bf0);
                    mma_tf32(cs[mt][bt*2 + 1], a[mt], bf1);
                }
            }
        }

#pragma unroll
        for (int i = 0; i < 8; i++) {
            int linear = tid + i * 256;
            int t = linear >> 5, d4 = (linear & 31) << 2;
            float4 v = *(const float4*)(Vg + (size_t)(kt*64 + t) * DQ + d4);
            smf[VT_OFF + (d4 + 0) * 68 + t] = v.x;
            smf[VT_OFF + (d4 + 1) * 68 + t] = v.y;
            smf[VT_OFF + (d4 + 2) * 68 + t] = v.z;
            smf[VT_OFF + (d4 + 3) * 68 + t] = v.w;
        }

        float rmax[4] = {-1e30f, -1e30f, -1e30f, -1e30f};
#pragma unroll
        for (int mt = 0; mt < 2; mt++) {
#pragma unroll
            for (int nt = 0; nt < 4; nt++) {
                int col = kt*64 + wn + nt*8 + 2*tig;
                float2 mk = *(const float2*)&g_maskf[b*TT + col];
                if (mk.x == 0.f) { cs[mt][nt][0] = -1e30f; cs[mt][nt][2] = -1e30f; }
                if (mk.y == 0.f) { cs[mt][nt][1] = -1e30f; cs[mt][nt][3] = -1e30f; }
                rmax[mt*2+0] = fmaxf(rmax[mt*2+0], fmaxf(cs[mt][nt][0], cs[mt][nt][1]));
                rmax[mt*2+1] = fmaxf(rmax[mt*2+1], fmaxf(cs[mt][nt][2], cs[mt][nt][3]));
            }
        }
#pragma unroll
        for (int i = 0; i < 4; i++) {
            rmax[i] = fmaxf(rmax[i], __shfl_xor_sync(0xFFFFFFFFu, rmax[i], 1));
            rmax[i] = fmaxf(rmax[i], __shfl_xor_sync(0xFFFFFFFFu, rmax[i], 2));
        }
        if (tig == 0) {
#pragma unroll
            for (int i = 0; i < 4; i++) {
                int row = wm + (i >> 1)*16 + g + (i & 1)*8;
                smf[RMX_OFF + row*2 + (wn >> 5)] = rmax[i];
            }
        }
        __syncthreads();

        if (kt + 1 < 16) {
#pragma unroll
            for (int i = 0; i < 8; i++) {
                int linear = tid + i * 256;
                int r = linear >> 5, c4 = (linear & 31) << 2;
                cp16(&smf[KS_OFF + r * 132 + c4], Kg + (size_t)((kt+1)*64 + r) * DQ + c4);
            }
        }
        cp_commit();

        float newm[4], rsum[4] = {0.f, 0.f, 0.f, 0.f};
#pragma unroll
        for (int i = 0; i < 4; i++) {
            int row = wm + (i >> 1)*16 + g + (i & 1)*8;
            float cm = fmaxf(smf[RMX_OFF + row*2], smf[RMX_OFF + row*2 + 1]);
            newm[i] = fmaxf(mrun[i], cm);
        }
#pragma unroll
        for (int mt = 0; mt < 2; mt++) {
#pragma unroll
            for (int nt = 0; nt < 4; nt++) {
                int colL = wn + nt*8 + 2*tig;
                float p0 = (cs[mt][nt][0] <= -1e29f) ? 0.f : __expf(cs[mt][nt][0] - newm[mt*2+0]);
                float p1 = (cs[mt][nt][1] <= -1e29f) ? 0.f : __expf(cs[mt][nt][1] - newm[mt*2+0]);
                float p2 = (cs[mt][nt][2] <= -1e29f) ? 0.f : __expf(cs[mt][nt][2] - newm[mt*2+1]);
                float p3 = (cs[mt][nt][3] <= -1e29f) ? 0.f : __expf(cs[mt][nt][3] - newm[mt*2+1]);
                rsum[mt*2+0] += p0 + p1;
                rsum[mt*2+1] += p2 + p3;
                int rA = wm + mt*16 + g;
                smf[PS_OFF + rA*68 + colL + 0]     = rtf(p0);
                smf[PS_OFF + rA*68 + colL + 1]     = rtf(p1);
                smf[PS_OFF + (rA+8)*68 + colL + 0] = rtf(p2);
                smf[PS_OFF + (rA+8)*68 + colL + 1] = rtf(p3);
            }
        }
#pragma unroll
        for (int i = 0; i < 4; i++) {
            rsum[i] += __shfl_xor_sync(0xFFFFFFFFu, rsum[i], 1);
            rsum[i] += __shfl_xor_sync(0xFFFFFFFFu, rsum[i], 2);
        }
        if (tig == 0) {
#pragma unroll
            for (int i = 0; i < 4; i++) {
                int row = wm + (i >> 1)*16 + g + (i & 1)*8;
                smf[RSM_OFF + row*2 + (wn >> 5)] = rsum[i];
            }
        }
        __syncthreads();

        float alpha[4];
#pragma unroll
        for (int i = 0; i < 4; i++) {
            int row = wm + (i >> 1)*16 + g + (i & 1)*8;
            float s = smf[RSM_OFF + row*2] + smf[RSM_OFF + row*2 + 1];
            alpha[i] = __expf(mrun[i] - newm[i]);
            lrun[i] = lrun[i] * alpha[i] + s;
            mrun[i] = newm[i];
        }
#pragma unroll
        for (int mt = 0; mt < 2; mt++)
#pragma unroll
            for (int nt = 0; nt < 8; nt++) {
                co[mt][nt][0] *= alpha[mt*2+0];
                co[mt][nt][1] *= alpha[mt*2+0];
                co[mt][nt][2] *= alpha[mt*2+1];
                co[mt][nt][3] *= alpha[mt*2+1];
            }

#pragma unroll
        for (int ks = 0; ks < 8; ks++) {
            const int kw = ks * 8;
            unsigned a[2][4];
#pragma unroll
            for (int mt = 0; mt < 2; mt++)
                ldm_x4(a[mt][0], a[mt][1], a[mt][2], a[mt][3],
                       &smu[PS_OFF + (wm + mt*16 + (grp & 1)*8 + rr) * 68 + kw + (grp >> 1)*4]);
#pragma unroll
            for (int bt = 0; bt < 4; bt++) {
                unsigned b0, b1, b2, b3;
                ldm_x4(b0, b1, b2, b3,
                       &smu[VT_OFF + (wnd + bt*16 + (grp >> 1)*8 + rr) * 68 + kw + (grp & 1)*4]);
                unsigned bf0[2] = {b0, b1};
                unsigned bf1[2] = {b2, b3};
#pragma unroll
                for (int mt = 0; mt < 2; mt++) {
                    mma_tf32(co[mt][bt*2 + 0], a[mt], bf0);
                    mma_tf32(co[mt][bt*2 + 1], a[mt], bf1);
                }
            }
        }
    }

    float invl[4];
#pragma unroll
    for (int i = 0; i < 4; i++) invl[i] = 1.0f / lrun[i];
#pragma unroll
    for (int mt = 0; mt < 2; mt++) {
#pragma unroll
        for (int nt = 0; nt < 8; nt++) {
            int rowA = m0 + wm + mt*16 + g;
            int col  = wnd + nt*8 + 2*tig;
            float2 lo = make_float2(rtf(co[mt][nt][0] * invl[mt*2+0]),
                                    rtf(co[mt][nt][1] * invl[mt*2+0]));
            float2 hi = make_float2(rtf(co[mt][nt][2] * invl[mt*2+1]),
                                    rtf(co[mt][nt][3] * invl[mt*2+1]));
            *(float2*)(g_o + ((size_t)(b*TT + rowA)) * DMOD + h*DQ + col) = lo;
            *(float2*)(g_o + ((size_t)(b*TT + rowA + 8)) * DMOD + h*DQ + col) = hi;
        }
    }
}

// ---------------------------------------------------------------------------
// tf32 HMMA GEMM (QKV, OPROJ) — round-3 proven
// ---------------------------------------------------------------------------
template<int MODE>
__global__ void __launch_bounds__(256)
gemm_tc()
{
    constexpr int K = 512;

    __shared__ unsigned As[2][128][36];
    __shared__ unsigned Bs[2][64][36];

    const int tid  = threadIdx.x;
    const int lane = tid & 31;
    const int warp = tid >> 5;
    const int wm = (warp & 3) * 32;
    const int wn = (warp >> 2) * 32;
    const int m0 = blockIdx.y * 128;
    const int n0 = blockIdx.x * 64;
    const int z  = blockIdx.z;

    const float* Abase = (MODE == 0) ? g_xr : g_o;

    const float* Wb;
    int bstride;
    if constexpr (MODE == 0) { Wb = ((z >> 3) ? g_wqp : g_wqc) + (size_t)(z & 7) * (DM2 * 192); bstride = 192; }
    else                     { Wb = z ? g_wop : g_woc; bstride = DM2; }

    float c[2][4][4];
#pragma unroll
    for (int mt = 0; mt < 2; mt++)
#pragma unroll
        for (int nt = 0; nt < 4; nt++)
#pragma unroll
            for (int r = 0; r < 4; r++) c[mt][nt][r] = 0.f;

    const int a_ml = tid >> 3;
    const int a_kq = (tid & 7) << 2;
    const int bt_kl = tid >> 4;
    const int bt_nq = (tid & 15) << 2;

    auto a_idx = [&](int m, int k) -> size_t {
        if constexpr (MODE == 0)
            return (size_t)m * DMOD + (size_t)(z >> 3) * DM2 + k;
        else
            return (size_t)m * DMOD + (size_t)((k >> 6) << 7) + (size_t)z * DQ2 + (k & 63);
    };

    auto loadA = [&](int k0, int buf) {
#pragma unroll
        for (int it = 0; it < 4; it++) {
            int m = m0 + a_ml + it * 32;
            cp16(&As[buf][a_ml + it * 32][a_kq], Abase + a_idx(m, k0 + a_kq));
        }
    };
    float4 breg[2];
    auto ldgB = [&](int k0) {
#pragma unroll
        for (int it = 0; it < 2; it++) {
            int k = k0 + bt_kl + it * 16;
            breg[it] = *(const float4*)(Wb + (size_t)k * bstride + n0 + bt_nq);
        }
    };
    auto stsB = [&](int buf) {
#pragma unroll
        for (int it = 0; it < 2; it++) {
            int kk = bt_kl + it * 16;
            Bs[buf][bt_nq + 0][kk] = __float_as_uint(breg[it].x);
            Bs[buf][bt_nq + 1][kk] = __float_as_uint(breg[it].y);
            Bs[buf][bt_nq + 2][kk] = __float_as_uint(breg[it].z);
            Bs[buf][bt_nq + 3][kk] = __float_as_uint(breg[it].w);
        }
    };

    loadA(0, 0);
    ldgB(0); stsB(0);
    cp_commit();
    cp_wait0();
    __syncthreads();

    const int grp = lane >> 3;
    const int rr  = lane & 7;

    int cur = 0;
    for (int k0 = 0; k0 < K; k0 += 32) {
        const int nxt = cur ^ 1;
        const bool has_next = (k0 + 32 < K);
        if (has_next) {
            loadA(k0 + 32, nxt);
            ldgB(k0 + 32);
            cp_commit();
        }
#pragma unroll
        for (int ks = 0; ks < 4; ks++) {
            const int kw = ks * 8;
            unsigned a[2][4];
#pragma unroll
            for (int mt = 0; mt < 2; mt++) {
                const unsigned* p = &As[cur][wm + mt*16 + (grp & 1)*8 + rr][kw + (grp >> 1)*4];
                ldm_x4(a[mt][0], a[mt][1], a[mt][2], a[mt][3], p);
            }
            unsigned b[4][2];
#pragma unroll
            for (int bt = 0; bt < 2; bt++) {
                const unsigned* p = &Bs[cur][wn + bt*16 + (grp >> 1)*8 + rr][kw + (grp & 1)*4];
                unsigned r0, r1, r2, r3;
                ldm_x4(r0, r1, r2, r3, p);
                b[bt*2 + 0][0] = r0; b[bt*2 + 0][1] = r1;
                b[bt*2 + 1][0] = r2; b[bt*2 + 1][1] = r3;
            }
#pragma unroll
            for (int mt = 0; mt < 2; mt++)
#pragma unroll
                for (int nt = 0; nt < 4; nt++)
                    mma_tf32(c[mt][nt], a[mt], b[nt]);
        }
        if (has_next) {
            stsB(nxt);
            cp_wait0();
        }
        __syncthreads();
        cur = nxt;
    }

    const int g   = lane >> 2;
    const int tig = lane & 3;

#pragma unroll
    for (int mt = 0; mt < 2; mt++) {
#pragma unroll
        for (int nt = 0; nt < 4; nt++) {
            const int mr = m0 + wm + mt*16 + g;
            const int nl = wn + nt*8 + 2*tig;
            float2 lo = make_float2(c[mt][nt][0], c[mt][nt][1]);
            float2 hi = make_float2(c[mt][nt][2], c[mt][nt][3]);

            if constexpr (MODE == 0) {
                const int cc = blockIdx.x;
                const int hh = z & 7, sel = z >> 3;
                const float scale = (cc == 0) ? 0.08838834764831845f : 1.0f;
                float* dst = (cc == 0) ? g_q : ((cc == 1) ? g_k : g_v);
                lo.x = rtf(lo.x * scale); lo.y = rtf(lo.y * scale);
                hi.x = rtf(hi.x * scale); hi.y = rtf(hi.y * scale);
                {
                    int b_ = mr >> 10, t_ = mr & 1023;
                    size_t base = ((((size_t)b_*HH + hh)*TT + t_) << 7) + ((size_t)sel << 6);
                    *(float2*)(dst + base + nl) = lo;
                }
                {
                    int m2 = mr + 8;
                    int b_ = m2 >> 10, t_ = m2 & 1023;
                    size_t base = ((((size_t)b_*HH + hh)*TT + t_) << 7) + ((size_t)sel << 6);
                    *(float2*)(dst + base + nl) = hi;
                }
            } else {
                size_t r0 = (size_t)mr * DMOD + (size_t)z * DM2 + n0 + nl;
                *(float2*)(g_t1 + r0) = lo;
                *(float2*)(g_t1 + r0 + 8*DMOD) = hi;
            }
        }
    }
}

// ---------------------------------------------------------------------------
// bf16 HMMA GEMM (FFN): 128x64x32 tiles, m16n8k16, cp.async double-buffered.
//  MODE 4 FFN1: A=g_x1b [BT][DMOD] half z, B=g_w1{c,p}b [DF2][DM2]
//               +bias relu -> g_hb (bf16)
//  MODE 5 FFN2: A=g_hb [BT][2*DF2] half z, B=g_w2{c,p}b [DM2][DF2]
//               +bias -> g_t1 (fp32)
// ---------------------------------------------------------------------------
template<int MODE>
__global__ void __launch_bounds__(256)
gemm_bf(const float* __restrict__ bias0,
        const float* __restrict__ bias1)
{
    constexpr int K = (MODE == 4) ? 512 : 2048;

    __shared__ unsigned short As[2][128][40];
    __shared__ unsigned short Bs[2][64][40];

    const int tid  = threadIdx.x;
    const int lane = tid & 31;
    const int warp = tid >> 5;
    const int wm = (warp & 3) * 32;
    const int wn = (warp >> 2) * 32;
    const int m0 = blockIdx.y * 128;
    const int n0 = blockIdx.x * 64;
    const int z  = blockIdx.z;

    const unsigned short* Ab;
    int astr;
    if constexpr (MODE == 4) { Ab = g_x1b + (size_t)z * DM2; astr = DMOD;  }
    else                     { Ab = g_hb  + (size_t)z * DF2; astr = 2*DF2; }

    const unsigned short* Wb;
    int bstr;
    if constexpr (MODE == 4) { Wb = z ? g_w1pb : g_w1cb; bstr = DM2; }
    else                     { Wb = z ? g_w2pb : g_w2cb; bstr = DF2; }

    float c[2][4][4];
#pragma unroll
    for (int mt = 0; mt < 2; mt++)
#pragma unroll
        for (int nt = 0; nt < 4; nt++)
#pragma unroll
            for (int r = 0; r < 4; r++) c[mt][nt][r] = 0.f;

    const int ld_r  = tid >> 2;          // 0..63
    const int ld_c8 = (tid & 3) << 3;    // 0,8,16,24 (bf16 elems; 16B chunks)

    auto loadA = [&](int k0, int buf) {
#pragma unroll
        for (int it = 0; it < 2; it++) {
            int m = m0 + ld_r + it * 64;
            cp16(&As[buf][ld_r + it * 64][ld_c8], Ab + (size_t)m * astr + k0 + ld_c8);
        }
    };
    auto loadB = [&](int k0, int buf) {
        int n = n0 + ld_r;
        cp16(&Bs[buf][ld_r][ld_c8], Wb + (size_t)n * bstr + k0 + ld_c8);
    };

    loadA(0, 0);
    loadB(0, 0);
    cp_commit();
    cp_wait0();
    __syncthreads();

    const int l16 = lane & 15;           // row within 16
    const int kh  = (lane >> 4) * 8;     // k-half (8 bf16 = 16B)

    int cur = 0;
    for (int k0 = 0; k0 < K; k0 += 32) {
        const int nxt = cur ^ 1;
        const bool has_next = (k0 + 32 < K);
        if (has_next) {
            loadA(k0 + 32, nxt);
            loadB(k0 + 32, nxt);
            cp_commit();
        }
#pragma unroll
        for (int ks = 0; ks < 2; ks++) {
            const int kofs = ks * 16 + kh;
            unsigned a[2][4];
#pragma unroll
            for (int mt = 0; mt < 2; mt++)
                ldm_x4(a[mt][0], a[mt][1], a[mt][2], a[mt][3],
                       &As[cur][wm + mt*16 + l16][kofs]);
            unsigned b[4][2];
#pragma unroll
            for (int bt = 0; bt < 2; bt++) {
                unsigned r0, r1, r2, r3;
                ldm_x4(r0, r1, r2, r3, &Bs[cur][wn + bt*16 + l16][kofs]);
                b[bt*2 + 0][0] = r0; b[bt*2 + 0][1] = r2;
                b[bt*2 + 1][0] = r1; b[bt*2 + 1][1] = r3;
            }
#pragma unroll
            for (int mt = 0; mt < 2; mt++)
#pragma unroll
                for (int nt = 0; nt < 4; nt++)
                    mma_bf16(c[mt][nt], a[mt], b[nt]);
        }
        if (has_next) cp_wait0();
        __syncthreads();
        cur = nxt;
    }

    // ---- epilogue ----
    const int g   = lane >> 2;
    const int tig = lane & 3;
    const float* bs = z ? bias1 : bias0;

#pragma unroll
    for (int mt = 0; mt < 2; mt++) {
#pragma unroll
        for (int nt = 0; nt < 4; nt++) {
            const int mr = m0 + wm + mt*16 + g;
            const int nl = wn + nt*8 + 2*tig;
            float b0 = bs[n0 + nl], b1 = bs[n0 + nl + 1];

            if constexpr (MODE == 4) {
                float p0 = fmaxf(c[mt][nt][0] + b0, 0.f);
                float p1 = fmaxf(c[mt][nt][1] + b1, 0.f);
                float p2 = fmaxf(c[mt][nt][2] + b0, 0.f);
                float p3 = fmaxf(c[mt][nt][3] + b1, 0.f);
                size_t e0 = (size_t)mr * (2*DF2) + (size_t)z * DF2 + n0 + nl;
                *(unsigned*)&g_hb[e0] = bfpack(p0, p1);
                *(unsigned*)&g_hb[e0 + (size_t)8 * (2*DF2)] = bfpack(p2, p3);
            } else {
                size_t r0 = (size_t)mr * DMOD + (size_t)z * DM2 + n0 + nl;
                float2 o0 = make_float2(c[mt][nt][0] + b0, c[mt][nt][1] + b1);
                float2 o1 = make_float2(c[mt][nt][2] + b0, c[mt][nt][3] + b1);
                *(float2*)(g_t1 + r0) = o0;
                *(float2*)(g_t1 + r0 + 8*DMOD) = o1;
            }
        }
    }
}

// ---------------------------------------------------------------------------
// Fused residual + LayerNorm
// PHASE 0: g_x1 = LN(x + g_t1) fp32, plus g_x1b bf16 copy (FFN1 operand)
// PHASE 1: out  = LN(g_x1 + g_t1)
// ---------------------------------------------------------------------------
template<int PHASE>
__global__ void __launch_bounds__(256)
ln_k(const float* __restrict__ a,
     const float* __restrict__ gamma,
     const float* __restrict__ beta,
     float* __restrict__ outp)
{
    const int row = blockIdx.x;
    const int tid = threadIdx.x;
    const int lane = tid & 31, wid = tid >> 5;
    const float* r1 = (PHASE == 0) ? a : g_x1;

    __shared__ float red1[8];
    __shared__ float red2[8];

    float4 av = ((const float4*)(r1 + (size_t)row * DMOD))[tid];
    float4 tv = ((const float4*)(g_t1 + (size_t)row * DMOD))[tid];
    float v[4] = {av.x + tv.x, av.y + tv.y, av.z + tv.z, av.w + tv.w};

    float s = v[0] + v[1] + v[2] + v[3];
#pragma unroll
    for (int o = 16; o > 0; o >>= 1) s += __shfl_xor_sync(0xFFFFFFFFu, s, o);
    if (lane == 0) red1[wid] = s;
    __syncthreads();
    float tot = red1[0];
#pragma unroll
    for (int i = 1; i < 8; i++) tot += red1[i];
    const float mu = tot * (1.0f / DMOD);

    float vs = 0.f;
#pragma unroll
    for (int i = 0; i < 4; i++) { float d = v[i] - mu; vs += d * d; }
#pragma unroll
    for (int o = 16; o > 0; o >>= 1) vs += __shfl_xor_sync(0xFFFFFFFFu, vs, o);
    if (lane == 0) red2[wid] = vs;
    __syncthreads();
    float vtot = red2[0];
#pragma unroll
    for (int i = 1; i < 8; i++) vtot += red2[i];
    const float rs = rsqrtf(vtot * (1.0f / DMOD) + 1e-5f);

    float4 g4 = ((const float4*)gamma)[tid];
    float4 b4 = ((const float4*)beta)[tid];
    float4 o4;
    o4.x = (v[0] - mu) * rs * g4.x + b4.x;
    o4.y = (v[1] - mu) * rs * g4.y + b4.y;
    o4.z = (v[2] - mu) * rs * g4.z + b4.z;
    o4.w = (v[3] - mu) * rs * g4.w + b4.w;

    if constexpr (PHASE == 0) {
        ((float4*)(g_x1 + (size_t)row * DMOD))[tid] = o4;
        uint2 p;
        p.x = bfpack(o4.x, o4.y);
        p.y = bfpack(o4.z, o4.w);
        ((uint2*)(g_x1b + (size_t)row * DMOD))[tid] = p;
    } else {
        ((float4*)(outp + (size_t)row * DMOD))[tid] = o4;
    }
}

// ---------------------------------------------------------------------------
extern "C" void kernel_launch(void* const* d_in, const int* in_sizes, int n_in,
                              void* d_out, int out_size)
{
    (void)in_sizes; (void)n_in; (void)out_size;
    const float* x      = (const float*)d_in[0];
    const void*  mask   = d_in[1];
    const float* wqkv_c = (const float*)d_in[2];
    const float* wqkv_p = (const float*)d_in[3];
    const float* wo_c   = (const float*)d_in[4];
    const float* wo_p   = (const float*)d_in[5];
    const float* w1_c   = (const float*)d_in[6];
    const float* b1_c   = (const float*)d_in[7];
    const float* w1_p   = (const float*)d_in[8];
    const float* b1_p   = (const float*)d_in[9];
    const float* w2_c   = (const float*)d_in[10];
    const float* b2_c   = (const float*)d_in[11];
    const float* w2_p   = (const float*)d_in[12];
    const float* b2_p   = (const float*)d_in[13];
    const float* ln1_g  = (const float*)d_in[14];
    const float* ln1_b  = (const float*)d_in[15];
    const float* ln2_g  = (const float*)d_in[16];
    const float* ln2_b  = (const float*)d_in[17];
    float* out = (float*)d_out;

    const int flash_smem = FLASH_SMEM_WORDS * 4;
    cudaFuncSetAttribute(flash_k, cudaFuncAttributeMaxDynamicSharedMemorySize, flash_smem);

    mask_probe_k<<<1, 1024>>>(mask);

    float* xr;  cudaGetSymbolAddress((void**)&xr,  g_xr);
    float* wqc; cudaGetSymbolAddress((void**)&wqc, g_wqc);
    float* wqp; cudaGetSymbolAddress((void**)&wqp, g_wqp);
    float* woc; cudaGetSymbolAddress((void**)&woc, g_woc);
    float* wop; cudaGetSymbolAddress((void**)&wop, g_wop);
    void* w1cb; cudaGetSymbolAddress(&w1cb, g_w1cb);
    void* w1pb; cudaGetSymbolAddress(&w1pb, g_w1pb);
    void* w2cb; cudaGetSymbolAddress(&w2cb, g_w2cb);
    void* w2pb; cudaGetSymbolAddress(&w2pb, g_w2pb);

    auto cvt = [&](const float* s, float* d, int n) {
        int n4 = n >> 2;
        cvt_k<<<(n4 + 255) / 256, 256>>>((const float4*)s, (float4*)d, n4);
    };
    auto cvtb = [&](const float* s, void* d, int n) {
        int n4 = n >> 2;
        cvtb_k<<<(n4 + 255) / 256, 256>>>((const float4*)s, (uint2*)d, n4);
    };
    cvt(x, xr, BT*DMOD);
    cvt(wqkv_c, wqc, HH*DM2*192);
    cvt(wqkv_p, wqp, HH*DM2*192);
    cvt(wo_c, woc, HH*DQ2*DM2);
    cvt(wo_p, wop, HH*DQ2*DM2);
    cvtb(w1_c, w1cb, DF2*DM2);
    cvtb(w1_p, w1pb, DF2*DM2);
    cvtb(w2_c, w2cb, DM2*DF2);
    cvtb(w2_p, w2pb, DM2*DF2);

    // 1. QKV (tf32)
    gemm_tc<0><<<dim3(3, 32, 16), 256>>>();
    // 2-4. flash attention (tf32)
    flash_k<<<dim3(8, 32), 256, flash_smem>>>();
    // 5. OPROJ (tf32)
    gemm_tc<3><<<dim3(8, 32, 2), 256>>>();
    // 6. LN1 -> g_x1 (fp32) + g_x1b (bf16)
    ln_k<0><<<BT, 256>>>(x, ln1_g, ln1_b, nullptr);
    // 7. FFN1 (bf16)
    gemm_bf<4><<<dim3(32, 32, 2), 256>>>(b1_c, b1_p);
    // 8. FFN2 (bf16)
    gemm_bf<5><<<dim3(8, 32, 2), 256>>>(b2_c, b2_p);
    // 9. LN2 -> out
    ln_k<1><<<BT, 256>>>(nullptr, ln2_g, ln2_b, out);
}

// round 8
// speedup vs baseline: 1.7495x; 1.5110x over previous
#include <cuda_runtime.h>
#include <cuda_fp16.h>
#include <math.h>
#include <stdint.h>

// ---------------------------------------------------------------------------
// PartitionedTransformerEncoderLayer — Round 8: fp16 HMMA everywhere
// (m16n8k16.f16, fp32 accum). fp16 precision == tf32 (11 bits) at 2x rate.
// Flash attention fp16 tiles -> 89KB smem -> 2 CTAs/SM, single wave.
// ---------------------------------------------------------------------------

#define HH   8
#define TT   1024
#define BB   4
#define DMOD 1024
#define DM2  512
#define DQ   128
#define DQ2  64
#define DF2  2048
#define BT   4096

// fp16 scratch (unsigned short storage, cast at use)
__device__ unsigned short g_qh[BB*HH*TT*DQ];
__device__ unsigned short g_kh[BB*HH*TT*DQ];
__device__ unsigned short g_vh[BB*HH*TT*DQ];
__device__ unsigned short g_ob[(size_t)BT*DMOD];
__device__ unsigned short g_xh[(size_t)BT*DMOD];
__device__ unsigned short g_x1h[(size_t)BT*DMOD];
__device__ unsigned short g_hh[(size_t)BT*2*DF2];
__device__ unsigned short g_wqTc[HH*192*DM2];
__device__ unsigned short g_wqTp[HH*192*DM2];
__device__ unsigned short g_woTc[DM2*DM2];
__device__ unsigned short g_woTp[DM2*DM2];
__device__ unsigned short g_w1ch[DF2*DM2];
__device__ unsigned short g_w1ph[DF2*DM2];
__device__ unsigned short g_w2ch[DM2*DF2];
__device__ unsigned short g_w2ph[DM2*DF2];
// fp32 scratch
__device__ float g_t1[(size_t)BT*DMOD];
__device__ float g_x1[(size_t)BT*DMOD];
__device__ float g_maskf[BB*TT];

// ---------------------------------------------------------------------------
__device__ __forceinline__ void cp16(void* smem, const void* g) {
    unsigned s = (unsigned)__cvta_generic_to_shared(smem);
    asm volatile("cp.async.cg.shared.global [%0], [%1], 16;" :: "r"(s), "l"(g));
}
__device__ __forceinline__ void cp_commit() { asm volatile("cp.async.commit_group;"); }
__device__ __forceinline__ void cp_wait0()  { asm volatile("cp.async.wait_group 0;"); }

__device__ __forceinline__ void ldm_x4(unsigned &r0, unsigned &r1,
                                       unsigned &r2, unsigned &r3,
                                       const void* p) {
    unsigned addr = (unsigned)__cvta_generic_to_shared(p);
    asm volatile("ldmatrix.sync.aligned.m8n8.x4.shared.b16 {%0,%1,%2,%3}, [%4];"
                 : "=r"(r0), "=r"(r1), "=r"(r2), "=r"(r3) : "r"(addr));
}
__device__ __forceinline__ void mma_f16(float* c, const unsigned* a, const unsigned* b) {
    asm volatile("mma.sync.aligned.m16n8k16.row.col.f32.f16.f16.f32 "
                 "{%0,%1,%2,%3}, {%4,%5,%6,%7}, {%8,%9}, {%0,%1,%2,%3};"
                 : "+f"(c[0]), "+f"(c[1]), "+f"(c[2]), "+f"(c[3])
                 : "r"(a[0]), "r"(a[1]), "r"(a[2]), "r"(a[3]),
                   "r"(b[0]), "r"(b[1]));
}
__device__ __forceinline__ unsigned h2u(__half2 h) { return *(unsigned*)&h; }

// ---------------------------------------------------------------------------
// Mask canonicalization
// ---------------------------------------------------------------------------
__global__ void mask_probe_k(const void* __restrict__ maskraw) {
    const unsigned int* w = (const unsigned int*)maskraw;
    int tid = threadIdx.x;
    unsigned int v = w[tid];
    int oki = (v == 0u || v == 1u);
    int okf = (v == 0u || v == 0x3F800000u);
    int all_i = __syncthreads_and(oki);
    int all_f = __syncthreads_and(okf);
    if (all_i) {
        const int* wi = (const int*)maskraw;
        for (int i = tid; i < BB*TT; i += 1024) g_maskf[i] = wi[i] ? 1.f : 0.f;
    } else if (all_f) {
        const float* wf = (const float*)maskraw;
        for (int i = tid; i < BB*TT; i += 1024) g_maskf[i] = (wf[i] != 0.f) ? 1.f : 0.f;
    } else {
        const unsigned char* wb = (const unsigned char*)maskraw;
        for (int i = tid; i < BB*TT; i += 1024) g_maskf[i] = wb[i] ? 1.f : 0.f;
    }
}

// fp32 -> fp16 elementwise
__global__ void __launch_bounds__(256) cvth_k(const float4* __restrict__ src,
                                              uint2* __restrict__ dst, int n4) {
    int i = blockIdx.x * 256 + threadIdx.x;
    if (i < n4) {
        float4 v = src[i];
        uint2 p;
        p.x = h2u(__floats2half2_rn(v.x, v.y));
        p.y = h2u(__floats2half2_rn(v.z, v.w));
        dst[i] = p;
    }
}

// fp32 [K][N] (per slab) -> fp16 [N][K] transpose-convert
__global__ void __launch_bounds__(256) cvtT_k(const float* __restrict__ src,
                                              unsigned short* __restrict__ dst,
                                              int K, int N) {
    __shared__ float t[32][33];
    const size_t slab = (size_t)blockIdx.z * K * N;
    const int n0 = blockIdx.x * 32, k0 = blockIdx.y * 32;
    const int tx = threadIdx.x, ty = threadIdx.y;   // 32 x 8
#pragma unroll
    for (int j = 0; j < 4; j++)
        t[ty + 8*j][tx] = src[slab + (size_t)(k0 + ty + 8*j) * N + n0 + tx];
    __syncthreads();
#pragma unroll
    for (int j = 0; j < 4; j++) {
        __half h = __float2half_rn(t[tx][ty + 8*j]);
        dst[slab + (size_t)(n0 + ty + 8*j) * K + k0 + tx] = *(unsigned short*)&h;
    }
}

// ---------------------------------------------------------------------------
// fp16 HMMA GEMM: 128x64x32 tiles, m16n8k16, cp.async double-buffered.
// All B operands are k-contiguous fp16 [n][k].
//  0 QKV  : A=g_xh (half sel),  B=g_wqT{c,p}[h] -> g_qh/g_kh/g_vh (q scaled)
//  3 OPROJ: A=g_ob (gather),    B=g_woT{c,p}    -> g_t1 fp32
//  4 FFN1 : A=g_x1h (half),     B=g_w1{c,p}h +b relu -> g_hh
//  5 FFN2 : A=g_hh (half),      B=g_w2{c,p}h +b      -> g_t1 fp32
// ---------------------------------------------------------------------------
template<int MODE>
__global__ void __launch_bounds__(256)
gemm_h(const float* __restrict__ bias0,
       const float* __restrict__ bias1)
{
    constexpr int K = (MODE == 5) ? 2048 : 512;

    __shared__ unsigned short As[2][128][40];
    __shared__ unsigned short Bs[2][64][40];

    const int tid  = threadIdx.x;
    const int lane = tid & 31;
    const int warp = tid >> 5;
    const int wm = (warp & 3) * 32;
    const int wn = (warp >> 2) * 32;
    const int m0 = blockIdx.y * 128;
    const int n0 = blockIdx.x * 64;
    const int z  = blockIdx.z;

    const unsigned short* Ab;
    int astr;
    if constexpr (MODE == 0)      { Ab = g_xh  + (size_t)(z >> 3) * DM2; astr = DMOD;  }
    else if constexpr (MODE == 3) { Ab = g_ob;                            astr = DMOD;  }
    else if constexpr (MODE == 4) { Ab = g_x1h + (size_t)z * DM2;         astr = DMOD;  }
    else                          { Ab = g_hh  + (size_t)z * DF2;         astr = 2*DF2; }

    const unsigned short* Wb;
    int bstr;
    if constexpr (MODE == 0) { Wb = ((z >> 3) ? g_wqTp : g_wqTc) + (size_t)(z & 7) * (192*DM2); bstr = DM2; }
    else if constexpr (MODE == 3) { Wb = z ? g_woTp : g_woTc; bstr = DM2;  }
    else if constexpr (MODE == 4) { Wb = z ? g_w1ph : g_w1ch; bstr = DM2;  }
    else                          { Wb = z ? g_w2ph : g_w2ch; bstr = DF2;  }

    float c[2][4][4];
#pragma unroll
    for (int mt = 0; mt < 2; mt++)
#pragma unroll
        for (int nt = 0; nt < 4; nt++)
#pragma unroll
            for (int r = 0; r < 4; r++) c[mt][nt][r] = 0.f;

    const int ld_r  = tid >> 2;          // 0..63
    const int ld_c8 = (tid & 3) << 3;    // 0,8,16,24 halves

    auto a_idx = [&](int m, int k) -> size_t {
        if constexpr (MODE == 3)
            return (size_t)m * DMOD + (size_t)((k >> 6) << 7) + (size_t)z * DQ2 + (k & 63);
        else
            return (size_t)m * astr + k;
    };

    auto loadA = [&](int k0, int buf) {
#pragma unroll
        for (int it = 0; it < 2; it++) {
            int m = m0 + ld_r + it * 64;
            cp16(&As[buf][ld_r + it * 64][ld_c8], Ab + a_idx(m, k0 + ld_c8));
        }
    };
    auto loadB = [&](int k0, int buf) {
        int n = n0 + ld_r;
        cp16(&Bs[buf][ld_r][ld_c8], Wb + (size_t)n * bstr + k0 + ld_c8);
    };

    loadA(0, 0);
    loadB(0, 0);
    cp_commit();
    cp_wait0();
    __syncthreads();

    const int l16 = lane & 15;
    const int kh  = (lane >> 4) * 8;

    int cur = 0;
    for (int k0 = 0; k0 < K; k0 += 32) {
        const int nxt = cur ^ 1;
        const bool has_next = (k0 + 32 < K);
        if (has_next) {
            loadA(k0 + 32, nxt);
            loadB(k0 + 32, nxt);
            cp_commit();
        }
#pragma unroll
        for (int ks = 0; ks < 2; ks++) {
            const int kofs = ks * 16 + kh;
            unsigned a[2][4];
#pragma unroll
            for (int mt = 0; mt < 2; mt++)
                ldm_x4(a[mt][0], a[mt][1], a[mt][2], a[mt][3],
                       &As[cur][wm + mt*16 + l16][kofs]);
            unsigned b[4][2];
#pragma unroll
            for (int bt = 0; bt < 2; bt++) {
                unsigned r0, r1, r2, r3;
                ldm_x4(r0, r1, r2, r3, &Bs[cur][wn + bt*16 + l16][kofs]);
                b[bt*2 + 0][0] = r0; b[bt*2 + 0][1] = r2;
                b[bt*2 + 1][0] = r1; b[bt*2 + 1][1] = r3;
            }
#pragma unroll
            for (int mt = 0; mt < 2; mt++)
#pragma unroll
                for (int nt = 0; nt < 4; nt++)
                    mma_f16(c[mt][nt], a[mt], b[nt]);
        }
        if (has_next) cp_wait0();
        __syncthreads();
        cur = nxt;
    }

    // ---- epilogue ----
    const int g   = lane >> 2;
    const int tig = lane & 3;

#pragma unroll
    for (int mt = 0; mt < 2; mt++) {
#pragma unroll
        for (int nt = 0; nt < 4; nt++) {
            const int mr = m0 + wm + mt*16 + g;
            const int nl = wn + nt*8 + 2*tig;

            if constexpr (MODE == 0) {
                const int cc = blockIdx.x;           // 0=q 1=k 2=v
                const int hh = z & 7, sel = z >> 3;
                const float scale = (cc == 0) ? 0.08838834764831845f : 1.0f;
                unsigned short* dst = (cc == 0) ? g_qh : ((cc == 1) ? g_kh : g_vh);
                unsigned lo = h2u(__floats2half2_rn(c[mt][nt][0]*scale, c[mt][nt][1]*scale));
                unsigned hi = h2u(__floats2half2_rn(c[mt][nt][2]*scale, c[mt][nt][3]*scale));
                {
                    int b_ = mr >> 10, t_ = mr & 1023;
                    size_t base = (((size_t)(b_*HH + hh))*TT + t_) * DQ + sel*DQ2;
                    *(unsigned*)(dst + base + nl) = lo;
                }
                {
                    int m2 = mr + 8;
                    int b_ = m2 >> 10, t_ = m2 & 1023;
                    size_t base = (((size_t)(b_*HH + hh))*TT + t_) * DQ + sel*DQ2;
                    *(unsigned*)(dst + base + nl) = hi;
                }
            } else if constexpr (MODE == 3) {
                size_t r0 = (size_t)mr * DMOD + (size_t)z * DM2 + n0 + nl;
                *(float2*)(g_t1 + r0) = make_float2(c[mt][nt][0], c[mt][nt][1]);
                *(float2*)(g_t1 + r0 + 8*DMOD) = make_float2(c[mt][nt][2], c[mt][nt][3]);
            } else if constexpr (MODE == 4) {
                const float* bs = z ? bias1 : bias0;
                float b0 = bs[n0 + nl], b1 = bs[n0 + nl + 1];
                size_t e0 = (size_t)mr * (2*DF2) + (size_t)z * DF2 + n0 + nl;
                unsigned lo = h2u(__floats2half2_rn(fmaxf(c[mt][nt][0]+b0, 0.f),
                                                    fmaxf(c[mt][nt][1]+b1, 0.f)));
                unsigned hi = h2u(__floats2half2_rn(fmaxf(c[mt][nt][2]+b0, 0.f),
                                                    fmaxf(c[mt][nt][3]+b1, 0.f)));
                *(unsigned*)(g_hh + e0) = lo;
                *(unsigned*)(g_hh + e0 + (size_t)8 * (2*DF2)) = hi;
            } else {
                const float* bs = z ? bias1 : bias0;
                float b0 = bs[n0 + nl], b1 = bs[n0 + nl + 1];
                size_t r0 = (size_t)mr * DMOD + (size_t)z * DM2 + n0 + nl;
                *(float2*)(g_t1 + r0) = make_float2(c[mt][nt][0]+b0, c[mt][nt][1]+b1);
                *(float2*)(g_t1 + r0 + 8*DMOD) = make_float2(c[mt][nt][2]+b0, c[mt][nt][3]+b1);
            }
        }
    }
}

// ---------------------------------------------------------------------------
// Flash attention fp16: Q tile 128 x d128, 16 KV tiles of 64.
// Smem (halves): Qs[128][136] | Ks[64][136] | Vt[128][72] | Ps[128][72]
// then floats: RMX[128][2] | RSM[128][2].  Total 91136 B -> 2 CTAs/SM.
// ---------------------------------------------------------------------------
#define QS_H  0
#define KS_H  17408
#define VT_H  26112
#define PS_H  35328
#define RMX_F 22272
#define RSM_F 22528
#define FLASH_SMEM_BYTES 91136

__global__ void __launch_bounds__(256, 2)
flash_k()
{
    extern __shared__ __align__(16) char smraw[];
    unsigned short* smh = (unsigned short*)smraw;
    float* smf = (float*)smraw;

    const int tid  = threadIdx.x;
    const int lane = tid & 31;
    const int warp = tid >> 5;
    const int l16  = lane & 15;
    const int kh   = (lane >> 4) * 8;
    const int g    = lane >> 2;
    const int tig  = lane & 3;

    const int wm  = (warp & 3) * 32;
    const int wn  = (warp >> 2) * 32;
    const int wnd = (warp >> 2) * 64;

    const int m0 = blockIdx.x * 128;
    const int z  = blockIdx.y;
    const int b  = z >> 3;
    const int h  = z & 7;

    const unsigned short* Qg = g_qh + (size_t)z * (TT*DQ);
    const unsigned short* Kg = g_kh + (size_t)z * (TT*DQ);
    const unsigned short* Vg = g_vh + (size_t)z * (TT*DQ);

    // prologue: Q (128x128 halves, 2048 chunks) + K tile 0 (1024 chunks)
#pragma unroll
    for (int i = 0; i < 8; i++) {
        int ch = tid + i * 256;
        int r = ch >> 4, c8 = (ch & 15) * 8;
        cp16(&smh[QS_H + r * 136 + c8], Qg + (size_t)(m0 + r) * DQ + c8);
    }
#pragma unroll
    for (int i = 0; i < 4; i++) {
        int ch = tid + i * 256;
        int r = ch >> 4, c8 = (ch & 15) * 8;
        cp16(&smh[KS_H + r * 136 + c8], Kg + (size_t)r * DQ + c8);
    }
    cp_commit();

    float co[2][8][4];
#pragma unroll
    for (int mt = 0; mt < 2; mt++)
#pragma unroll
        for (int nt = 0; nt < 8; nt++)
#pragma unroll
            for (int r = 0; r < 4; r++) co[mt][nt][r] = 0.f;
    float mrun[4] = {-1e30f, -1e30f, -1e30f, -1e30f};
    float lrun[4] = {0.f, 0.f, 0.f, 0.f};

    for (int kt = 0; kt < 16; kt++) {
        cp_wait0();
        __syncthreads();

        // ---- S = Q K^T (8 k16 steps) ----
        float cs[2][4][4];
#pragma unroll
        for (int mt = 0; mt < 2; mt++)
#pragma unroll
            for (int nt = 0; nt < 4; nt++)
#pragma unroll
                for (int r = 0; r < 4; r++) cs[mt][nt][r] = 0.f;
#pragma unroll
        for (int ks = 0; ks < 8; ks++) {
            const int kofs = ks * 16 + kh;
            unsigned a[2][4];
#pragma unroll
            for (int mt = 0; mt < 2; mt++)
                ldm_x4(a[mt][0], a[mt][1], a[mt][2], a[mt][3],
                       &smh[QS_H + (wm + mt*16 + l16) * 136 + kofs]);
#pragma unroll
            for (int bt = 0; bt < 2; bt++) {
                unsigned r0, r1, r2, r3;
                ldm_x4(r0, r1, r2, r3,
                       &smh[KS_H + (wn + bt*16 + l16) * 136 + kofs]);
                unsigned bf0[2] = {r0, r2};
                unsigned bf1[2] = {r1, r3};
#pragma unroll
                for (int mt = 0; mt < 2; mt++) {
                    mma_f16(cs[mt][bt*2 + 0], a[mt], bf0);
                    mma_f16(cs[mt][bt*2 + 1], a[mt], bf1);
                }
            }
        }

        // ---- V tile transpose into Vt[d][t] (half2 pairs) ----
#pragma unroll
        for (int i = 0; i < 2; i++) {
            int lin = tid + i * 256;            // 0..511
            int tp = lin & 31, d8 = (lin >> 5) * 8;
            const unsigned short* vp = Vg + (size_t)(kt*64 + 2*tp) * DQ + d8;
            float4 va = *(const float4*)vp;
            float4 vb = *(const float4*)(vp + DQ);
            const __half* ha = (const __half*)&va;
            const __half* hb = (const __half*)&vb;
#pragma unroll
            for (int j = 0; j < 8; j++) {
                __half2 pr = __halves2half2(ha[j], hb[j]);
                *(__half2*)&smh[VT_H + (d8 + j) * 72 + 2*tp] = pr;
            }
        }

        // ---- mask + row max ----
        float rmax[4] = {-1e30f, -1e30f, -1e30f, -1e30f};
#pragma unroll
        for (int mt = 0; mt < 2; mt++) {
#pragma unroll
            for (int nt = 0; nt < 4; nt++) {
                int col = kt*64 + wn + nt*8 + 2*tig;
                float2 mk = *(const float2*)&g_maskf[b*TT + col];
                if (mk.x == 0.f) { cs[mt][nt][0] = -1e30f; cs[mt][nt][2] = -1e30f; }
                if (mk.y == 0.f) { cs[mt][nt][1] = -1e30f; cs[mt][nt][3] = -1e30f; }
                rmax[mt*2+0] = fmaxf(rmax[mt*2+0], fmaxf(cs[mt][nt][0], cs[mt][nt][1]));
                rmax[mt*2+1] = fmaxf(rmax[mt*2+1], fmaxf(cs[mt][nt][2], cs[mt][nt][3]));
            }
        }
#pragma unroll
        for (int i = 0; i < 4; i++) {
            rmax[i] = fmaxf(rmax[i], __shfl_xor_sync(0xFFFFFFFFu, rmax[i], 1));
            rmax[i] = fmaxf(rmax[i], __shfl_xor_sync(0xFFFFFFFFu, rmax[i], 2));
        }
        if (tig == 0) {
#pragma unroll
            for (int i = 0; i < 4; i++) {
                int row = wm + (i >> 1)*16 + g + (i & 1)*8;
                smf[RMX_F + row*2 + (wn >> 5)] = rmax[i];
            }
        }
        __syncthreads();

        // prefetch next K tile (all Ks ldmatrix reads done above)
        if (kt + 1 < 16) {
#pragma unroll
            for (int i = 0; i < 4; i++) {
                int ch = tid + i * 256;
                int r = ch >> 4, c8 = (ch & 15) * 8;
                cp16(&smh[KS_H + r * 136 + c8], Kg + (size_t)((kt+1)*64 + r) * DQ + c8);
            }
        }
        cp_commit();

        // ---- p = exp(s - m), store P (fp16), row sums ----
        float newm[4], rsum[4] = {0.f, 0.f, 0.f, 0.f};
#pragma unroll
        for (int i = 0; i < 4; i++) {
            int row = wm + (i >> 1)*16 + g + (i & 1)*8;
            float cm = fmaxf(smf[RMX_F + row*2], smf[RMX_F + row*2 + 1]);
            newm[i] = fmaxf(mrun[i], cm);
        }
#pragma unroll
        for (int mt = 0; mt < 2; mt++) {
#pragma unroll
            for (int nt = 0; nt < 4; nt++) {
                int colL = wn + nt*8 + 2*tig;
                float p0 = (cs[mt][nt][0] <= -1e29f) ? 0.f : __expf(cs[mt][nt][0] - newm[mt*2+0]);
                float p1 = (cs[mt][nt][1] <= -1e29f) ? 0.f : __expf(cs[mt][nt][1] - newm[mt*2+0]);
                float p2 = (cs[mt][nt][2] <= -1e29f) ? 0.f : __expf(cs[mt][nt][2] - newm[mt*2+1]);
                float p3 = (cs[mt][nt][3] <= -1e29f) ? 0.f : __expf(cs[mt][nt][3] - newm[mt*2+1]);
                rsum[mt*2+0] += p0 + p1;
                rsum[mt*2+1] += p2 + p3;
                int rA = wm + mt*16 + g;
                *(__half2*)&smh[PS_H + rA*72 + colL]     = __floats2half2_rn(p0, p1);
                *(__half2*)&smh[PS_H + (rA+8)*72 + colL] = __floats2half2_rn(p2, p3);
            }
        }
#pragma unroll
        for (int i = 0; i < 4; i++) {
            rsum[i] += __shfl_xor_sync(0xFFFFFFFFu, rsum[i], 1);
            rsum[i] += __shfl_xor_sync(0xFFFFFFFFu, rsum[i], 2);
        }
        if (tig == 0) {
#pragma unroll
            for (int i = 0; i < 4; i++) {
                int row = wm + (i >> 1)*16 + g + (i & 1)*8;
                smf[RSM_F + row*2 + (wn >> 5)] = rsum[i];
            }
        }
        __syncthreads();

        // ---- rescale O, update running stats ----
        float alpha[4];
#pragma unroll
        for (int i = 0; i < 4; i++) {
            int row = wm + (i >> 1)*16 + g + (i & 1)*8;
            float s = smf[RSM_F + row*2] + smf[RSM_F + row*2 + 1];
            alpha[i] = __expf(mrun[i] - newm[i]);
            lrun[i] = lrun[i] * alpha[i] + s;
            mrun[i] = newm[i];
        }
#pragma unroll
        for (int mt = 0; mt < 2; mt++)
#pragma unroll
            for (int nt = 0; nt < 8; nt++) {
                co[mt][nt][0] *= alpha[mt*2+0];
                co[mt][nt][1] *= alpha[mt*2+0];
                co[mt][nt][2] *= alpha[mt*2+1];
                co[mt][nt][3] *= alpha[mt*2+1];
            }

        // ---- O += P V (4 k16 steps, n = d = 128) ----
#pragma unroll
        for (int ks = 0; ks < 4; ks++) {
            const int kofs = ks * 16 + kh;
            unsigned a[2][4];
#pragma unroll
            for (int mt = 0; mt < 2; mt++)
                ldm_x4(a[mt][0], a[mt][1], a[mt][2], a[mt][3],
                       &smh[PS_H + (wm + mt*16 + l16) * 72 + kofs]);
#pragma unroll
            for (int bt = 0; bt < 4; bt++) {
                unsigned r0, r1, r2, r3;
                ldm_x4(r0, r1, r2, r3,
                       &smh[VT_H + (wnd + bt*16 + l16) * 72 + kofs]);
                unsigned bf0[2] = {r0, r2};
                unsigned bf1[2] = {r1, r3};
#pragma unroll
                for (int mt = 0; mt < 2; mt++) {
                    mma_f16(co[mt][bt*2 + 0], a[mt], bf0);
                    mma_f16(co[mt][bt*2 + 1], a[mt], bf1);
                }
            }
        }
    }

    // ---- epilogue: O /= l, store fp16 to g_ob [B,T,H*128] ----
    float invl[4];
#pragma unroll
    for (int i = 0; i < 4; i++) invl[i] = 1.0f / lrun[i];
#pragma unroll
    for (int mt = 0; mt < 2; mt++) {
#pragma unroll
        for (int nt = 0; nt < 8; nt++) {
            int rowA = m0 + wm + mt*16 + g;
            int col  = wnd + nt*8 + 2*tig;
            unsigned lo = h2u(__floats2half2_rn(co[mt][nt][0]*invl[mt*2+0],
                                                co[mt][nt][1]*invl[mt*2+0]));
            unsigned hi = h2u(__floats2half2_rn(co[mt][nt][2]*invl[mt*2+1],
                                                co[mt][nt][3]*invl[mt*2+1]));
            *(unsigned*)(g_ob + ((size_t)(b*TT + rowA)) * DMOD + h*DQ + col) = lo;
            *(unsigned*)(g_ob + ((size_t)(b*TT + rowA + 8)) * DMOD + h*DQ + col) = hi;
        }
    }
}

// ---------------------------------------------------------------------------
// Fused residual + LayerNorm
// PHASE 0: g_x1 = LN(x + g_t1) fp32, plus g_x1h fp16 copy
// PHASE 1: out  = LN(g_x1 + g_t1)
// ---------------------------------------------------------------------------
template<int PHASE>
__global__ void __launch_bounds__(256)
ln_k(const float* __restrict__ a,
     const float* __restrict__ gamma,
     const float* __restrict__ beta,
     float* __restrict__ outp)
{
    const int row = blockIdx.x;
    const int tid = threadIdx.x;
    const int lane = tid & 31, wid = tid >> 5;
    const float* r1 = (PHASE == 0) ? a : g_x1;

    __shared__ float red1[8];
    __shared__ float red2[8];

    float4 av = ((const float4*)(r1 + (size_t)row * DMOD))[tid];
    float4 tv = ((const float4*)(g_t1 + (size_t)row * DMOD))[tid];
    float v[4] = {av.x + tv.x, av.y + tv.y, av.z + tv.z, av.w + tv.w};

    float s = v[0] + v[1] + v[2] + v[3];
#pragma unroll
    for (int o = 16; o > 0; o >>= 1) s += __shfl_xor_sync(0xFFFFFFFFu, s, o);
    if (lane == 0) red1[wid] = s;
    __syncthreads();
    float tot = red1[0];
#pragma unroll
    for (int i = 1; i < 8; i++) tot += red1[i];
    const float mu = tot * (1.0f / DMOD);

    float vs = 0.f;
#pragma unroll
    for (int i = 0; i < 4; i++) { float d = v[i] - mu; vs += d * d; }
#pragma unroll
    for (int o = 16; o > 0; o >>= 1) vs += __shfl_xor_sync(0xFFFFFFFFu, vs, o);
    if (lane == 0) red2[wid] = vs;
    __syncthreads();
    float vtot = red2[0];
#pragma unroll
    for (int i = 1; i < 8; i++) vtot += red2[i];
    const float rs = rsqrtf(vtot * (1.0f / DMOD) + 1e-5f);

    float4 g4 = ((const float4*)gamma)[tid];
    float4 b4 = ((const float4*)beta)[tid];
    float4 o4;
    o4.x = (v[0] - mu) * rs * g4.x + b4.x;
    o4.y = (v[1] - mu) * rs * g4.y + b4.y;
    o4.z = (v[2] - mu) * rs * g4.z + b4.z;
    o4.w = (v[3] - mu) * rs * g4.w + b4.w;

    if constexpr (PHASE == 0) {
        ((float4*)(g_x1 + (size_t)row * DMOD))[tid] = o4;
        uint2 p;
        p.x = h2u(__floats2half2_rn(o4.x, o4.y));
        p.y = h2u(__floats2half2_rn(o4.z, o4.w));
        ((uint2*)(g_x1h + (size_t)row * DMOD))[tid] = p;
    } else {
        ((float4*)(outp + (size_t)row * DMOD))[tid] = o4;
    }
}

// ---------------------------------------------------------------------------
extern "C" void kernel_launch(void* const* d_in, const int* in_sizes, int n_in,
                              void* d_out, int out_size)
{
    (void)in_sizes; (void)n_in; (void)out_size;
    const float* x      = (const float*)d_in[0];
    const void*  mask   = d_in[1];
    const float* wqkv_c = (const float*)d_in[2];
    const float* wqkv_p = (const float*)d_in[3];
    const float* wo_c   = (const float*)d_in[4];
    const float* wo_p   = (const float*)d_in[5];
    const float* w1_c   = (const float*)d_in[6];
    const float* b1_c   = (const float*)d_in[7];
    const float* w1_p   = (const float*)d_in[8];
    const float* b1_p   = (const float*)d_in[9];
    const float* w2_c   = (const float*)d_in[10];
    const float* b2_c   = (const float*)d_in[11];
    const float* w2_p   = (const float*)d_in[12];
    const float* b2_p   = (const float*)d_in[13];
    const float* ln1_g  = (const float*)d_in[14];
    const float* ln1_b  = (const float*)d_in[15];
    const float* ln2_g  = (const float*)d_in[16];
    const float* ln2_b  = (const float*)d_in[17];
    float* out = (float*)d_out;

    cudaFuncSetAttribute(flash_k, cudaFuncAttributeMaxDynamicSharedMemorySize,
                         FLASH_SMEM_BYTES);

    mask_probe_k<<<1, 1024>>>(mask);

    void* xh;   cudaGetSymbolAddress(&xh,   g_xh);
    void* wqTc; cudaGetSymbolAddress(&wqTc, g_wqTc);
    void* wqTp; cudaGetSymbolAddress(&wqTp, g_wqTp);
    void* woTc; cudaGetSymbolAddress(&woTc, g_woTc);
    void* woTp; cudaGetSymbolAddress(&woTp, g_woTp);
    void* w1ch; cudaGetSymbolAddress(&w1ch, g_w1ch);
    void* w1ph; cudaGetSymbolAddress(&w1ph, g_w1ph);
    void* w2ch; cudaGetSymbolAddress(&w2ch, g_w2ch);
    void* w2ph; cudaGetSymbolAddress(&w2ph, g_w2ph);

    auto cvth = [&](const float* s, void* d, int n) {
        int n4 = n >> 2;
        cvth_k<<<(n4 + 255) / 256, 256>>>((const float4*)s, (uint2*)d, n4);
    };
    cvth(x, xh, BT*DMOD);
    cvth(w1_c, w1ch, DF2*DM2);
    cvth(w1_p, w1ph, DF2*DM2);
    cvth(w2_c, w2ch, DM2*DF2);
    cvth(w2_p, w2ph, DM2*DF2);

    // transpose-convert: wqkv [8 slabs][512][192] -> [192][512]; wo [512][512]
    cvtT_k<<<dim3(6, 16, 8), dim3(32, 8)>>>(wqkv_c, (unsigned short*)wqTc, DM2, 192);
    cvtT_k<<<dim3(6, 16, 8), dim3(32, 8)>>>(wqkv_p, (unsigned short*)wqTp, DM2, 192);
    cvtT_k<<<dim3(16, 16, 1), dim3(32, 8)>>>(wo_c, (unsigned short*)woTc, DM2, DM2);
    cvtT_k<<<dim3(16, 16, 1), dim3(32, 8)>>>(wo_p, (unsigned short*)woTp, DM2, DM2);

    // 1. QKV (fp16)
    gemm_h<0><<<dim3(3, 32, 16), 256>>>(nullptr, nullptr);
    // 2-4. flash attention (fp16)
    flash_k<<<dim3(8, 32), 256, FLASH_SMEM_BYTES>>>();
    // 5. OPROJ (fp16)
    gemm_h<3><<<dim3(8, 32, 2), 256>>>(nullptr, nullptr);
    // 6. LN1 -> g_x1 fp32 + g_x1h fp16
    ln_k<0><<<BT, 256>>>(x, ln1_g, ln1_b, nullptr);
    // 7. FFN1 (fp16)
    gemm_h<4><<<dim3(32, 32, 2), 256>>>(b1_c, b1_p);
    // 8. FFN2 (fp16)
    gemm_h<5><<<dim3(8, 32, 2), 256>>>(b2_c, b2_p);
    // 9. LN2 -> out
    ln_k<1><<<BT, 256>>>(nullptr, ln2_g, ln2_b, out);
}

// round 9
// speedup vs baseline: 1.7755x; 1.0148x over previous
#include <cuda_runtime.h>
#include <cuda_fp16.h>
#include <math.h>
#include <stdint.h>

// ---------------------------------------------------------------------------
// PartitionedTransformerEncoderLayer — Round 9: fp16 HMMA everywhere +
// FA2-style flash attention (register-resident P, 2 barriers/iter)
// ---------------------------------------------------------------------------

#define HH   8
#define TT   1024
#define BB   4
#define DMOD 1024
#define DM2  512
#define DQ   128
#define DQ2  64
#define DF2  2048
#define BT   4096

// fp16 scratch
__device__ unsigned short g_qh[BB*HH*TT*DQ];
__device__ unsigned short g_kh[BB*HH*TT*DQ];
__device__ unsigned short g_vh[BB*HH*TT*DQ];
__device__ unsigned short g_ob[(size_t)BT*DMOD];
__device__ unsigned short g_xh[(size_t)BT*DMOD];
__device__ unsigned short g_x1h[(size_t)BT*DMOD];
__device__ unsigned short g_hh[(size_t)BT*2*DF2];
__device__ unsigned short g_wqTc[HH*192*DM2];
__device__ unsigned short g_wqTp[HH*192*DM2];
__device__ unsigned short g_woTc[DM2*DM2];
__device__ unsigned short g_woTp[DM2*DM2];
__device__ unsigned short g_w1ch[DF2*DM2];
__device__ unsigned short g_w1ph[DF2*DM2];
__device__ unsigned short g_w2ch[DM2*DF2];
__device__ unsigned short g_w2ph[DM2*DF2];
// fp32 scratch
__device__ float g_t1[(size_t)BT*DMOD];
__device__ float g_x1[(size_t)BT*DMOD];
__device__ float g_maskf[BB*TT];

// ---------------------------------------------------------------------------
__device__ __forceinline__ void cp16(void* smem, const void* g) {
    unsigned s = (unsigned)__cvta_generic_to_shared(smem);
    asm volatile("cp.async.cg.shared.global [%0], [%1], 16;" :: "r"(s), "l"(g));
}
__device__ __forceinline__ void cp_commit() { asm volatile("cp.async.commit_group;"); }
__device__ __forceinline__ void cp_wait0()  { asm volatile("cp.async.wait_group 0;"); }

__device__ __forceinline__ void ldm_x4(unsigned &r0, unsigned &r1,
                                       unsigned &r2, unsigned &r3,
                                       const void* p) {
    unsigned addr = (unsigned)__cvta_generic_to_shared(p);
    asm volatile("ldmatrix.sync.aligned.m8n8.x4.shared.b16 {%0,%1,%2,%3}, [%4];"
                 : "=r"(r0), "=r"(r1), "=r"(r2), "=r"(r3) : "r"(addr));
}
__device__ __forceinline__ void mma_f16(float* c, const unsigned* a, const unsigned* b) {
    asm volatile("mma.sync.aligned.m16n8k16.row.col.f32.f16.f16.f32 "
                 "{%0,%1,%2,%3}, {%4,%5,%6,%7}, {%8,%9}, {%0,%1,%2,%3};"
                 : "+f"(c[0]), "+f"(c[1]), "+f"(c[2]), "+f"(c[3])
                 : "r"(a[0]), "r"(a[1]), "r"(a[2]), "r"(a[3]),
                   "r"(b[0]), "r"(b[1]));
}
__device__ __forceinline__ unsigned h2u(__half2 h) { return *(unsigned*)&h; }

// ---------------------------------------------------------------------------
// Mask canonicalization
// ---------------------------------------------------------------------------
__global__ void mask_probe_k(const void* __restrict__ maskraw) {
    const unsigned int* w = (const unsigned int*)maskraw;
    int tid = threadIdx.x;
    unsigned int v = w[tid];
    int oki = (v == 0u || v == 1u);
    int okf = (v == 0u || v == 0x3F800000u);
    int all_i = __syncthreads_and(oki);
    int all_f = __syncthreads_and(okf);
    if (all_i) {
        const int* wi = (const int*)maskraw;
        for (int i = tid; i < BB*TT; i += 1024) g_maskf[i] = wi[i] ? 1.f : 0.f;
    } else if (all_f) {
        const float* wf = (const float*)maskraw;
        for (int i = tid; i < BB*TT; i += 1024) g_maskf[i] = (wf[i] != 0.f) ? 1.f : 0.f;
    } else {
        const unsigned char* wb = (const unsigned char*)maskraw;
        for (int i = tid; i < BB*TT; i += 1024) g_maskf[i] = wb[i] ? 1.f : 0.f;
    }
}

// fp32 -> fp16 elementwise
__global__ void __launch_bounds__(256) cvth_k(const float4* __restrict__ src,
                                              uint2* __restrict__ dst, int n4) {
    int i = blockIdx.x * 256 + threadIdx.x;
    if (i < n4) {
        float4 v = src[i];
        uint2 p;
        p.x = h2u(__floats2half2_rn(v.x, v.y));
        p.y = h2u(__floats2half2_rn(v.z, v.w));
        dst[i] = p;
    }
}

// fp32 [K][N] (per slab) -> fp16 [N][K] transpose-convert
__global__ void __launch_bounds__(256) cvtT_k(const float* __restrict__ src,
                                              unsigned short* __restrict__ dst,
                                              int K, int N) {
    __shared__ float t[32][33];
    const size_t slab = (size_t)blockIdx.z * K * N;
    const int n0 = blockIdx.x * 32, k0 = blockIdx.y * 32;
    const int tx = threadIdx.x, ty = threadIdx.y;   // 32 x 8
#pragma unroll
    for (int j = 0; j < 4; j++)
        t[ty + 8*j][tx] = src[slab + (size_t)(k0 + ty + 8*j) * N + n0 + tx];
    __syncthreads();
#pragma unroll
    for (int j = 0; j < 4; j++) {
        __half h = __float2half_rn(t[tx][ty + 8*j]);
        dst[slab + (size_t)(n0 + ty + 8*j) * K + k0 + tx] = *(unsigned short*)&h;
    }
}

// ---------------------------------------------------------------------------
// fp16 HMMA GEMM (unchanged from round 8)
// ---------------------------------------------------------------------------
template<int MODE>
__global__ void __launch_bounds__(256)
gemm_h(const float* __restrict__ bias0,
       const float* __restrict__ bias1)
{
    constexpr int K = (MODE == 5) ? 2048 : 512;

    __shared__ unsigned short As[2][128][40];
    __shared__ unsigned short Bs[2][64][40];

    const int tid  = threadIdx.x;
    const int lane = tid & 31;
    const int warp = tid >> 5;
    const int wm = (warp & 3) * 32;
    const int wn = (warp >> 2) * 32;
    const int m0 = blockIdx.y * 128;
    const int n0 = blockIdx.x * 64;
    const int z  = blockIdx.z;

    const unsigned short* Ab;
    int astr;
    if constexpr (MODE == 0)      { Ab = g_xh  + (size_t)(z >> 3) * DM2; astr = DMOD;  }
    else if constexpr (MODE == 3) { Ab = g_ob;                            astr = DMOD;  }
    else if constexpr (MODE == 4) { Ab = g_x1h + (size_t)z * DM2;         astr = DMOD;  }
    else                          { Ab = g_hh  + (size_t)z * DF2;         astr = 2*DF2; }

    const unsigned short* Wb;
    int bstr;
    if constexpr (MODE == 0) { Wb = ((z >> 3) ? g_wqTp : g_wqTc) + (size_t)(z & 7) * (192*DM2); bstr = DM2; }
    else if constexpr (MODE == 3) { Wb = z ? g_woTp : g_woTc; bstr = DM2;  }
    else if constexpr (MODE == 4) { Wb = z ? g_w1ph : g_w1ch; bstr = DM2;  }
    else                          { Wb = z ? g_w2ph : g_w2ch; bstr = DF2;  }

    float c[2][4][4];
#pragma unroll
    for (int mt = 0; mt < 2; mt++)
#pragma unroll
        for (int nt = 0; nt < 4; nt++)
#pragma unroll
            for (int r = 0; r < 4; r++) c[mt][nt][r] = 0.f;

    const int ld_r  = tid >> 2;
    const int ld_c8 = (tid & 3) << 3;

    auto a_idx = [&](int m, int k) -> size_t {
        if constexpr (MODE == 3)
            return (size_t)m * DMOD + (size_t)((k >> 6) << 7) + (size_t)z * DQ2 + (k & 63);
        else
            return (size_t)m * astr + k;
    };

    auto loadA = [&](int k0, int buf) {
#pragma unroll
        for (int it = 0; it < 2; it++) {
            int m = m0 + ld_r + it * 64;
            cp16(&As[buf][ld_r + it * 64][ld_c8], Ab + a_idx(m, k0 + ld_c8));
        }
    };
    auto loadB = [&](int k0, int buf) {
        int n = n0 + ld_r;
        cp16(&Bs[buf][ld_r][ld_c8], Wb + (size_t)n * bstr + k0 + ld_c8);
    };

    loadA(0, 0);
    loadB(0, 0);
    cp_commit();
    cp_wait0();
    __syncthreads();

    const int l16 = lane & 15;
    const int kh  = (lane >> 4) * 8;

    int cur = 0;
    for (int k0 = 0; k0 < K; k0 += 32) {
        const int nxt = cur ^ 1;
        const bool has_next = (k0 + 32 < K);
        if (has_next) {
            loadA(k0 + 32, nxt);
            loadB(k0 + 32, nxt);
            cp_commit();
        }
#pragma unroll
        for (int ks = 0; ks < 2; ks++) {
            const int kofs = ks * 16 + kh;
            unsigned a[2][4];
#pragma unroll
            for (int mt = 0; mt < 2; mt++)
                ldm_x4(a[mt][0], a[mt][1], a[mt][2], a[mt][3],
                       &As[cur][wm + mt*16 + l16][kofs]);
            unsigned b[4][2];
#pragma unroll
            for (int bt = 0; bt < 2; bt++) {
                unsigned r0, r1, r2, r3;
                ldm_x4(r0, r1, r2, r3, &Bs[cur][wn + bt*16 + l16][kofs]);
                b[bt*2 + 0][0] = r0; b[bt*2 + 0][1] = r2;
                b[bt*2 + 1][0] = r1; b[bt*2 + 1][1] = r3;
            }
#pragma unroll
            for (int mt = 0; mt < 2; mt++)
#pragma unroll
                for (int nt = 0; nt < 4; nt++)
                    mma_f16(c[mt][nt], a[mt], b[nt]);
        }
        if (has_next) cp_wait0();
        __syncthreads();
        cur = nxt;
    }

    // ---- epilogue ----
    const int g   = lane >> 2;
    const int tig = lane & 3;

#pragma unroll
    for (int mt = 0; mt < 2; mt++) {
#pragma unroll
        for (int nt = 0; nt < 4; nt++) {
            const int mr = m0 + wm + mt*16 + g;
            const int nl = wn + nt*8 + 2*tig;

            if constexpr (MODE == 0) {
                const int cc = blockIdx.x;
                const int hh = z & 7, sel = z >> 3;
                const float scale = (cc == 0) ? 0.08838834764831845f : 1.0f;
                unsigned short* dst = (cc == 0) ? g_qh : ((cc == 1) ? g_kh : g_vh);
                unsigned lo = h2u(__floats2half2_rn(c[mt][nt][0]*scale, c[mt][nt][1]*scale));
                unsigned hi = h2u(__floats2half2_rn(c[mt][nt][2]*scale, c[mt][nt][3]*scale));
                {
                    int b_ = mr >> 10, t_ = mr & 1023;
                    size_t base = (((size_t)(b_*HH + hh))*TT + t_) * DQ + sel*DQ2;
                    *(unsigned*)(dst + base + nl) = lo;
                }
                {
                    int m2 = mr + 8;
                    int b_ = m2 >> 10, t_ = m2 & 1023;
                    size_t base = (((size_t)(b_*HH + hh))*TT + t_) * DQ + sel*DQ2;
                    *(unsigned*)(dst + base + nl) = hi;
                }
            } else if constexpr (MODE == 3) {
                size_t r0 = (size_t)mr * DMOD + (size_t)z * DM2 + n0 + nl;
                *(float2*)(g_t1 + r0) = make_float2(c[mt][nt][0], c[mt][nt][1]);
                *(float2*)(g_t1 + r0 + 8*DMOD) = make_float2(c[mt][nt][2], c[mt][nt][3]);
            } else if constexpr (MODE == 4) {
                const float* bs = z ? bias1 : bias0;
                float b0 = bs[n0 + nl], b1 = bs[n0 + nl + 1];
                size_t e0 = (size_t)mr * (2*DF2) + (size_t)z * DF2 + n0 + nl;
                unsigned lo = h2u(__floats2half2_rn(fmaxf(c[mt][nt][0]+b0, 0.f),
                                                    fmaxf(c[mt][nt][1]+b1, 0.f)));
                unsigned hi = h2u(__floats2half2_rn(fmaxf(c[mt][nt][2]+b0, 0.f),
                                                    fmaxf(c[mt][nt][3]+b1, 0.f)));
                *(unsigned*)(g_hh + e0) = lo;
                *(unsigned*)(g_hh + e0 + (size_t)8 * (2*DF2)) = hi;
            } else {
                const float* bs = z ? bias1 : bias0;
                float b0 = bs[n0 + nl], b1 = bs[n0 + nl + 1];
                size_t r0 = (size_t)mr * DMOD + (size_t)z * DM2 + n0 + nl;
                *(float2*)(g_t1 + r0) = make_float2(c[mt][nt][0]+b0, c[mt][nt][1]+b1);
                *(float2*)(g_t1 + r0 + 8*DMOD) = make_float2(c[mt][nt][2]+b0, c[mt][nt][3]+b1);
            }
        }
    }
}

// ---------------------------------------------------------------------------
// FA2-style flash attention: 8 warps x m16 rows (warp owns full rows).
// S accum fragments repack in-register into PV A-fragments (no P smem).
// Row stats warp-local (shfl over tig only). Vt double-buffered.
// 2 barriers per KV iteration.
// Smem (halves): Qs[128][136] | Ks[64][136] | Vt[2][128][72]  = 89088 B
// ---------------------------------------------------------------------------
#define QS_H   0
#define KS_H   17408
#define VT_H   26112
#define VT_BUF 9216
#define FLASH_SMEM_BYTES 89088

__global__ void __launch_bounds__(256, 2)
flash_k()
{
    extern __shared__ __align__(16) char smraw[];
    unsigned short* smh = (unsigned short*)smraw;

    const int tid  = threadIdx.x;
    const int lane = tid & 31;
    const int warp = tid >> 5;
    const int l16  = lane & 15;
    const int kh   = (lane >> 4) * 8;
    const int g    = lane >> 2;
    const int tig  = lane & 3;

    const int wm = warp * 16;            // warp's row block within Q tile

    const int m0 = blockIdx.x * 128;
    const int z  = blockIdx.y;
    const int b  = z >> 3;
    const int h  = z & 7;

    const unsigned short* Qg = g_qh + (size_t)z * (TT*DQ);
    const unsigned short* Kg = g_kh + (size_t)z * (TT*DQ);
    const unsigned short* Vg = g_vh + (size_t)z * (TT*DQ);

    // prologue: Q (128x128 halves) + K tile 0 (64x128)
#pragma unroll
    for (int i = 0; i < 8; i++) {
        int ch = tid + i * 256;
        int r = ch >> 4, c8 = (ch & 15) * 8;
        cp16(&smh[QS_H + r * 136 + c8], Qg + (size_t)(m0 + r) * DQ + c8);
    }
#pragma unroll
    for (int i = 0; i < 4; i++) {
        int ch = tid + i * 256;
        int r = ch >> 4, c8 = (ch & 15) * 8;
        cp16(&smh[KS_H + r * 136 + c8], Kg + (size_t)r * DQ + c8);
    }
    cp_commit();

    float co[16][4];
#pragma unroll
    for (int nt = 0; nt < 16; nt++)
#pragma unroll
        for (int r = 0; r < 4; r++) co[nt][r] = 0.f;
    float mrun[2] = {-1e30f, -1e30f};
    float lrun[2] = {0.f, 0.f};

    for (int kt = 0; kt < 16; kt++) {
        cp_wait0();
        __syncthreads();                 // barrier 1: K(kt) visible everywhere

        // ---- S = Q K^T : warp tile 16 x 64, 8 k16 steps ----
        float cs[8][4];
#pragma unroll
        for (int nt = 0; nt < 8; nt++)
#pragma unroll
            for (int r = 0; r < 4; r++) cs[nt][r] = 0.f;
#pragma unroll
        for (int ks = 0; ks < 8; ks++) {
            const int kofs = ks * 16 + kh;
            unsigned a[4];
            ldm_x4(a[0], a[1], a[2], a[3], &smh[QS_H + (wm + l16) * 136 + kofs]);
#pragma unroll
            for (int bt = 0; bt < 4; bt++) {
                unsigned r0, r1, r2, r3;
                ldm_x4(r0, r1, r2, r3, &smh[KS_H + (bt*16 + l16) * 136 + kofs]);
                unsigned bf0[2] = {r0, r2};
                unsigned bf1[2] = {r1, r3};
                mma_f16(cs[bt*2 + 0], a, bf0);
                mma_f16(cs[bt*2 + 1], a, bf1);
            }
        }

        // ---- V tile transpose into Vt[kt&1] ----
        const int vtb = VT_H + (kt & 1) * VT_BUF;
#pragma unroll
        for (int i = 0; i < 2; i++) {
            int lin = tid + i * 256;
            int tp = lin & 31, d8 = (lin >> 5) * 8;
            const unsigned short* vp = Vg + (size_t)(kt*64 + 2*tp) * DQ + d8;
            float4 va = *(const float4*)vp;
            float4 vb = *(const float4*)(vp + DQ);
            const __half* ha = (const __half*)&va;
            const __half* hb = (const __half*)&vb;
#pragma unroll
            for (int j = 0; j < 8; j++) {
                __half2 pr = __halves2half2(ha[j], hb[j]);
                *(__half2*)&smh[vtb + (d8 + j) * 72 + 2*tp] = pr;
            }
        }

        // ---- mask + row max (warp-local) ----
        float rmax[2] = {-1e30f, -1e30f};
#pragma unroll
        for (int nt = 0; nt < 8; nt++) {
            int col = kt*64 + nt*8 + 2*tig;
            float2 mk = *(const float2*)&g_maskf[b*TT + col];
            if (mk.x == 0.f) { cs[nt][0] = -1e30f; cs[nt][2] = -1e30f; }
            if (mk.y == 0.f) { cs[nt][1] = -1e30f; cs[nt][3] = -1e30f; }
            rmax[0] = fmaxf(rmax[0], fmaxf(cs[nt][0], cs[nt][1]));
            rmax[1] = fmaxf(rmax[1], fmaxf(cs[nt][2], cs[nt][3]));
        }
#pragma unroll
        for (int i = 0; i < 2; i++) {
            rmax[i] = fmaxf(rmax[i], __shfl_xor_sync(0xFFFFFFFFu, rmax[i], 1));
            rmax[i] = fmaxf(rmax[i], __shfl_xor_sync(0xFFFFFFFFu, rmax[i], 2));
        }

        __syncthreads();                 // barrier 2: K reads done + Vt written

        // prefetch next K tile into the (single) K buffer
        if (kt + 1 < 16) {
#pragma unroll
            for (int i = 0; i < 4; i++) {
                int ch = tid + i * 256;
                int r = ch >> 4, c8 = (ch & 15) * 8;
                cp16(&smh[KS_H + r * 136 + c8], Kg + (size_t)((kt+1)*64 + r) * DQ + c8);
            }
            cp_commit();
        }

        // ---- softmax in registers, pack P into PV A-fragments ----
        float newm[2], alpha[2], rsum[2] = {0.f, 0.f};
#pragma unroll
        for (int i = 0; i < 2; i++) {
            newm[i] = fmaxf(mrun[i], rmax[i]);
            alpha[i] = __expf(mrun[i] - newm[i]);
        }
        unsigned ap[4][4];
#pragma unroll
        for (int nt = 0; nt < 8; nt++) {
            float p0 = (cs[nt][0] <= -1e29f) ? 0.f : __expf(cs[nt][0] - newm[0]);
            float p1 = (cs[nt][1] <= -1e29f) ? 0.f : __expf(cs[nt][1] - newm[0]);
            float p2 = (cs[nt][2] <= -1e29f) ? 0.f : __expf(cs[nt][2] - newm[1]);
            float p3 = (cs[nt][3] <= -1e29f) ? 0.f : __expf(cs[nt][3] - newm[1]);
            rsum[0] += p0 + p1;
            rsum[1] += p2 + p3;
            const int base = (nt & 1) * 2;
            ap[nt >> 1][base + 0] = h2u(__floats2half2_rn(p0, p1));
            ap[nt >> 1][base + 1] = h2u(__floats2half2_rn(p2, p3));
        }
#pragma unroll
        for (int i = 0; i < 2; i++) {
            rsum[i] += __shfl_xor_sync(0xFFFFFFFFu, rsum[i], 1);
            rsum[i] += __shfl_xor_sync(0xFFFFFFFFu, rsum[i], 2);
            lrun[i] = lrun[i] * alpha[i] + rsum[i];
            mrun[i] = newm[i];
        }
        // rescale O
#pragma unroll
        for (int nt = 0; nt < 16; nt++) {
            co[nt][0] *= alpha[0]; co[nt][1] *= alpha[0];
            co[nt][2] *= alpha[1]; co[nt][3] *= alpha[1];
        }

        // ---- O += P V : 4 k16 steps, n = d = 128, A from registers ----
#pragma unroll
        for (int ks = 0; ks < 4; ks++) {
            const int kofs = ks * 16 + kh;
#pragma unroll
            for (int bt = 0; bt < 8; bt++) {
                unsigned r0, r1, r2, r3;
                ldm_x4(r0, r1, r2, r3, &smh[vtb + (bt*16 + l16) * 72 + kofs]);
                unsigned bf0[2] = {r0, r2};
                unsigned bf1[2] = {r1, r3};
                mma_f16(co[bt*2 + 0], ap[ks], bf0);
                mma_f16(co[bt*2 + 1], ap[ks], bf1);
            }
        }
    }

    // ---- epilogue: O /= l, store fp16 to g_ob [B,T,H*128] ----
    float invl[2] = {1.0f / lrun[0], 1.0f / lrun[1]};
    const int rowA = m0 + wm + g;
#pragma unroll
    for (int nt = 0; nt < 16; nt++) {
        int col = nt*8 + 2*tig;
        unsigned lo = h2u(__floats2half2_rn(co[nt][0]*invl[0], co[nt][1]*invl[0]));
        unsigned hi = h2u(__floats2half2_rn(co[nt][2]*invl[1], co[nt][3]*invl[1]));
        *(unsigned*)(g_ob + ((size_t)(b*TT + rowA)) * DMOD + h*DQ + col) = lo;
        *(unsigned*)(g_ob + ((size_t)(b*TT + rowA + 8)) * DMOD + h*DQ + col) = hi;
    }
}

// ---------------------------------------------------------------------------
// Fused residual + LayerNorm
// ---------------------------------------------------------------------------
template<int PHASE>
__global__ void __launch_bounds__(256)
ln_k(const float* __restrict__ a,
     const float* __restrict__ gamma,
     const float* __restrict__ beta,
     float* __restrict__ outp)
{
    const int row = blockIdx.x;
    const int tid = threadIdx.x;
    const int lane = tid & 31, wid = tid >> 5;
    const float* r1 = (PHASE == 0) ? a : g_x1;

    __shared__ float red1[8];
    __shared__ float red2[8];

    float4 av = ((const float4*)(r1 + (size_t)row * DMOD))[tid];
    float4 tv = ((const float4*)(g_t1 + (size_t)row * DMOD))[tid];
    float v[4] = {av.x + tv.x, av.y + tv.y, av.z + tv.z, av.w + tv.w};

    float s = v[0] + v[1] + v[2] + v[3];
#pragma unroll
    for (int o = 16; o > 0; o >>= 1) s += __shfl_xor_sync(0xFFFFFFFFu, s, o);
    if (lane == 0) red1[wid] = s;
    __syncthreads();
    float tot = red1[0];
#pragma unroll
    for (int i = 1; i < 8; i++) tot += red1[i];
    const float mu = tot * (1.0f / DMOD);

    float vs = 0.f;
#pragma unroll
    for (int i = 0; i < 4; i++) { float d = v[i] - mu; vs += d * d; }
#pragma unroll
    for (int o = 16; o > 0; o >>= 1) vs += __shfl_xor_sync(0xFFFFFFFFu, vs, o);
    if (lane == 0) red2[wid] = vs;
    __syncthreads();
    float vtot = red2[0];
#pragma unroll
    for (int i = 1; i < 8; i++) vtot += red2[i];
    const float rs = rsqrtf(vtot * (1.0f / DMOD) + 1e-5f);

    float4 g4 = ((const float4*)gamma)[tid];
    float4 b4 = ((const float4*)beta)[tid];
    float4 o4;
    o4.x = (v[0] - mu) * rs * g4.x + b4.x;
    o4.y = (v[1] - mu) * rs * g4.y + b4.y;
    o4.z = (v[2] - mu) * rs * g4.z + b4.z;
    o4.w = (v[3] - mu) * rs * g4.w + b4.w;

    if constexpr (PHASE == 0) {
        ((float4*)(g_x1 + (size_t)row * DMOD))[tid] = o4;
        uint2 p;
        p.x = h2u(__floats2half2_rn(o4.x, o4.y));
        p.y = h2u(__floats2half2_rn(o4.z, o4.w));
        ((uint2*)(g_x1h + (size_t)row * DMOD))[tid] = p;
    } else {
        ((float4*)(outp + (size_t)row * DMOD))[tid] = o4;
    }
}

// ---------------------------------------------------------------------------
extern "C" void kernel_launch(void* const* d_in, const int* in_sizes, int n_in,
                              void* d_out, int out_size)
{
    (void)in_sizes; (void)n_in; (void)out_size;
    const float* x      = (const float*)d_in[0];
    const void*  mask   = d_in[1];
    const float* wqkv_c = (const float*)d_in[2];
    const float* wqkv_p = (const float*)d_in[3];
    const float* wo_c   = (const float*)d_in[4];
    const float* wo_p   = (const float*)d_in[5];
    const float* w1_c   = (const float*)d_in[6];
    const float* b1_c   = (const float*)d_in[7];
    const float* w1_p   = (const float*)d_in[8];
    const float* b1_p   = (const float*)d_in[9];
    const float* w2_c   = (const float*)d_in[10];
    const float* b2_c   = (const float*)d_in[11];
    const float* w2_p   = (const float*)d_in[12];
    const float* b2_p   = (const float*)d_in[13];
    const float* ln1_g  = (const float*)d_in[14];
    const float* ln1_b  = (const float*)d_in[15];
    const float* ln2_g  = (const float*)d_in[16];
    const float* ln2_b  = (const float*)d_in[17];
    float* out = (float*)d_out;

    cudaFuncSetAttribute(flash_k, cudaFuncAttributeMaxDynamicSharedMemorySize,
                         FLASH_SMEM_BYTES);

    void* xh;   cudaGetSymbolAddress(&xh,   g_xh);
    void* wqTc; cudaGetSymbolAddress(&wqTc, g_wqTc);
    void* wqTp; cudaGetSymbolAddress(&wqTp, g_wqTp);
    void* woTc; cudaGetSymbolAddress(&woTc, g_woTc);
    void* woTp; cudaGetSymbolAddress(&woTp, g_woTp);
    void* w1ch; cudaGetSymbolAddress(&w1ch, g_w1ch);
    void* w1ph; cudaGetSymbolAddress(&w1ph, g_w1ph);
    void* w2ch; cudaGetSymbolAddress(&w2ch, g_w2ch);
    void* w2ph; cudaGetSymbolAddress(&w2ph, g_w2ph);

    auto cvth = [&](const float* s, void* d, int n) {
        int n4 = n >> 2;
        cvth_k<<<(n4 + 255) / 256, 256>>>((const float4*)s, (uint2*)d, n4);
    };

    // Launch order keeps flash_k as the 6th launch (ncu -s 5 -c 1 captures it).
    // 1
    mask_probe_k<<<1, 1024>>>(mask);
    // 2
    cvth(x, xh, BT*DMOD);
    // 3, 4: wqkv [8 slabs][512][192] -> [192][512]
    cvtT_k<<<dim3(6, 16, 8), dim3(32, 8)>>>(wqkv_c, (unsigned short*)wqTc, DM2, 192);
    cvtT_k<<<dim3(6, 16, 8), dim3(32, 8)>>>(wqkv_p, (unsigned short*)wqTp, DM2, 192);
    // 5: QKV (fp16)
    gemm_h<0><<<dim3(3, 32, 16), 256>>>(nullptr, nullptr);
    // 6: flash attention  <-- profiled
    flash_k<<<dim3(8, 32), 256, FLASH_SMEM_BYTES>>>();
    // 7, 8: wo transpose-convert
    cvtT_k<<<dim3(16, 16, 1), dim3(32, 8)>>>(wo_c, (unsigned short*)woTc, DM2, DM2);
    cvtT_k<<<dim3(16, 16, 1), dim3(32, 8)>>>(wo_p, (unsigned short*)woTp, DM2, DM2);
    // 9: OPROJ
    gemm_h<3><<<dim3(8, 32, 2), 256>>>(nullptr, nullptr);
    // 10: LN1
    ln_k<0><<<BT, 256>>>(x, ln1_g, ln1_b, nullptr);
    // 11-14: FFN weight converts
    cvth(w1_c, w1ch, DF2*DM2);
    cvth(w1_p, w1ph, DF2*DM2);
    cvth(w2_c, w2ch, DM2*DF2);
    cvth(w2_p, w2ph, DM2*DF2);
    // 15: FFN1
    gemm_h<4><<<dim3(32, 32, 2), 256>>>(b1_c, b1_p);
    // 16: FFN2
    gemm_h<5><<<dim3(8, 32, 2), 256>>>(b2_c, b2_p);
    // 17: LN2 -> out
    ln_k<1><<<BT, 256>>>(nullptr, ln2_g, ln2_b, out);
}

// round 10
// speedup vs baseline: 1.9164x; 1.0794x over previous
#include <cuda_runtime.h>
#include <cuda_fp16.h>
#include <math.h>
#include <stdint.h>

// ---------------------------------------------------------------------------
// PartitionedTransformerEncoderLayer — Round 10: fp16 HMMA, FA2 flash,
// 128x128 FFN tiles, consolidated conversion kernels (11 launches total)
// ---------------------------------------------------------------------------

#define HH   8
#define TT   1024
#define BB   4
#define DMOD 1024
#define DM2  512
#define DQ   128
#define DQ2  64
#define DF2  2048
#define BT   4096

// fp16 scratch
__device__ unsigned short g_qh[BB*HH*TT*DQ];
__device__ unsigned short g_kh[BB*HH*TT*DQ];
__device__ unsigned short g_vh[BB*HH*TT*DQ];
__device__ unsigned short g_ob[(size_t)BT*DMOD];
__device__ unsigned short g_xh[(size_t)BT*DMOD];
__device__ unsigned short g_x1h[(size_t)BT*DMOD];
__device__ unsigned short g_hh[(size_t)BT*2*DF2];
__device__ unsigned short g_wqTc[HH*192*DM2];
__device__ unsigned short g_wqTp[HH*192*DM2];
__device__ unsigned short g_woTc[DM2*DM2];
__device__ unsigned short g_woTp[DM2*DM2];
__device__ unsigned short g_w1ch[DF2*DM2];
__device__ unsigned short g_w1ph[DF2*DM2];
__device__ unsigned short g_w2ch[DM2*DF2];
__device__ unsigned short g_w2ph[DM2*DF2];
// fp32 scratch
__device__ float g_t1[(size_t)BT*DMOD];
__device__ float g_x1[(size_t)BT*DMOD];
__device__ float g_maskf[BB*TT];

// ---------------------------------------------------------------------------
__device__ __forceinline__ void cp16(void* smem, const void* g) {
    unsigned s = (unsigned)__cvta_generic_to_shared(smem);
    asm volatile("cp.async.cg.shared.global [%0], [%1], 16;" :: "r"(s), "l"(g));
}
__device__ __forceinline__ void cp_commit() { asm volatile("cp.async.commit_group;"); }
__device__ __forceinline__ void cp_wait0()  { asm volatile("cp.async.wait_group 0;"); }

__device__ __forceinline__ void ldm_x4(unsigned &r0, unsigned &r1,
                                       unsigned &r2, unsigned &r3,
                                       const void* p) {
    unsigned addr = (unsigned)__cvta_generic_to_shared(p);
    asm volatile("ldmatrix.sync.aligned.m8n8.x4.shared.b16 {%0,%1,%2,%3}, [%4];"
                 : "=r"(r0), "=r"(r1), "=r"(r2), "=r"(r3) : "r"(addr));
}
__device__ __forceinline__ void mma_f16(float* c, const unsigned* a, const unsigned* b) {
    asm volatile("mma.sync.aligned.m16n8k16.row.col.f32.f16.f16.f32 "
                 "{%0,%1,%2,%3}, {%4,%5,%6,%7}, {%8,%9}, {%0,%1,%2,%3};"
                 : "+f"(c[0]), "+f"(c[1]), "+f"(c[2]), "+f"(c[3])
                 : "r"(a[0]), "r"(a[1]), "r"(a[2]), "r"(a[3]),
                   "r"(b[0]), "r"(b[1]));
}
__device__ __forceinline__ unsigned h2u(__half2 h) { return *(unsigned*)&h; }

// ---------------------------------------------------------------------------
// Mask canonicalization
// ---------------------------------------------------------------------------
__global__ void mask_probe_k(const void* __restrict__ maskraw) {
    const unsigned int* w = (const unsigned int*)maskraw;
    int tid = threadIdx.x;
    unsigned int v = w[tid];
    int oki = (v == 0u || v == 1u);
    int okf = (v == 0u || v == 0x3F800000u);
    int all_i = __syncthreads_and(oki);
    int all_f = __syncthreads_and(okf);
    if (all_i) {
        const int* wi = (const int*)maskraw;
        for (int i = tid; i < BB*TT; i += 1024) g_maskf[i] = wi[i] ? 1.f : 0.f;
    } else if (all_f) {
        const float* wf = (const float*)maskraw;
        for (int i = tid; i < BB*TT; i += 1024) g_maskf[i] = (wf[i] != 0.f) ? 1.f : 0.f;
    } else {
        const unsigned char* wb = (const unsigned char*)maskraw;
        for (int i = tid; i < BB*TT; i += 1024) g_maskf[i] = wb[i] ? 1.f : 0.f;
    }
}

// ---------------------------------------------------------------------------
// Consolidated fp32 -> fp16 conversion: x (1048576 f4) + w1c/w1p/w2c/w2p
// (262144 f4 each). Linear segment map over 2097152 float4s.
// ---------------------------------------------------------------------------
__global__ void __launch_bounds__(256)
cvt_all_k(const float4* __restrict__ x,   uint2* __restrict__ xh,
          const float4* __restrict__ w1c, uint2* __restrict__ d1c,
          const float4* __restrict__ w1p, uint2* __restrict__ d1p,
          const float4* __restrict__ w2c, uint2* __restrict__ d2c,
          const float4* __restrict__ w2p, uint2* __restrict__ d2p)
{
    int i = blockIdx.x * 256 + threadIdx.x;
    const float4* s; uint2* d; int off;
    if (i < 1048576) { s = x; d = xh; off = i; }
    else {
        int j = i - 1048576;
        int seg = j >> 18;
        off = j & 262143;
        if      (seg == 0) { s = w1c; d = d1c; }
        else if (seg == 1) { s = w1p; d = d1p; }
        else if (seg == 2) { s = w2c; d = d2c; }
        else               { s = w2p; d = d2p; }
    }
    float4 v = s[off];
    uint2 p;
    p.x = h2u(__floats2half2_rn(v.x, v.y));
    p.y = h2u(__floats2half2_rn(v.z, v.w));
    d[off] = p;
}

// fp32 [K][N] slabs (two tensors) -> fp16 [N][K] transpose-convert
__global__ void __launch_bounds__(256)
cvtT2_k(const float* __restrict__ srcA, const float* __restrict__ srcB,
        unsigned short* __restrict__ dstA, unsigned short* __restrict__ dstB,
        int K, int N, int nslab)
{
    __shared__ float t[32][33];
    const int zz = blockIdx.z;
    const float* src = (zz < nslab) ? srcA : srcB;
    unsigned short* dst = (zz < nslab) ? dstA : dstB;
    const int sl = (zz < nslab) ? zz : zz - nslab;
    const size_t slab = (size_t)sl * K * N;
    const int n0 = blockIdx.x * 32, k0 = blockIdx.y * 32;
    const int tx = threadIdx.x, ty = threadIdx.y;   // 32 x 8
#pragma unroll
    for (int j = 0; j < 4; j++)
        t[ty + 8*j][tx] = src[slab + (size_t)(k0 + ty + 8*j) * N + n0 + tx];
    __syncthreads();
#pragma unroll
    for (int j = 0; j < 4; j++) {
        __half h = __float2half_rn(t[tx][ty + 8*j]);
        dst[slab + (size_t)(n0 + ty + 8*j) * K + k0 + tx] = *(unsigned short*)&h;
    }
}

// ---------------------------------------------------------------------------
// fp16 HMMA GEMM 128x64x32 (QKV, OPROJ) — round-8 proven
// ---------------------------------------------------------------------------
template<int MODE>
__global__ void __launch_bounds__(256)
gemm_h()
{
    constexpr int K = 512;

    __shared__ unsigned short As[2][128][40];
    __shared__ unsigned short Bs[2][64][40];

    const int tid  = threadIdx.x;
    const int lane = tid & 31;
    const int warp = tid >> 5;
    const int wm = (warp & 3) * 32;
    const int wn = (warp >> 2) * 32;
    const int m0 = blockIdx.y * 128;
    const int n0 = blockIdx.x * 64;
    const int z  = blockIdx.z;

    const unsigned short* Ab = (MODE == 0) ? g_xh + (size_t)(z >> 3) * DM2 : g_ob;

    const unsigned short* Wb;
    int bstr;
    if constexpr (MODE == 0) { Wb = ((z >> 3) ? g_wqTp : g_wqTc) + (size_t)(z & 7) * (192*DM2); bstr = DM2; }
    else                     { Wb = z ? g_woTp : g_woTc; bstr = DM2; }

    float c[2][4][4];
#pragma unroll
    for (int mt = 0; mt < 2; mt++)
#pragma unroll
        for (int nt = 0; nt < 4; nt++)
#pragma unroll
            for (int r = 0; r < 4; r++) c[mt][nt][r] = 0.f;

    const int ld_r  = tid >> 2;
    const int ld_c8 = (tid & 3) << 3;

    auto a_idx = [&](int m, int k) -> size_t {
        if constexpr (MODE == 3)
            return (size_t)m * DMOD + (size_t)((k >> 6) << 7) + (size_t)z * DQ2 + (k & 63);
        else
            return (size_t)m * DMOD + k;
    };

    auto loadA = [&](int k0, int buf) {
#pragma unroll
        for (int it = 0; it < 2; it++) {
            int m = m0 + ld_r + it * 64;
            cp16(&As[buf][ld_r + it * 64][ld_c8], Ab + a_idx(m, k0 + ld_c8));
        }
    };
    auto loadB = [&](int k0, int buf) {
        int n = n0 + ld_r;
        cp16(&Bs[buf][ld_r][ld_c8], Wb + (size_t)n * bstr + k0 + ld_c8);
    };

    loadA(0, 0);
    loadB(0, 0);
    cp_commit();
    cp_wait0();
    __syncthreads();

    const int l16 = lane & 15;
    const int kh  = (lane >> 4) * 8;

    int cur = 0;
    for (int k0 = 0; k0 < K; k0 += 32) {
        const int nxt = cur ^ 1;
        const bool has_next = (k0 + 32 < K);
        if (has_next) {
            loadA(k0 + 32, nxt);
            loadB(k0 + 32, nxt);
            cp_commit();
        }
#pragma unroll
        for (int ks = 0; ks < 2; ks++) {
            const int kofs = ks * 16 + kh;
            unsigned a[2][4];
#pragma unroll
            for (int mt = 0; mt < 2; mt++)
                ldm_x4(a[mt][0], a[mt][1], a[mt][2], a[mt][3],
                       &As[cur][wm + mt*16 + l16][kofs]);
            unsigned b[4][2];
#pragma unroll
            for (int bt = 0; bt < 2; bt++) {
                unsigned r0, r1, r2, r3;
                ldm_x4(r0, r1, r2, r3, &Bs[cur][wn + bt*16 + l16][kofs]);
                b[bt*2 + 0][0] = r0; b[bt*2 + 0][1] = r2;
                b[bt*2 + 1][0] = r1; b[bt*2 + 1][1] = r3;
            }
#pragma unroll
            for (int mt = 0; mt < 2; mt++)
#pragma unroll
                for (int nt = 0; nt < 4; nt++)
                    mma_f16(c[mt][nt], a[mt], b[nt]);
        }
        if (has_next) cp_wait0();
        __syncthreads();
        cur = nxt;
    }

    const int g   = lane >> 2;
    const int tig = lane & 3;

#pragma unroll
    for (int mt = 0; mt < 2; mt++) {
#pragma unroll
        for (int nt = 0; nt < 4; nt++) {
            const int mr = m0 + wm + mt*16 + g;
            const int nl = wn + nt*8 + 2*tig;

            if constexpr (MODE == 0) {
                const int cc = blockIdx.x;
                const int hh = z & 7, sel = z >> 3;
                const float scale = (cc == 0) ? 0.08838834764831845f : 1.0f;
                unsigned short* dst = (cc == 0) ? g_qh : ((cc == 1) ? g_kh : g_vh);
                unsigned lo = h2u(__floats2half2_rn(c[mt][nt][0]*scale, c[mt][nt][1]*scale));
                unsigned hi = h2u(__floats2half2_rn(c[mt][nt][2]*scale, c[mt][nt][3]*scale));
                {
                    int b_ = mr >> 10, t_ = mr & 1023;
                    size_t base = (((size_t)(b_*HH + hh))*TT + t_) * DQ + sel*DQ2;
                    *(unsigned*)(dst + base + nl) = lo;
                }
                {
                    int m2 = mr + 8;
                    int b_ = m2 >> 10, t_ = m2 & 1023;
                    size_t base = (((size_t)(b_*HH + hh))*TT + t_) * DQ + sel*DQ2;
                    *(unsigned*)(dst + base + nl) = hi;
                }
            } else {
                size_t r0 = (size_t)mr * DMOD + (size_t)z * DM2 + n0 + nl;
                *(float2*)(g_t1 + r0) = make_float2(c[mt][nt][0], c[mt][nt][1]);
                *(float2*)(g_t1 + r0 + 8*DMOD) = make_float2(c[mt][nt][2], c[mt][nt][3]);
            }
        }
    }
}

// ---------------------------------------------------------------------------
// fp16 HMMA GEMM 128x128x32 (FFN): 8 warps (4M x 2N), warp 32x64,
// mma:ldm = 2.67, halves A re-reads vs N=64 tiles.
//  MODE 4 FFN1: A=g_x1h (half z), B=g_w1{c,p}h +bias relu -> g_hh
//  MODE 5 FFN2: A=g_hh  (half z), B=g_w2{c,p}h +bias      -> g_t1
// ---------------------------------------------------------------------------
template<int MODE>
__global__ void __launch_bounds__(256, 2)
gemm_hb(const float* __restrict__ bias0,
        const float* __restrict__ bias1)
{
    constexpr int K = (MODE == 4) ? 512 : 2048;

    __shared__ unsigned short As[2][128][40];
    __shared__ unsigned short Bs[2][128][40];

    const int tid  = threadIdx.x;
    const int lane = tid & 31;
    const int warp = tid >> 5;
    const int wm = (warp & 3) * 32;
    const int wn = (warp >> 2) * 64;
    const int m0 = blockIdx.y * 128;
    const int n0 = blockIdx.x * 128;
    const int z  = blockIdx.z;

    const unsigned short* Ab;
    int astr;
    if constexpr (MODE == 4) { Ab = g_x1h + (size_t)z * DM2; astr = DMOD;  }
    else                     { Ab = g_hh  + (size_t)z * DF2; astr = 2*DF2; }

    const unsigned short* Wb;
    int bstr;
    if constexpr (MODE == 4) { Wb = z ? g_w1ph : g_w1ch; bstr = DM2; }
    else                     { Wb = z ? g_w2ph : g_w2ch; bstr = DF2; }

    float c[2][8][4];
#pragma unroll
    for (int mt = 0; mt < 2; mt++)
#pragma unroll
        for (int nt = 0; nt < 8; nt++)
#pragma unroll
            for (int r = 0; r < 4; r++) c[mt][nt][r] = 0.f;

    const int ld_r  = tid >> 2;          // 0..63
    const int ld_c8 = (tid & 3) << 3;    // 0,8,16,24 halves

    auto loadA = [&](int k0, int buf) {
#pragma unroll
        for (int it = 0; it < 2; it++) {
            int m = m0 + ld_r + it * 64;
            cp16(&As[buf][ld_r + it * 64][ld_c8], Ab + (size_t)m * astr + k0 + ld_c8);
        }
    };
    auto loadB = [&](int k0, int buf) {
#pragma unroll
        for (int it = 0; it < 2; it++) {
            int n = n0 + ld_r + it * 64;
            cp16(&Bs[buf][ld_r + it * 64][ld_c8], Wb + (size_t)n * bstr + k0 + ld_c8);
        }
    };

    loadA(0, 0);
    loadB(0, 0);
    cp_commit();
    cp_wait0();
    __syncthreads();

    const int l16 = lane & 15;
    const int kh  = (lane >> 4) * 8;

    int cur = 0;
    for (int k0 = 0; k0 < K; k0 += 32) {
        const int nxt = cur ^ 1;
        const bool has_next = (k0 + 32 < K);
        if (has_next) {
            loadA(k0 + 32, nxt);
            loadB(k0 + 32, nxt);
            cp_commit();
        }
#pragma unroll
        for (int ks = 0; ks < 2; ks++) {
            const int kofs = ks * 16 + kh;
            unsigned a[2][4];
#pragma unroll
            for (int mt = 0; mt < 2; mt++)
                ldm_x4(a[mt][0], a[mt][1], a[mt][2], a[mt][3],
                       &As[cur][wm + mt*16 + l16][kofs]);
#pragma unroll
            for (int bt = 0; bt < 4; bt++) {
                unsigned r0, r1, r2, r3;
                ldm_x4(r0, r1, r2, r3, &Bs[cur][wn + bt*16 + l16][kofs]);
                unsigned bf0[2] = {r0, r2};
                unsigned bf1[2] = {r1, r3};
#pragma unroll
                for (int mt = 0; mt < 2; mt++) {
                    mma_f16(c[mt][bt*2 + 0], a[mt], bf0);
                    mma_f16(c[mt][bt*2 + 1], a[mt], bf1);
                }
            }
        }
        if (has_next) cp_wait0();
        __syncthreads();
        cur = nxt;
    }

    // ---- epilogue ----
    const int g   = lane >> 2;
    const int tig = lane & 3;
    const float* bs = z ? bias1 : bias0;

#pragma unroll
    for (int mt = 0; mt < 2; mt++) {
#pragma unroll
        for (int nt = 0; nt < 8; nt++) {
            const int mr = m0 + wm + mt*16 + g;
            const int nl = wn + nt*8 + 2*tig;
            float b0 = bs[n0 + nl], b1 = bs[n0 + nl + 1];

            if constexpr (MODE == 4) {
                size_t e0 = (size_t)mr * (2*DF2) + (size_t)z * DF2 + n0 + nl;
                unsigned lo = h2u(__floats2half2_rn(fmaxf(c[mt][nt][0]+b0, 0.f),
                                                    fmaxf(c[mt][nt][1]+b1, 0.f)));
                unsigned hi = h2u(__floats2half2_rn(fmaxf(c[mt][nt][2]+b0, 0.f),
                                                    fmaxf(c[mt][nt][3]+b1, 0.f)));
                *(unsigned*)(g_hh + e0) = lo;
                *(unsigned*)(g_hh + e0 + (size_t)8 * (2*DF2)) = hi;
            } else {
                size_t r0 = (size_t)mr * DMOD + (size_t)z * DM2 + n0 + nl;
                *(float2*)(g_t1 + r0) = make_float2(c[mt][nt][0]+b0, c[mt][nt][1]+b1);
                *(float2*)(g_t1 + r0 + 8*DMOD) = make_float2(c[mt][nt][2]+b0, c[mt][nt][3]+b1);
            }
        }
    }
}

// ---------------------------------------------------------------------------
// FA2-style flash attention (round-9 proven)
// ---------------------------------------------------------------------------
#define QS_H   0
#define KS_H   17408
#define VT_H   26112
#define VT_BUF 9216
#define FLASH_SMEM_BYTES 89088

__global__ void __launch_bounds__(256, 2)
flash_k()
{
    extern __shared__ __align__(16) char smraw[];
    unsigned short* smh = (unsigned short*)smraw;

    const int tid  = threadIdx.x;
    const int lane = tid & 31;
    const int warp = tid >> 5;
    const int l16  = lane & 15;
    const int kh   = (lane >> 4) * 8;
    const int g    = lane >> 2;
    const int tig  = lane & 3;

    const int wm = warp * 16;

    const int m0 = blockIdx.x * 128;
    const int z  = blockIdx.y;
    const int b  = z >> 3;
    const int h  = z & 7;

    const unsigned short* Qg = g_qh + (size_t)z * (TT*DQ);
    const unsigned short* Kg = g_kh + (size_t)z * (TT*DQ);
    const unsigned short* Vg = g_vh + (size_t)z * (TT*DQ);

#pragma unroll
    for (int i = 0; i < 8; i++) {
        int ch = tid + i * 256;
        int r = ch >> 4, c8 = (ch & 15) * 8;
        cp16(&smh[QS_H + r * 136 + c8], Qg + (size_t)(m0 + r) * DQ + c8);
    }
#pragma unroll
    for (int i = 0; i < 4; i++) {
        int ch = tid + i * 256;
        int r = ch >> 4, c8 = (ch & 15) * 8;
        cp16(&smh[KS_H + r * 136 + c8], Kg + (size_t)r * DQ + c8);
    }
    cp_commit();

    float co[16][4];
#pragma unroll
    for (int nt = 0; nt < 16; nt++)
#pragma unroll
        for (int r = 0; r < 4; r++) co[nt][r] = 0.f;
    float mrun[2] = {-1e30f, -1e30f};
    float lrun[2] = {0.f, 0.f};

    for (int kt = 0; kt < 16; kt++) {
        cp_wait0();
        __syncthreads();

        float cs[8][4];
#pragma unroll
        for (int nt = 0; nt < 8; nt++)
#pragma unroll
            for (int r = 0; r < 4; r++) cs[nt][r] = 0.f;
#pragma unroll
        for (int ks = 0; ks < 8; ks++) {
            const int kofs = ks * 16 + kh;
            unsigned a[4];
            ldm_x4(a[0], a[1], a[2], a[3], &smh[QS_H + (wm + l16) * 136 + kofs]);
#pragma unroll
            for (int bt = 0; bt < 4; bt++) {
                unsigned r0, r1, r2, r3;
                ldm_x4(r0, r1, r2, r3, &smh[KS_H + (bt*16 + l16) * 136 + kofs]);
                unsigned bf0[2] = {r0, r2};
                unsigned bf1[2] = {r1, r3};
                mma_f16(cs[bt*2 + 0], a, bf0);
                mma_f16(cs[bt*2 + 1], a, bf1);
            }
        }

        const int vtb = VT_H + (kt & 1) * VT_BUF;
#pragma unroll
        for (int i = 0; i < 2; i++) {
            int lin = tid + i * 256;
            int tp = lin & 31, d8 = (lin >> 5) * 8;
            const unsigned short* vp = Vg + (size_t)(kt*64 + 2*tp) * DQ + d8;
            float4 va = *(const float4*)vp;
            float4 vb = *(const float4*)(vp + DQ);
            const __half* ha = (const __half*)&va;
            const __half* hb = (const __half*)&vb;
#pragma unroll
            for (int j = 0; j < 8; j++) {
                __half2 pr = __halves2half2(ha[j], hb[j]);
                *(__half2*)&smh[vtb + (d8 + j) * 72 + 2*tp] = pr;
            }
        }

        float rmax[2] = {-1e30f, -1e30f};
#pragma unroll
        for (int nt = 0; nt < 8; nt++) {
            int col = kt*64 + nt*8 + 2*tig;
            float2 mk = *(const float2*)&g_maskf[b*TT + col];
            if (mk.x == 0.f) { cs[nt][0] = -1e30f; cs[nt][2] = -1e30f; }
            if (mk.y == 0.f) { cs[nt][1] = -1e30f; cs[nt][3] = -1e30f; }
            rmax[0] = fmaxf(rmax[0], fmaxf(cs[nt][0], cs[nt][1]));
            rmax[1] = fmaxf(rmax[1], fmaxf(cs[nt][2], cs[nt][3]));
        }
#pragma unroll
        for (int i = 0; i < 2; i++) {
            rmax[i] = fmaxf(rmax[i], __shfl_xor_sync(0xFFFFFFFFu, rmax[i], 1));
            rmax[i] = fmaxf(rmax[i], __shfl_xor_sync(0xFFFFFFFFu, rmax[i], 2));
        }

        __syncthreads();

        if (kt + 1 < 16) {
#pragma unroll
            for (int i = 0; i < 4; i++) {
                int ch = tid + i * 256;
                int r = ch >> 4, c8 = (ch & 15) * 8;
                cp16(&smh[KS_H + r * 136 + c8], Kg + (size_t)((kt+1)*64 + r) * DQ + c8);
            }
            cp_commit();
        }

        float newm[2], alpha[2], rsum[2] = {0.f, 0.f};
#pragma unroll
        for (int i = 0; i < 2; i++) {
            newm[i] = fmaxf(mrun[i], rmax[i]);
            alpha[i] = __expf(mrun[i] - newm[i]);
        }
        unsigned ap[4][4];
#pragma unroll
        for (int nt = 0; nt < 8; nt++) {
            float p0 = (cs[nt][0] <= -1e29f) ? 0.f : __expf(cs[nt][0] - newm[0]);
            float p1 = (cs[nt][1] <= -1e29f) ? 0.f : __expf(cs[nt][1] - newm[0]);
            float p2 = (cs[nt][2] <= -1e29f) ? 0.f : __expf(cs[nt][2] - newm[1]);
            float p3 = (cs[nt][3] <= -1e29f) ? 0.f : __expf(cs[nt][3] - newm[1]);
            rsum[0] += p0 + p1;
            rsum[1] += p2 + p3;
            const int base = (nt & 1) * 2;
            ap[nt >> 1][base + 0] = h2u(__floats2half2_rn(p0, p1));
            ap[nt >> 1][base + 1] = h2u(__floats2half2_rn(p2, p3));
        }
#pragma unroll
        for (int i = 0; i < 2; i++) {
            rsum[i] += __shfl_xor_sync(0xFFFFFFFFu, rsum[i], 1);
            rsum[i] += __shfl_xor_sync(0xFFFFFFFFu, rsum[i], 2);
            lrun[i] = lrun[i] * alpha[i] + rsum[i];
            mrun[i] = newm[i];
        }
#pragma unroll
        for (int nt = 0; nt < 16; nt++) {
            co[nt][0] *= alpha[0]; co[nt][1] *= alpha[0];
            co[nt][2] *= alpha[1]; co[nt][3] *= alpha[1];
        }

#pragma unroll
        for (int ks = 0; ks < 4; ks++) {
            const int kofs = ks * 16 + kh;
#pragma unroll
            for (int bt = 0; bt < 8; bt++) {
                unsigned r0, r1, r2, r3;
                ldm_x4(r0, r1, r2, r3, &smh[vtb + (bt*16 + l16) * 72 + kofs]);
                unsigned bf0[2] = {r0, r2};
                unsigned bf1[2] = {r1, r3};
                mma_f16(co[bt*2 + 0], ap[ks], bf0);
                mma_f16(co[bt*2 + 1], ap[ks], bf1);
            }
        }
    }

    float invl[2] = {1.0f / lrun[0], 1.0f / lrun[1]};
    const int rowA = m0 + wm + g;
#pragma unroll
    for (int nt = 0; nt < 16; nt++) {
        int col = nt*8 + 2*tig;
        unsigned lo = h2u(__floats2half2_rn(co[nt][0]*invl[0], co[nt][1]*invl[0]));
        unsigned hi = h2u(__floats2half2_rn(co[nt][2]*invl[1], co[nt][3]*invl[1]));
        *(unsigned*)(g_ob + ((size_t)(b*TT + rowA)) * DMOD + h*DQ + col) = lo;
        *(unsigned*)(g_ob + ((size_t)(b*TT + rowA + 8)) * DMOD + h*DQ + col) = hi;
    }
}

// ---------------------------------------------------------------------------
// Fused residual + LayerNorm
// ---------------------------------------------------------------------------
template<int PHASE>
__global__ void __launch_bounds__(256)
ln_k(const float* __restrict__ a,
     const float* __restrict__ gamma,
     const float* __restrict__ beta,
     float* __restrict__ outp)
{
    const int row = blockIdx.x;
    const int tid = threadIdx.x;
    const int lane = tid & 31, wid = tid >> 5;
    const float* r1 = (PHASE == 0) ? a : g_x1;

    __shared__ float red1[8];
    __shared__ float red2[8];

    float4 av = ((const float4*)(r1 + (size_t)row * DMOD))[tid];
    float4 tv = ((const float4*)(g_t1 + (size_t)row * DMOD))[tid];
    float v[4] = {av.x + tv.x, av.y + tv.y, av.z + tv.z, av.w + tv.w};

    float s = v[0] + v[1] + v[2] + v[3];
#pragma unroll
    for (int o = 16; o > 0; o >>= 1) s += __shfl_xor_sync(0xFFFFFFFFu, s, o);
    if (lane == 0) red1[wid] = s;
    __syncthreads();
    float tot = red1[0];
#pragma unroll
    for (int i = 1; i < 8; i++) tot += red1[i];
    const float mu = tot * (1.0f / DMOD);

    float vs = 0.f;
#pragma unroll
    for (int i = 0; i < 4; i++) { float d = v[i] - mu; vs += d * d; }
#pragma unroll
    for (int o = 16; o > 0; o >>= 1) vs += __shfl_xor_sync(0xFFFFFFFFu, vs, o);
    if (lane == 0) red2[wid] = vs;
    __syncthreads();
    float vtot = red2[0];
#pragma unroll
    for (int i = 1; i < 8; i++) vtot += red2[i];
    const float rs = rsqrtf(vtot * (1.0f / DMOD) + 1e-5f);

    float4 g4 = ((const float4*)gamma)[tid];
    float4 b4 = ((const float4*)beta)[tid];
    float4 o4;
    o4.x = (v[0] - mu) * rs * g4.x + b4.x;
    o4.y = (v[1] - mu) * rs * g4.y + b4.y;
    o4.z = (v[2] - mu) * rs * g4.z + b4.z;
    o4.w = (v[3] - mu) * rs * g4.w + b4.w;

    if constexpr (PHASE == 0) {
        ((float4*)(g_x1 + (size_t)row * DMOD))[tid] = o4;
        uint2 p;
        p.x = h2u(__floats2half2_rn(o4.x, o4.y));
        p.y = h2u(__floats2half2_rn(o4.z, o4.w));
        ((uint2*)(g_x1h + (size_t)row * DMOD))[tid] = p;
    } else {
        ((float4*)(outp + (size_t)row * DMOD))[tid] = o4;
    }
}

// ---------------------------------------------------------------------------
extern "C" void kernel_launch(void* const* d_in, const int* in_sizes, int n_in,
                              void* d_out, int out_size)
{
    (void)in_sizes; (void)n_in; (void)out_size;
    const float* x      = (const float*)d_in[0];
    const void*  mask   = d_in[1];
    const float* wqkv_c = (const float*)d_in[2];
    const float* wqkv_p = (const float*)d_in[3];
    const float* wo_c   = (const float*)d_in[4];
    const float* wo_p   = (const float*)d_in[5];
    const float* w1_c   = (const float*)d_in[6];
    const float* b1_c   = (const float*)d_in[7];
    const float* w1_p   = (const float*)d_in[8];
    const float* b1_p   = (const float*)d_in[9];
    const float* w2_c   = (const float*)d_in[10];
    const float* b2_c   = (const float*)d_in[11];
    const float* w2_p   = (const float*)d_in[12];
    const float* b2_p   = (const float*)d_in[13];
    const float* ln1_g  = (const float*)d_in[14];
    const float* ln1_b  = (const float*)d_in[15];
    const float* ln2_g  = (const float*)d_in[16];
    const float* ln2_b  = (const float*)d_in[17];
    float* out = (float*)d_out;

    cudaFuncSetAttribute(flash_k, cudaFuncAttributeMaxDynamicSharedMemorySize,
                         FLASH_SMEM_BYTES);

    void* xh;   cudaGetSymbolAddress(&xh,   g_xh);
    void* wqTc; cudaGetSymbolAddress(&wqTc, g_wqTc);
    void* wqTp; cudaGetSymbolAddress(&wqTp, g_wqTp);
    void* woTc; cudaGetSymbolAddress(&woTc, g_woTc);
    void* woTp; cudaGetSymbolAddress(&woTp, g_woTp);
    void* w1ch; cudaGetSymbolAddress(&w1ch, g_w1ch);
    void* w1ph; cudaGetSymbolAddress(&w1ph, g_w1ph);
    void* w2ch; cudaGetSymbolAddress(&w2ch, g_w2ch);
    void* w2ph; cudaGetSymbolAddress(&w2ph, g_w2ph);

    // 1: mask
    mask_probe_k<<<1, 1024>>>(mask);
    // 2: all elementwise fp32->fp16 conversions in one launch
    cvt_all_k<<<8192, 256>>>((const float4*)x, (uint2*)xh,
                             (const float4*)w1_c, (uint2*)w1ch,
                             (const float4*)w1_p, (uint2*)w1ph,
                             (const float4*)w2_c, (uint2*)w2ch,
                             (const float4*)w2_p, (uint2*)w2ph);
    // 3: wqkv transpose-convert (both tensors, 16 slabs)
    cvtT2_k<<<dim3(6, 16, 16), dim3(32, 8)>>>(wqkv_c, wqkv_p,
                                              (unsigned short*)wqTc,
                                              (unsigned short*)wqTp, DM2, 192, 8);
    // 4: wo transpose-convert (both tensors)
    cvtT2_k<<<dim3(16, 16, 2), dim3(32, 8)>>>(wo_c, wo_p,
                                              (unsigned short*)woTc,
                                              (unsigned short*)woTp, DM2, DM2, 1);
    // 5: QKV
    gemm_h<0><<<dim3(3, 32, 16), 256>>>();
    // 6: flash attention
    flash_k<<<dim3(8, 32), 256, FLASH_SMEM_BYTES>>>();
    // 7: OPROJ
    gemm_h<3><<<dim3(8, 32, 2), 256>>>();
    // 8: LN1
    ln_k<0><<<BT, 256>>>(x, ln1_g, ln1_b, nullptr);
    // 9: FFN1 (128x128 tiles)
    gemm_hb<4><<<dim3(16, 32, 2), 256>>>(b1_c, b1_p);
    // 10: FFN2 (128x128 tiles)
    gemm_hb<5><<<dim3(4, 32, 2), 256>>>(b2_c, b2_p);
    // 11: LN2 -> out
    ln_k<1><<<BT, 256>>>(nullptr, ln2_g, ln2_b, out);
}

// round 11
// speedup vs baseline: 1.9379x; 1.0112x over previous
#include <cuda_runtime.h>
#include <cuda_fp16.h>
#include <math.h>
#include <stdint.h>

// ---------------------------------------------------------------------------
// PartitionedTransformerEncoderLayer — Round 11: all GEMMs on 128x128 fp16
// tiles (QKV unified over flattened [1536][512] weight), FA2 flash.
// ---------------------------------------------------------------------------

#define HH   8
#define TT   1024
#define BB   4
#define DMOD 1024
#define DM2  512
#define DQ   128
#define DQ2  64
#define DF2  2048
#define BT   4096

// fp16 scratch
__device__ unsigned short g_qh[BB*HH*TT*DQ];
__device__ unsigned short g_kh[BB*HH*TT*DQ];
__device__ unsigned short g_vh[BB*HH*TT*DQ];
__device__ unsigned short g_ob[(size_t)BT*DMOD];
__device__ unsigned short g_xh[(size_t)BT*DMOD];
__device__ unsigned short g_x1h[(size_t)BT*DMOD];
__device__ unsigned short g_hh[(size_t)BT*2*DF2];
__device__ unsigned short g_wqTc[HH*192*DM2];
__device__ unsigned short g_wqTp[HH*192*DM2];
__device__ unsigned short g_woTc[DM2*DM2];
__device__ unsigned short g_woTp[DM2*DM2];
__device__ unsigned short g_w1ch[DF2*DM2];
__device__ unsigned short g_w1ph[DF2*DM2];
__device__ unsigned short g_w2ch[DM2*DF2];
__device__ unsigned short g_w2ph[DM2*DF2];
// fp32 scratch
__device__ float g_t1[(size_t)BT*DMOD];
__device__ float g_x1[(size_t)BT*DMOD];
__device__ float g_maskf[BB*TT];

// ---------------------------------------------------------------------------
__device__ __forceinline__ void cp16(void* smem, const void* g) {
    unsigned s = (unsigned)__cvta_generic_to_shared(smem);
    asm volatile("cp.async.cg.shared.global [%0], [%1], 16;" :: "r"(s), "l"(g));
}
__device__ __forceinline__ void cp_commit() { asm volatile("cp.async.commit_group;"); }
__device__ __forceinline__ void cp_wait0()  { asm volatile("cp.async.wait_group 0;"); }

__device__ __forceinline__ void ldm_x4(unsigned &r0, unsigned &r1,
                                       unsigned &r2, unsigned &r3,
                                       const void* p) {
    unsigned addr = (unsigned)__cvta_generic_to_shared(p);
    asm volatile("ldmatrix.sync.aligned.m8n8.x4.shared.b16 {%0,%1,%2,%3}, [%4];"
                 : "=r"(r0), "=r"(r1), "=r"(r2), "=r"(r3) : "r"(addr));
}
__device__ __forceinline__ void mma_f16(float* c, const unsigned* a, const unsigned* b) {
    asm volatile("mma.sync.aligned.m16n8k16.row.col.f32.f16.f16.f32 "
                 "{%0,%1,%2,%3}, {%4,%5,%6,%7}, {%8,%9}, {%0,%1,%2,%3};"
                 : "+f"(c[0]), "+f"(c[1]), "+f"(c[2]), "+f"(c[3])
                 : "r"(a[0]), "r"(a[1]), "r"(a[2]), "r"(a[3]),
                   "r"(b[0]), "r"(b[1]));
}
__device__ __forceinline__ unsigned h2u(__half2 h) { return *(unsigned*)&h; }

// ---------------------------------------------------------------------------
// Mask canonicalization
// ---------------------------------------------------------------------------
__global__ void mask_probe_k(const void* __restrict__ maskraw) {
    const unsigned int* w = (const unsigned int*)maskraw;
    int tid = threadIdx.x;
    unsigned int v = w[tid];
    int oki = (v == 0u || v == 1u);
    int okf = (v == 0u || v == 0x3F800000u);
    int all_i = __syncthreads_and(oki);
    int all_f = __syncthreads_and(okf);
    if (all_i) {
        const int* wi = (const int*)maskraw;
        for (int i = tid; i < BB*TT; i += 1024) g_maskf[i] = wi[i] ? 1.f : 0.f;
    } else if (all_f) {
        const float* wf = (const float*)maskraw;
        for (int i = tid; i < BB*TT; i += 1024) g_maskf[i] = (wf[i] != 0.f) ? 1.f : 0.f;
    } else {
        const unsigned char* wb = (const unsigned char*)maskraw;
        for (int i = tid; i < BB*TT; i += 1024) g_maskf[i] = wb[i] ? 1.f : 0.f;
    }
}

// ---------------------------------------------------------------------------
// Consolidated fp32 -> fp16 conversion (x + 4 FFN weights, 1 launch)
// ---------------------------------------------------------------------------
__global__ void __launch_bounds__(256)
cvt_all_k(const float4* __restrict__ x,   uint2* __restrict__ xh,
          const float4* __restrict__ w1c, uint2* __restrict__ d1c,
          const float4* __restrict__ w1p, uint2* __restrict__ d1p,
          const float4* __restrict__ w2c, uint2* __restrict__ d2c,
          const float4* __restrict__ w2p, uint2* __restrict__ d2p)
{
    int i = blockIdx.x * 256 + threadIdx.x;
    const float4* s; uint2* d; int off;
    if (i < 1048576) { s = x; d = xh; off = i; }
    else {
        int j = i - 1048576;
        int seg = j >> 18;
        off = j & 262143;
        if      (seg == 0) { s = w1c; d = d1c; }
        else if (seg == 1) { s = w1p; d = d1p; }
        else if (seg == 2) { s = w2c; d = d2c; }
        else               { s = w2p; d = d2p; }
    }
    float4 v = s[off];
    uint2 p;
    p.x = h2u(__floats2half2_rn(v.x, v.y));
    p.y = h2u(__floats2half2_rn(v.z, v.w));
    d[off] = p;
}

// fp32 [K][N] slabs (two tensors) -> fp16 [N][K] transpose-convert
__global__ void __launch_bounds__(256)
cvtT2_k(const float* __restrict__ srcA, const float* __restrict__ srcB,
        unsigned short* __restrict__ dstA, unsigned short* __restrict__ dstB,
        int K, int N, int nslab)
{
    __shared__ float t[32][33];
    const int zz = blockIdx.z;
    const float* src = (zz < nslab) ? srcA : srcB;
    unsigned short* dst = (zz < nslab) ? dstA : dstB;
    const int sl = (zz < nslab) ? zz : zz - nslab;
    const size_t slab = (size_t)sl * K * N;
    const int n0 = blockIdx.x * 32, k0 = blockIdx.y * 32;
    const int tx = threadIdx.x, ty = threadIdx.y;   // 32 x 8
#pragma unroll
    for (int j = 0; j < 4; j++)
        t[ty + 8*j][tx] = src[slab + (size_t)(k0 + ty + 8*j) * N + n0 + tx];
    __syncthreads();
#pragma unroll
    for (int j = 0; j < 4; j++) {
        __half h = __float2half_rn(t[tx][ty + 8*j]);
        dst[slab + (size_t)(n0 + ty + 8*j) * K + k0 + tx] = *(unsigned short*)&h;
    }
}

// ---------------------------------------------------------------------------
// fp16 HMMA GEMM 128x128x32: 8 warps (4M x 2N), warp 32x64, mma:ldm 2.67.
//  MODE 0 QKV  : A=g_xh (half z), B=g_wqT{c,p} [1536][512]
//                -> scatter to g_qh/g_kh/g_vh (q scaled), head decode in epi
//  MODE 3 OPROJ: A=g_ob (gathered), B=g_woT{c,p} [512][512] -> g_t1 fp32
//  MODE 4 FFN1 : A=g_x1h (half z), B=g_w1{c,p}h +bias relu -> g_hh
//  MODE 5 FFN2 : A=g_hh  (half z), B=g_w2{c,p}h +bias      -> g_t1 fp32
// ---------------------------------------------------------------------------
template<int MODE>
__global__ void __launch_bounds__(256, 2)
gemm_hb(const float* __restrict__ bias0,
        const float* __restrict__ bias1)
{
    constexpr int K = (MODE == 5) ? 2048 : 512;

    __shared__ unsigned short As[2][128][40];
    __shared__ unsigned short Bs[2][128][40];

    const int tid  = threadIdx.x;
    const int lane = tid & 31;
    const int warp = tid >> 5;
    const int wm = (warp & 3) * 32;
    const int wn = (warp >> 2) * 64;
    const int m0 = blockIdx.y * 128;
    const int n0 = blockIdx.x * 128;
    const int z  = blockIdx.z;

    const unsigned short* Ab;
    int astr;
    if constexpr (MODE == 0)      { Ab = g_xh  + (size_t)z * DM2; astr = DMOD;  }
    else if constexpr (MODE == 3) { Ab = g_ob;                    astr = DMOD;  }
    else if constexpr (MODE == 4) { Ab = g_x1h + (size_t)z * DM2; astr = DMOD;  }
    else                          { Ab = g_hh  + (size_t)z * DF2; astr = 2*DF2; }

    const unsigned short* Wb;
    int bstr;
    if constexpr (MODE == 0)      { Wb = z ? g_wqTp : g_wqTc; bstr = DM2; }
    else if constexpr (MODE == 3) { Wb = z ? g_woTp : g_woTc; bstr = DM2; }
    else if constexpr (MODE == 4) { Wb = z ? g_w1ph : g_w1ch; bstr = DM2; }
    else                          { Wb = z ? g_w2ph : g_w2ch; bstr = DF2; }

    float c[2][8][4];
#pragma unroll
    for (int mt = 0; mt < 2; mt++)
#pragma unroll
        for (int nt = 0; nt < 8; nt++)
#pragma unroll
            for (int r = 0; r < 4; r++) c[mt][nt][r] = 0.f;

    const int ld_r  = tid >> 2;          // 0..63
    const int ld_c8 = (tid & 3) << 3;    // 0,8,16,24 halves

    auto a_idx = [&](int m, int k) -> size_t {
        if constexpr (MODE == 3)
            return (size_t)m * DMOD + (size_t)((k >> 6) << 7) + (size_t)z * DQ2 + (k & 63);
        else
            return (size_t)m * astr + k;
    };

    auto loadA = [&](int k0, int buf) {
#pragma unroll
        for (int it = 0; it < 2; it++) {
            int m = m0 + ld_r + it * 64;
            cp16(&As[buf][ld_r + it * 64][ld_c8], Ab + a_idx(m, k0 + ld_c8));
        }
    };
    auto loadB = [&](int k0, int buf) {
#pragma unroll
        for (int it = 0; it < 2; it++) {
            int n = n0 + ld_r + it * 64;
            cp16(&Bs[buf][ld_r + it * 64][ld_c8], Wb + (size_t)n * bstr + k0 + ld_c8);
        }
    };

    loadA(0, 0);
    loadB(0, 0);
    cp_commit();
    cp_wait0();
    __syncthreads();

    const int l16 = lane & 15;
    const int kh  = (lane >> 4) * 8;

    int cur = 0;
    for (int k0 = 0; k0 < K; k0 += 32) {
        const int nxt = cur ^ 1;
        const bool has_next = (k0 + 32 < K);
        if (has_next) {
            loadA(k0 + 32, nxt);
            loadB(k0 + 32, nxt);
            cp_commit();
        }
#pragma unroll
        for (int ks = 0; ks < 2; ks++) {
            const int kofs = ks * 16 + kh;
            unsigned a[2][4];
#pragma unroll
            for (int mt = 0; mt < 2; mt++)
                ldm_x4(a[mt][0], a[mt][1], a[mt][2], a[mt][3],
                       &As[cur][wm + mt*16 + l16][kofs]);
#pragma unroll
            for (int bt = 0; bt < 4; bt++) {
                unsigned r0, r1, r2, r3;
                ldm_x4(r0, r1, r2, r3, &Bs[cur][wn + bt*16 + l16][kofs]);
                unsigned bf0[2] = {r0, r2};
                unsigned bf1[2] = {r1, r3};
#pragma unroll
                for (int mt = 0; mt < 2; mt++) {
                    mma_f16(c[mt][bt*2 + 0], a[mt], bf0);
                    mma_f16(c[mt][bt*2 + 1], a[mt], bf1);
                }
            }
        }
        if (has_next) cp_wait0();
        __syncthreads();
        cur = nxt;
    }

    // ---- epilogue ----
    const int g   = lane >> 2;
    const int tig = lane & 3;

#pragma unroll
    for (int mt = 0; mt < 2; mt++) {
#pragma unroll
        for (int nt = 0; nt < 8; nt++) {
            const int mr = m0 + wm + mt*16 + g;
            const int nl = wn + nt*8 + 2*tig;

            if constexpr (MODE == 0) {
                // col in [0,1536): head = col/192, cc = (col%192)/64, a = col%64
                // pairs never straddle a 64-block (col even).
                const int col  = n0 + nl;
                const int head = col / 192;
                const int rem  = col - head * 192;
                const int cc   = rem >> 6;
                const int a_   = rem & 63;
                const float scale = (cc == 0) ? 0.08838834764831845f : 1.0f;
                unsigned short* dst = (cc == 0) ? g_qh : ((cc == 1) ? g_kh : g_vh);
                unsigned lo = h2u(__floats2half2_rn(c[mt][nt][0]*scale, c[mt][nt][1]*scale));
                unsigned hi = h2u(__floats2half2_rn(c[mt][nt][2]*scale, c[mt][nt][3]*scale));
                {
                    int b_ = mr >> 10, t_ = mr & 1023;
                    size_t base = (((size_t)(b_*HH + head))*TT + t_) * DQ + z*DQ2;
                    *(unsigned*)(dst + base + a_) = lo;
                }
                {
                    int m2 = mr + 8;
                    int b_ = m2 >> 10, t_ = m2 & 1023;
                    size_t base = (((size_t)(b_*HH + head))*TT + t_) * DQ + z*DQ2;
                    *(unsigned*)(dst + base + a_) = hi;
                }
            } else if constexpr (MODE == 3) {
                size_t r0 = (size_t)mr * DMOD + (size_t)z * DM2 + n0 + nl;
                *(float2*)(g_t1 + r0) = make_float2(c[mt][nt][0], c[mt][nt][1]);
                *(float2*)(g_t1 + r0 + 8*DMOD) = make_float2(c[mt][nt][2], c[mt][nt][3]);
            } else if constexpr (MODE == 4) {
                const float* bs = z ? bias1 : bias0;
                float b0 = bs[n0 + nl], b1 = bs[n0 + nl + 1];
                size_t e0 = (size_t)mr * (2*DF2) + (size_t)z * DF2 + n0 + nl;
                unsigned lo = h2u(__floats2half2_rn(fmaxf(c[mt][nt][0]+b0, 0.f),
                                                    fmaxf(c[mt][nt][1]+b1, 0.f)));
                unsigned hi = h2u(__floats2half2_rn(fmaxf(c[mt][nt][2]+b0, 0.f),
                                                    fmaxf(c[mt][nt][3]+b1, 0.f)));
                *(unsigned*)(g_hh + e0) = lo;
                *(unsigned*)(g_hh + e0 + (size_t)8 * (2*DF2)) = hi;
            } else {
                const float* bs = z ? bias1 : bias0;
                float b0 = bs[n0 + nl], b1 = bs[n0 + nl + 1];
                size_t r0 = (size_t)mr * DMOD + (size_t)z * DM2 + n0 + nl;
                *(float2*)(g_t1 + r0) = make_float2(c[mt][nt][0]+b0, c[mt][nt][1]+b1);
                *(float2*)(g_t1 + r0 + 8*DMOD) = make_float2(c[mt][nt][2]+b0, c[mt][nt][3]+b1);
            }
        }
    }
}

// ---------------------------------------------------------------------------
// FA2-style flash attention (round-9/10 proven)
// ---------------------------------------------------------------------------
#define QS_H   0
#define KS_H   17408
#define VT_H   26112
#define VT_BUF 9216
#define FLASH_SMEM_BYTES 89088

__global__ void __launch_bounds__(256, 2)
flash_k()
{
    extern __shared__ __align__(16) char smraw[];
    unsigned short* smh = (unsigned short*)smraw;

    const int tid  = threadIdx.x;
    const int lane = tid & 31;
    const int warp = tid >> 5;
    const int l16  = lane & 15;
    const int kh   = (lane >> 4) * 8;
    const int g    = lane >> 2;
    const int tig  = lane & 3;

    const int wm = warp * 16;

    const int m0 = blockIdx.x * 128;
    const int z  = blockIdx.y;
    const int b  = z >> 3;
    const int h  = z & 7;

    const unsigned short* Qg = g_qh + (size_t)z * (TT*DQ);
    const unsigned short* Kg = g_kh + (size_t)z * (TT*DQ);
    const unsigned short* Vg = g_vh + (size_t)z * (TT*DQ);

#pragma unroll
    for (int i = 0; i < 8; i++) {
        int ch = tid + i * 256;
        int r = ch >> 4, c8 = (ch & 15) * 8;
        cp16(&smh[QS_H + r * 136 + c8], Qg + (size_t)(m0 + r) * DQ + c8);
    }
#pragma unroll
    for (int i = 0; i < 4; i++) {
        int ch = tid + i * 256;
        int r = ch >> 4, c8 = (ch & 15) * 8;
        cp16(&smh[KS_H + r * 136 + c8], Kg + (size_t)r * DQ + c8);
    }
    cp_commit();

    float co[16][4];
#pragma unroll
    for (int nt = 0; nt < 16; nt++)
#pragma unroll
        for (int r = 0; r < 4; r++) co[nt][r] = 0.f;
    float mrun[2] = {-1e30f, -1e30f};
    float lrun[2] = {0.f, 0.f};

    for (int kt = 0; kt < 16; kt++) {
        cp_wait0();
        __syncthreads();

        float cs[8][4];
#pragma unroll
        for (int nt = 0; nt < 8; nt++)
#pragma unroll
            for (int r = 0; r < 4; r++) cs[nt][r] = 0.f;
#pragma unroll
        for (int ks = 0; ks < 8; ks++) {
            const int kofs = ks * 16 + kh;
            unsigned a[4];
            ldm_x4(a[0], a[1], a[2], a[3], &smh[QS_H + (wm + l16) * 136 + kofs]);
#pragma unroll
            for (int bt = 0; bt < 4; bt++) {
                unsigned r0, r1, r2, r3;
                ldm_x4(r0, r1, r2, r3, &smh[KS_H + (bt*16 + l16) * 136 + kofs]);
                unsigned bf0[2] = {r0, r2};
                unsigned bf1[2] = {r1, r3};
                mma_f16(cs[bt*2 + 0], a, bf0);
                mma_f16(cs[bt*2 + 1], a, bf1);
            }
        }

        const int vtb = VT_H + (kt & 1) * VT_BUF;
#pragma unroll
        for (int i = 0; i < 2; i++) {
            int lin = tid + i * 256;
            int tp = lin & 31, d8 = (lin >> 5) * 8;
            const unsigned short* vp = Vg + (size_t)(kt*64 + 2*tp) * DQ + d8;
            float4 va = *(const float4*)vp;
            float4 vb = *(const float4*)(vp + DQ);
            const __half* ha = (const __half*)&va;
            const __half* hb = (const __half*)&vb;
#pragma unroll
            for (int j = 0; j < 8; j++) {
                __half2 pr = __halves2half2(ha[j], hb[j]);
                *(__half2*)&smh[vtb + (d8 + j) * 72 + 2*tp] = pr;
            }
        }

        float rmax[2] = {-1e30f, -1e30f};
#pragma unroll
        for (int nt = 0; nt < 8; nt++) {
            int col = kt*64 + nt*8 + 2*tig;
            float2 mk = *(const float2*)&g_maskf[b*TT + col];
            if (mk.x == 0.f) { cs[nt][0] = -1e30f; cs[nt][2] = -1e30f; }
            if (mk.y == 0.f) { cs[nt][1] = -1e30f; cs[nt][3] = -1e30f; }
            rmax[0] = fmaxf(rmax[0], fmaxf(cs[nt][0], cs[nt][1]));
            rmax[1] = fmaxf(rmax[1], fmaxf(cs[nt][2], cs[nt][3]));
        }
#pragma unroll
        for (int i = 0; i < 2; i++) {
            rmax[i] = fmaxf(rmax[i], __shfl_xor_sync(0xFFFFFFFFu, rmax[i], 1));
            rmax[i] = fmaxf(rmax[i], __shfl_xor_sync(0xFFFFFFFFu, rmax[i], 2));
        }

        __syncthreads();

        if (kt + 1 < 16) {
#pragma unroll
            for (int i = 0; i < 4; i++) {
                int ch = tid + i * 256;
                int r = ch >> 4, c8 = (ch & 15) * 8;
                cp16(&smh[KS_H + r * 136 + c8], Kg + (size_t)((kt+1)*64 + r) * DQ + c8);
            }
            cp_commit();
        }

        float newm[2], alpha[2], rsum[2] = {0.f, 0.f};
#pragma unroll
        for (int i = 0; i < 2; i++) {
            newm[i] = fmaxf(mrun[i], rmax[i]);
            alpha[i] = __expf(mrun[i] - newm[i]);
        }
        unsigned ap[4][4];
#pragma unroll
        for (int nt = 0; nt < 8; nt++) {
            float p0 = (cs[nt][0] <= -1e29f) ? 0.f : __expf(cs[nt][0] - newm[0]);
            float p1 = (cs[nt][1] <= -1e29f) ? 0.f : __expf(cs[nt][1] - newm[0]);
            float p2 = (cs[nt][2] <= -1e29f) ? 0.f : __expf(cs[nt][2] - newm[1]);
            float p3 = (cs[nt][3] <= -1e29f) ? 0.f : __expf(cs[nt][3] - newm[1]);
            rsum[0] += p0 + p1;
            rsum[1] += p2 + p3;
            const int base = (nt & 1) * 2;
            ap[nt >> 1][base + 0] = h2u(__floats2half2_rn(p0, p1));
            ap[nt >> 1][base + 1] = h2u(__floats2half2_rn(p2, p3));
        }
#pragma unroll
        for (int i = 0; i < 2; i++) {
            rsum[i] += __shfl_xor_sync(0xFFFFFFFFu, rsum[i], 1);
            rsum[i] += __shfl_xor_sync(0xFFFFFFFFu, rsum[i], 2);
            lrun[i] = lrun[i] * alpha[i] + rsum[i];
            mrun[i] = newm[i];
        }
#pragma unroll
        for (int nt = 0; nt < 16; nt++) {
            co[nt][0] *= alpha[0]; co[nt][1] *= alpha[0];
            co[nt][2] *= alpha[1]; co[nt][3] *= alpha[1];
        }

#pragma unroll
        for (int ks = 0; ks < 4; ks++) {
            const int kofs = ks * 16 + kh;
#pragma unroll
            for (int bt = 0; bt < 8; bt++) {
                unsigned r0, r1, r2, r3;
                ldm_x4(r0, r1, r2, r3, &smh[vtb + (bt*16 + l16) * 72 + kofs]);
                unsigned bf0[2] = {r0, r2};
                unsigned bf1[2] = {r1, r3};
                mma_f16(co[bt*2 + 0], ap[ks], bf0);
                mma_f16(co[bt*2 + 1], ap[ks], bf1);
            }
        }
    }

    float invl[2] = {1.0f / lrun[0], 1.0f / lrun[1]};
    const int rowA = m0 + wm + g;
#pragma unroll
    for (int nt = 0; nt < 16; nt++) {
        int col = nt*8 + 2*tig;
        unsigned lo = h2u(__floats2half2_rn(co[nt][0]*invl[0], co[nt][1]*invl[0]));
        unsigned hi = h2u(__floats2half2_rn(co[nt][2]*invl[1], co[nt][3]*invl[1]));
        *(unsigned*)(g_ob + ((size_t)(b*TT + rowA)) * DMOD + h*DQ + col) = lo;
        *(unsigned*)(g_ob + ((size_t)(b*TT + rowA + 8)) * DMOD + h*DQ + col) = hi;
    }
}

// ---------------------------------------------------------------------------
// Fused residual + LayerNorm
// ---------------------------------------------------------------------------
template<int PHASE>
__global__ void __launch_bounds__(256)
ln_k(const float* __restrict__ a,
     const float* __restrict__ gamma,
     const float* __restrict__ beta,
     float* __restrict__ outp)
{
    const int row = blockIdx.x;
    const int tid = threadIdx.x;
    const int lane = tid & 31, wid = tid >> 5;
    const float* r1 = (PHASE == 0) ? a : g_x1;

    __shared__ float red1[8];
    __shared__ float red2[8];

    float4 av = ((const float4*)(r1 + (size_t)row * DMOD))[tid];
    float4 tv = ((const float4*)(g_t1 + (size_t)row * DMOD))[tid];
    float v[4] = {av.x + tv.x, av.y + tv.y, av.z + tv.z, av.w + tv.w};

    float s = v[0] + v[1] + v[2] + v[3];
#pragma unroll
    for (int o = 16; o > 0; o >>= 1) s += __shfl_xor_sync(0xFFFFFFFFu, s, o);
    if (lane == 0) red1[wid] = s;
    __syncthreads();
    float tot = red1[0];
#pragma unroll
    for (int i = 1; i < 8; i++) tot += red1[i];
    const float mu = tot * (1.0f / DMOD);

    float vs = 0.f;
#pragma unroll
    for (int i = 0; i < 4; i++) { float d = v[i] - mu; vs += d * d; }
#pragma unroll
    for (int o = 16; o > 0; o >>= 1) vs += __shfl_xor_sync(0xFFFFFFFFu, vs, o);
    if (lane == 0) red2[wid] = vs;
    __syncthreads();
    float vtot = red2[0];
#pragma unroll
    for (int i = 1; i < 8; i++) vtot += red2[i];
    const float rs = rsqrtf(vtot * (1.0f / DMOD) + 1e-5f);

    float4 g4 = ((const float4*)gamma)[tid];
    float4 b4 = ((const float4*)beta)[tid];
    float4 o4;
    o4.x = (v[0] - mu) * rs * g4.x + b4.x;
    o4.y = (v[1] - mu) * rs * g4.y + b4.y;
    o4.z = (v[2] - mu) * rs * g4.z + b4.z;
    o4.w = (v[3] - mu) * rs * g4.w + b4.w;

    if constexpr (PHASE == 0) {
        ((float4*)(g_x1 + (size_t)row * DMOD))[tid] = o4;
        uint2 p;
        p.x = h2u(__floats2half2_rn(o4.x, o4.y));
        p.y = h2u(__floats2half2_rn(o4.z, o4.w));
        ((uint2*)(g_x1h + (size_t)row * DMOD))[tid] = p;
    } else {
        ((float4*)(outp + (size_t)row * DMOD))[tid] = o4;
    }
}

// ---------------------------------------------------------------------------
extern "C" void kernel_launch(void* const* d_in, const int* in_sizes, int n_in,
                              void* d_out, int out_size)
{
    (void)in_sizes; (void)n_in; (void)out_size;
    const float* x      = (const float*)d_in[0];
    const void*  mask   = d_in[1];
    const float* wqkv_c = (const float*)d_in[2];
    const float* wqkv_p = (const float*)d_in[3];
    const float* wo_c   = (const float*)d_in[4];
    const float* wo_p   = (const float*)d_in[5];
    const float* w1_c   = (const float*)d_in[6];
    const float* b1_c   = (const float*)d_in[7];
    const float* w1_p   = (const float*)d_in[8];
    const float* b1_p   = (const float*)d_in[9];
    const float* w2_c   = (const float*)d_in[10];
    const float* b2_c   = (const float*)d_in[11];
    const float* w2_p   = (const float*)d_in[12];
    const float* b2_p   = (const float*)d_in[13];
    const float* ln1_g  = (const float*)d_in[14];
    const float* ln1_b  = (const float*)d_in[15];
    const float* ln2_g  = (const float*)d_in[16];
    const float* ln2_b  = (const float*)d_in[17];
    float* out = (float*)d_out;

    cudaFuncSetAttribute(flash_k, cudaFuncAttributeMaxDynamicSharedMemorySize,
                         FLASH_SMEM_BYTES);

    void* xh;   cudaGetSymbolAddress(&xh,   g_xh);
    void* wqTc; cudaGetSymbolAddress(&wqTc, g_wqTc);
    void* wqTp; cudaGetSymbolAddress(&wqTp, g_wqTp);
    void* woTc; cudaGetSymbolAddress(&woTc, g_woTc);
    void* woTp; cudaGetSymbolAddress(&woTp, g_woTp);
    void* w1ch; cudaGetSymbolAddress(&w1ch, g_w1ch);
    void* w1ph; cudaGetSymbolAddress(&w1ph, g_w1ph);
    void* w2ch; cudaGetSymbolAddress(&w2ch, g_w2ch);
    void* w2ph; cudaGetSymbolAddress(&w2ph, g_w2ph);

    // 1: mask
    mask_probe_k<<<1, 1024>>>(mask);
    // 2: elementwise conversions (x + FFN weights)
    cvt_all_k<<<8192, 256>>>((const float4*)x, (uint2*)xh,
                             (const float4*)w1_c, (uint2*)w1ch,
                             (const float4*)w1_p, (uint2*)w1ph,
                             (const float4*)w2_c, (uint2*)w2ch,
                             (const float4*)w2_p, (uint2*)w2ph);
    // 3: wqkv transpose-convert (both tensors, 16 slabs)
    cvtT2_k<<<dim3(6, 16, 16), dim3(32, 8)>>>(wqkv_c, wqkv_p,
                                              (unsigned short*)wqTc,
                                              (unsigned short*)wqTp, DM2, 192, 8);
    // 4: wo transpose-convert (both tensors)
    cvtT2_k<<<dim3(16, 16, 2), dim3(32, 8)>>>(wo_c, wo_p,
                                              (unsigned short*)woTc,
                                              (unsigned short*)woTp, DM2, DM2, 1);
    // 5: QKV unified (N=1536 per half)
    gemm_hb<0><<<dim3(12, 32, 2), 256>>>(nullptr, nullptr);
    // 6: flash attention
    flash_k<<<dim3(8, 32), 256, FLASH_SMEM_BYTES>>>();
    // 7: OPROJ
    gemm_hb<3><<<dim3(4, 32, 2), 256>>>(nullptr, nullptr);
    // 8: LN1
    ln_k<0><<<BT, 256>>>(x, ln1_g, ln1_b, nullptr);
    // 9: FFN1
    gemm_hb<4><<<dim3(16, 32, 2), 256>>>(b1_c, b1_p);
    // 10: FFN2
    gemm_hb<5><<<dim3(4, 32, 2), 256>>>(b2_c, b2_p);
    // 11: LN2 -> out
    ln_k<1><<<BT, 256>>>(nullptr, ln2_g, ln2_b, out);
}